// round 8
// baseline (speedup 1.0000x reference)
#include <cuda_runtime.h>
#include <math.h>
#include <stdint.h>

#define NN 50000
#define NE 800000
#define H 128
#define NRAD 16
#define TE 64              // edges per block
#define TN 32              // nodes per block
#define EDP 284            // ef row stride: mod32=28 -> conflict-free A-frags
#define HS  132            // h/eh row stride: mod32=4 -> conflict-free
#define SBN 136            // weight chunk stride (N=128): mod32=8
#define SBN3 72            // weight chunk stride (N=64): mod32=8
#define PI_F 3.14159265358979f

// dynamic smem layout (bytes)
#define OFF_EF 0
#define SZ_EF  (TE * EDP * 4)              // 72704
#define OFF_H  (OFF_EF + SZ_EF)            // 72704
#define SZ_H   (TE * HS * 4)               // 33792
#define OFF_B0 (OFF_H + SZ_H)              // 106496
#define SZ_B   (32 * SBN * 4)              // 17408
#define OFF_B1 (OFF_B0 + SZ_B)             // 123904
#define SMEM_EDGE (OFF_B1 + SZ_B)          // 141312

typedef unsigned long long u64t;

__device__ float g_agg[NN * H];
__device__ float g_cnt[NN];
__device__ float g_delta[NN * 3];

__device__ __forceinline__ float silu_f(float v) { return v / (1.f + __expf(-v)); }

__device__ __forceinline__ float tf32r(float f) {
    uint32_t u; asm("cvt.rna.tf32.f32 %0, %1;" : "=r"(u) : "f"(f));
    return __uint_as_float(u);
}
__device__ __forceinline__ float4 tf32r4(float4 v) {
    v.x = tf32r(v.x); v.y = tf32r(v.y); v.z = tf32r(v.z); v.w = tf32r(v.w);
    return v;
}
__device__ __forceinline__ void mma_tf32(float* d, uint32_t a0, uint32_t a1, uint32_t a2,
                                         uint32_t a3, uint32_t b0, uint32_t b1) {
    asm("mma.sync.aligned.m16n8k8.row.col.f32.tf32.tf32.f32 "
        "{%0,%1,%2,%3},{%4,%5,%6,%7},{%8,%9},{%0,%1,%2,%3};"
        : "+f"(d[0]), "+f"(d[1]), "+f"(d[2]), "+f"(d[3])
        : "r"(a0), "r"(a1), "r"(a2), "r"(a3), "r"(b0), "r"(b1));
}

__device__ __forceinline__ void fma2(u64t& d, u64t a, u64t b) {
    asm("fma.rn.f32x2 %0, %1, %2, %0;" : "+l"(d) : "l"(a), "l"(b));
}
__device__ __forceinline__ u64t pack2(float lo, float hi) {
    u64t d; asm("mov.b64 %0, {%1, %2};" : "=l"(d) : "f"(lo), "f"(hi)); return d;
}
__device__ __forceinline__ float hadd2(u64t d) {
    float lo, hi; asm("mov.b64 {%0, %1}, %2;" : "=f"(lo), "=f"(hi) : "l"(d));
    return lo + hi;
}

__global__ __launch_bounds__(256) void edge_kernel(
    const float* __restrict__ x, const float* __restrict__ pos,
    const float* __restrict__ charge, const float* __restrict__ edge_attr,
    const int* __restrict__ edge_index,
    const float* __restrict__ We1, const float* __restrict__ be1,
    const float* __restrict__ g1, const float* __restrict__ bt1,
    const float* __restrict__ We2, const float* __restrict__ be2,
    const float* __restrict__ Wc1, const float* __restrict__ bc1,
    const float* __restrict__ Wc2, const float* __restrict__ bc2)
{
    extern __shared__ __align__(16) char dyn_smem[];
    float* const ef   = (float*)(dyn_smem + OFF_EF);   // [64][284] (tf32 values)
    float* const s_h  = (float*)(dyn_smem + OFF_H);    // [64][132]
    float* const s_eh = (float*)(dyn_smem + OFF_EF);   // [64][132] overlays dead ef
    float* const s_B0 = (float*)(dyn_smem + OFF_B0);
    float* const s_B1 = (float*)(dyn_smem + OFF_B1);

    __shared__ float s_gate[TE];
    __shared__ float s_unit[TE][3];
    __shared__ int   s_src[TE];
    __shared__ float s_coord[TE];

    const int tid = threadIdx.x;
    const int e0 = blockIdx.x * TE;

    // ---- per-edge scalars ----
    if (tid < TE) {
        const int e = e0 + tid;
        const int src = edge_index[e];
        const int dst = edge_index[NE + e];
        s_src[tid] = src;
        const float rx = pos[dst * 3 + 0] - pos[src * 3 + 0];
        const float ry = pos[dst * 3 + 1] - pos[src * 3 + 1];
        const float rz = pos[dst * 3 + 2] - pos[src * 3 + 2];
        const float dist = sqrtf(rx * rx + ry * ry + rz * rz + 1e-8f);
        const float inv = 1.f / dist;
        s_unit[tid][0] = rx * inv; s_unit[tid][1] = ry * inv; s_unit[tid][2] = rz * inv;

        const float4 ea = *(const float4*)&edge_attr[e * 4];
        float ca = cosf(ea.x);
        float p2 = 0.5f * (3.f * ca * ca - 1.f);
        float p3 = (5.f * ca * p2 - 2.f * ca) * (1.f / 3.f);
        float a_score = 0.25f * (1.f + fabsf(ca) + fabsf(p2) + fabsf(p3)) * ea.z;
        float cd = cosf(ea.y);
        float q2 = 0.5f * (3.f * cd * cd - 1.f);
        float q3 = (5.f * cd * q2 - 2.f * cd) * (1.f / 3.f);
        float d_score = 0.25f * (1.f + fabsf(cd) + fabsf(q2) + fabsf(q3)) * ea.w;
        float gate = fminf(fmaxf(1.f + 0.6f * (a_score + d_score), 0.35f), 2.5f);
        s_gate[tid] = gate;
        s_coord[tid] = bc2[0];

        const float qs = charge[src], qd = charge[dst];
        float* row = &ef[tid * EDP];
        const float gi = gate * inv;
        #pragma unroll
        for (int i = 0; i < NRAD; i++) {
            float f = (float)(i + 1) * (PI_F / 5.0f);
            row[2 * H + i] = tf32r(sinf(f * dist) * gi);
        }
        row[272] = tf32r(dist * 0.2f * gate);
        row[273] = tf32r(qs * qd * gate);
        row[274] = tf32r(fabsf(qs - qd) * gate);
        #pragma unroll
        for (int i = 275; i < EDP; i++) row[i] = 0.f;
    }

    // ---- gather x[src], x[dst] (tf32-converted at write) ----
    for (int idx = tid; idx < TE * 32; idx += 256) {
        const int e = idx >> 5, j4 = idx & 31;
        const int src = edge_index[e0 + e];
        const int dst = edge_index[NE + e0 + e];
        *(float4*)&ef[e * EDP + j4 * 4]     = tf32r4(*(const float4*)&x[src * H + j4 * 4]);
        *(float4*)&ef[e * EDP + H + j4 * 4] = tf32r4(*(const float4*)&x[dst * H + j4 * 4]);
    }

    const int lane = tid & 31, w = tid >> 5;
    const int g = lane >> 2, tg = lane & 3;
    const int mg = w & 1;            // m-group: 2 m-tiles
    const int ng = w >> 1;           // n-group: 4 n-tiles (GEMM1/2), 2 (GEMM3)
    const int m0 = mg * 32;
    const int nb = ng * 32;
    const int nb3 = ng * 16;
    const int kk = tid >> 3, q = tid & 7;

    float d[2][4][4];
    #pragma unroll
    for (int mi = 0; mi < 2; mi++)
        #pragma unroll
        for (int t = 0; t < 4; t++)
            #pragma unroll
            for (int i = 0; i < 4; i++) d[mi][t][i] = 0.f;

    float4 r0, r1, r2, r3;
    const float4 z4 = make_float4(0.f, 0.f, 0.f, 0.f);

    // ================= GEMM1: ef[64x280] @ We1[280x128] =================
    {
        // preload chunk 0
        {
            const int k = kk;
            const float* s = &We1[k * H + q * 16];
            r0 = tf32r4(*(const float4*)(s + 0));
            r1 = tf32r4(*(const float4*)(s + 4));
            r2 = tf32r4(*(const float4*)(s + 8));
            r3 = tf32r4(*(const float4*)(s + 12));
            float* dw = &s_B0[kk * SBN + q * 16];
            *(float4*)(dw + 0) = r0; *(float4*)(dw + 4) = r1;
            *(float4*)(dw + 8) = r2; *(float4*)(dw + 12) = r3;
        }
        for (int c = 0; c < 9; c++) {
            if (c < 8) {
                const int k = (c + 1) * 32 + kk;
                if (k < 275) {
                    const float* s = &We1[k * H + q * 16];
                    r0 = tf32r4(*(const float4*)(s + 0));
                    r1 = tf32r4(*(const float4*)(s + 4));
                    r2 = tf32r4(*(const float4*)(s + 8));
                    r3 = tf32r4(*(const float4*)(s + 12));
                } else { r0 = z4; r1 = z4; r2 = z4; r3 = z4; }
            }
            __syncthreads();
            const float* bp = (c & 1) ? s_B1 : s_B0;
            #pragma unroll
            for (int ks = 0; ks < 4; ks++) {
                const int sg = c * 4 + ks;
                if (sg >= 35) break;
                const int kg = sg * 8, kl = ks * 8;
                uint32_t a[2][4];
                #pragma unroll
                for (int mi = 0; mi < 2; mi++) {
                    const int rA = m0 + mi * 16 + g;
                    a[mi][0] = __float_as_uint(ef[rA * EDP + kg + tg]);
                    a[mi][1] = __float_as_uint(ef[(rA + 8) * EDP + kg + tg]);
                    a[mi][2] = __float_as_uint(ef[rA * EDP + kg + 4 + tg]);
                    a[mi][3] = __float_as_uint(ef[(rA + 8) * EDP + kg + 4 + tg]);
                }
                #pragma unroll
                for (int t = 0; t < 4; t++) {
                    const uint32_t b0 = __float_as_uint(bp[(kl + tg) * SBN + nb + t * 8 + g]);
                    const uint32_t b1 = __float_as_uint(bp[(kl + 4 + tg) * SBN + nb + t * 8 + g]);
                    mma_tf32(d[0][t], a[0][0], a[0][1], a[0][2], a[0][3], b0, b1);
                    mma_tf32(d[1][t], a[1][0], a[1][1], a[1][2], a[1][3], b0, b1);
                }
            }
            if (c < 8) {
                float* np = (c & 1) ? s_B0 : s_B1;
                float* dw = &np[kk * SBN + q * 16];
                *(float4*)(dw + 0) = r0; *(float4*)(dw + 4) = r1;
                *(float4*)(dw + 8) = r2; *(float4*)(dw + 12) = r3;
            }
        }
    }

    // ---- epilogue1: silu(+be1) -> s_h (raw fp32; LN re-rounds) ----
    #pragma unroll
    for (int t = 0; t < 4; t++) {
        const int col = nb + t * 8 + tg * 2;
        const float bb0 = be1[col], bb1 = be1[col + 1];
        #pragma unroll
        for (int mi = 0; mi < 2; mi++) {
            const int rA = m0 + mi * 16 + g;
            s_h[rA * HS + col]           = silu_f(d[mi][t][0] + bb0);
            s_h[rA * HS + col + 1]       = silu_f(d[mi][t][1] + bb1);
            s_h[(rA + 8) * HS + col]     = silu_f(d[mi][t][2] + bb0);
            s_h[(rA + 8) * HS + col + 1] = silu_f(d[mi][t][3] + bb1);
        }
    }
    __syncthreads();

    // ---- LayerNorm(h): warp per 8 edges; write tf32 ----
    {
        const float ga = g1[lane], gb = g1[lane + 32], gc = g1[lane + 64], gd = g1[lane + 96];
        const float ba = bt1[lane], bb = bt1[lane + 32], bcv = bt1[lane + 64], bd = bt1[lane + 96];
        #pragma unroll
        for (int qq = 0; qq < 8; qq++) {
            const int e = w * 8 + qq;
            float v0 = s_h[e * HS + lane], v1 = s_h[e * HS + lane + 32];
            float v2 = s_h[e * HS + lane + 64], v3 = s_h[e * HS + lane + 96];
            float s1 = v0 + v1 + v2 + v3;
            float s2 = v0 * v0 + v1 * v1 + v2 * v2 + v3 * v3;
            #pragma unroll
            for (int o = 16; o; o >>= 1) {
                s1 += __shfl_xor_sync(0xffffffffu, s1, o);
                s2 += __shfl_xor_sync(0xffffffffu, s2, o);
            }
            const float m = s1 * (1.f / 128.f);
            const float var = s2 * (1.f / 128.f) - m * m;
            const float rstd = rsqrtf(var + 1e-5f);
            s_h[e * HS + lane]      = tf32r((v0 - m) * rstd * ga + ba);
            s_h[e * HS + lane + 32] = tf32r((v1 - m) * rstd * gb + bb);
            s_h[e * HS + lane + 64] = tf32r((v2 - m) * rstd * gc + bcv);
            s_h[e * HS + lane + 96] = tf32r((v3 - m) * rstd * gd + bd);
        }
    }

    // ================= GEMM2: h[64x128] @ We2[128x128] =================
    #pragma unroll
    for (int mi = 0; mi < 2; mi++)
        #pragma unroll
        for (int t = 0; t < 4; t++)
            #pragma unroll
            for (int i = 0; i < 4; i++) d[mi][t][i] = 0.f;
    {
        {
            const float* s = &We2[kk * H + q * 16];
            r0 = tf32r4(*(const float4*)(s + 0));
            r1 = tf32r4(*(const float4*)(s + 4));
            r2 = tf32r4(*(const float4*)(s + 8));
            r3 = tf32r4(*(const float4*)(s + 12));
            float* dw = &s_B0[kk * SBN + q * 16];
            *(float4*)(dw + 0) = r0; *(float4*)(dw + 4) = r1;
            *(float4*)(dw + 8) = r2; *(float4*)(dw + 12) = r3;
        }
        for (int c = 0; c < 4; c++) {
            if (c < 3) {
                const float* s = &We2[((c + 1) * 32 + kk) * H + q * 16];
                r0 = tf32r4(*(const float4*)(s + 0));
                r1 = tf32r4(*(const float4*)(s + 4));
                r2 = tf32r4(*(const float4*)(s + 8));
                r3 = tf32r4(*(const float4*)(s + 12));
            }
            __syncthreads();
            const float* bp = (c & 1) ? s_B1 : s_B0;
            #pragma unroll
            for (int ks = 0; ks < 4; ks++) {
                const int kg = c * 32 + ks * 8, kl = ks * 8;
                uint32_t a[2][4];
                #pragma unroll
                for (int mi = 0; mi < 2; mi++) {
                    const int rA = m0 + mi * 16 + g;
                    a[mi][0] = __float_as_uint(s_h[rA * HS + kg + tg]);
                    a[mi][1] = __float_as_uint(s_h[(rA + 8) * HS + kg + tg]);
                    a[mi][2] = __float_as_uint(s_h[rA * HS + kg + 4 + tg]);
                    a[mi][3] = __float_as_uint(s_h[(rA + 8) * HS + kg + 4 + tg]);
                }
                #pragma unroll
                for (int t = 0; t < 4; t++) {
                    const uint32_t b0 = __float_as_uint(bp[(kl + tg) * SBN + nb + t * 8 + g]);
                    const uint32_t b1 = __float_as_uint(bp[(kl + 4 + tg) * SBN + nb + t * 8 + g]);
                    mma_tf32(d[0][t], a[0][0], a[0][1], a[0][2], a[0][3], b0, b1);
                    mma_tf32(d[1][t], a[1][0], a[1][1], a[1][2], a[1][3], b0, b1);
                }
            }
            if (c < 3) {
                float* np = (c & 1) ? s_B0 : s_B1;
                float* dw = &np[kk * SBN + q * 16];
                *(float4*)(dw + 0) = r0; *(float4*)(dw + 4) = r1;
                *(float4*)(dw + 8) = r2; *(float4*)(dw + 12) = r3;
            }
        }
    }

    // ---- epilogue2: eh = silu(+be2) -> s_eh (tf32; also scattered) ----
    #pragma unroll
    for (int t = 0; t < 4; t++) {
        const int col = nb + t * 8 + tg * 2;
        const float bb0 = be2[col], bb1 = be2[col + 1];
        #pragma unroll
        for (int mi = 0; mi < 2; mi++) {
            const int rA = m0 + mi * 16 + g;
            s_eh[rA * HS + col]           = tf32r(silu_f(d[mi][t][0] + bb0));
            s_eh[rA * HS + col + 1]       = tf32r(silu_f(d[mi][t][1] + bb1));
            s_eh[(rA + 8) * HS + col]     = tf32r(silu_f(d[mi][t][2] + bb0));
            s_eh[(rA + 8) * HS + col + 1] = tf32r(silu_f(d[mi][t][3] + bb1));
        }
    }

    // ================= GEMM3: eh[64x128] @ Wc1[128x64] =================
    float d3[2][2][4];
    #pragma unroll
    for (int mi = 0; mi < 2; mi++)
        #pragma unroll
        for (int t = 0; t < 2; t++)
            #pragma unroll
            for (int i = 0; i < 4; i++) d3[mi][t][i] = 0.f;
    {
        {
            const float* s = &Wc1[kk * 64 + q * 8];
            r0 = tf32r4(*(const float4*)(s + 0));
            r1 = tf32r4(*(const float4*)(s + 4));
            float* dw = &s_B0[kk * SBN3 + q * 8];
            *(float4*)(dw + 0) = r0; *(float4*)(dw + 4) = r1;
        }
        for (int c = 0; c < 4; c++) {
            if (c < 3) {
                const float* s = &Wc1[((c + 1) * 32 + kk) * 64 + q * 8];
                r0 = tf32r4(*(const float4*)(s + 0));
                r1 = tf32r4(*(const float4*)(s + 4));
            }
            __syncthreads();
            const float* bp = (c & 1) ? s_B1 : s_B0;
            #pragma unroll
            for (int ks = 0; ks < 4; ks++) {
                const int kg = c * 32 + ks * 8, kl = ks * 8;
                uint32_t a[2][4];
                #pragma unroll
                for (int mi = 0; mi < 2; mi++) {
                    const int rA = m0 + mi * 16 + g;
                    a[mi][0] = __float_as_uint(s_eh[rA * HS + kg + tg]);
                    a[mi][1] = __float_as_uint(s_eh[(rA + 8) * HS + kg + tg]);
                    a[mi][2] = __float_as_uint(s_eh[rA * HS + kg + 4 + tg]);
                    a[mi][3] = __float_as_uint(s_eh[(rA + 8) * HS + kg + 4 + tg]);
                }
                #pragma unroll
                for (int t = 0; t < 2; t++) {
                    const uint32_t b0 = __float_as_uint(bp[(kl + tg) * SBN3 + nb3 + t * 8 + g]);
                    const uint32_t b1 = __float_as_uint(bp[(kl + 4 + tg) * SBN3 + nb3 + t * 8 + g]);
                    mma_tf32(d3[0][t], a[0][0], a[0][1], a[0][2], a[0][3], b0, b1);
                    mma_tf32(d3[1][t], a[1][0], a[1][1], a[1][2], a[1][3], b0, b1);
                }
            }
            if (c < 3) {
                float* np = (c & 1) ? s_B0 : s_B1;
                float* dw = &np[kk * SBN3 + q * 8];
                *(float4*)(dw + 0) = r0; *(float4*)(dw + 4) = r1;
            }
        }
    }

    // ---- epilogue3: coord partial = silu(+bc1) @ Wc2 ----
    #pragma unroll
    for (int mi = 0; mi < 2; mi++) {
        float sA = 0.f, sB2 = 0.f;
        #pragma unroll
        for (int t = 0; t < 2; t++) {
            const int col = nb3 + t * 8 + tg * 2;
            const float w0 = Wc2[col], w1 = Wc2[col + 1];
            const float c0 = bc1[col], c1 = bc1[col + 1];
            sA  += silu_f(d3[mi][t][0] + c0) * w0 + silu_f(d3[mi][t][1] + c1) * w1;
            sB2 += silu_f(d3[mi][t][2] + c0) * w0 + silu_f(d3[mi][t][3] + c1) * w1;
        }
        const int rA = m0 + mi * 16 + g;
        atomicAdd(&s_coord[rA], sA);
        atomicAdd(&s_coord[rA + 8], sB2);
    }
    __syncthreads();

    // ---- scatter ----
    for (int idx = tid; idx < TE * H; idx += 256) {
        const int e = idx >> 7, jc = idx & (H - 1);
        atomicAdd(&g_agg[s_src[e] * H + jc], s_eh[e * HS + jc]);
    }
    if (tid < TE) {
        const int src = s_src[tid];
        const float f = s_coord[tid] * s_gate[tid];
        atomicAdd(&g_cnt[src], 1.0f);
        atomicAdd(&g_delta[src * 3 + 0], s_unit[tid][0] * f);
        atomicAdd(&g_delta[src * 3 + 1], s_unit[tid][1] * f);
        atomicAdd(&g_delta[src * 3 + 2], s_unit[tid][2] * f);
    }
}

__global__ __launch_bounds__(256) void node_kernel(
    const float* __restrict__ x, const float* __restrict__ pos,
    const float* __restrict__ Wn, const float* __restrict__ bn,
    const float* __restrict__ gn, const float* __restrict__ btn,
    float* __restrict__ out)
{
    __shared__ __align__(16) float s_cat[TN * 260];
    const int tid = threadIdx.x;
    const int n0 = blockIdx.x * TN;

    for (int idx = tid; idx < TN * 64; idx += 256) {
        const int nl = idx >> 6, j4 = idx & 63;
        const int n = n0 + nl;
        float4 v = make_float4(0.f, 0.f, 0.f, 0.f);
        if (n < NN) {
            if (j4 < 32) {
                v = *(const float4*)&x[n * H + j4 * 4];
            } else {
                const float c = fmaxf(g_cnt[n], 1.f);
                const float iv = 1.f / c;
                v = *(const float4*)&g_agg[n * H + (j4 - 32) * 4];
                v.x *= iv; v.y *= iv; v.z *= iv; v.w *= iv;
            }
        }
        *(float4*)&s_cat[nl * 260 + j4 * 4] = v;
    }
    __syncthreads();

    const int jj = tid & 63, g = tid >> 6;
    const int nbv = g * 8;
    u64t accA[8], accB[8];
    #pragma unroll
    for (int e = 0; e < 8; e++) { accA[e] = 0ull; accB[e] = 0ull; }
    for (int k = 0; k < 256; k += 4) {
        const float wA0 = Wn[(k + 0) * H + jj],      wA1 = Wn[(k + 1) * H + jj];
        const float wA2 = Wn[(k + 2) * H + jj],      wA3 = Wn[(k + 3) * H + jj];
        const float wB0 = Wn[(k + 0) * H + jj + 64], wB1 = Wn[(k + 1) * H + jj + 64];
        const float wB2 = Wn[(k + 2) * H + jj + 64], wB3 = Wn[(k + 3) * H + jj + 64];
        const u64t pA0 = pack2(wA0, wA1), pA1 = pack2(wA2, wA3);
        const u64t pB0 = pack2(wB0, wB1), pB1 = pack2(wB2, wB3);
        #pragma unroll
        for (int e = 0; e < 8; e++) {
            const ulonglong2 v = *(const ulonglong2*)&s_cat[(nbv + e) * 260 + k];
            fma2(accA[e], v.x, pA0); fma2(accA[e], v.y, pA1);
            fma2(accB[e], v.x, pB0); fma2(accB[e], v.y, pB1);
        }
    }
    const float bA = bn[jj], bB = bn[jj + 64];
    __syncthreads();
    float* const s_y = s_cat;
    #pragma unroll
    for (int e = 0; e < 8; e++) {
        s_y[(nbv + e) * H + jj]      = silu_f(hadd2(accA[e]) + bA);
        s_y[(nbv + e) * H + jj + 64] = silu_f(hadd2(accB[e]) + bB);
    }
    __syncthreads();

    const int lane = tid & 31, wrp = tid >> 5;
    const float ga = gn[lane], gb = gn[lane + 32], gc = gn[lane + 64], gd = gn[lane + 96];
    const float ba = btn[lane], bb = btn[lane + 32], bcv = btn[lane + 64], bd = btn[lane + 96];
    #pragma unroll
    for (int qq = 0; qq < 4; qq++) {
        const int nl = wrp * 4 + qq;
        const int n = n0 + nl;
        float v0 = s_y[nl * H + lane], v1 = s_y[nl * H + lane + 32];
        float v2 = s_y[nl * H + lane + 64], v3 = s_y[nl * H + lane + 96];
        float s1 = v0 + v1 + v2 + v3;
        float s2 = v0 * v0 + v1 * v1 + v2 * v2 + v3 * v3;
        #pragma unroll
        for (int o = 16; o; o >>= 1) {
            s1 += __shfl_xor_sync(0xffffffffu, s1, o);
            s2 += __shfl_xor_sync(0xffffffffu, s2, o);
        }
        const float m = s1 * (1.f / 128.f);
        const float var = s2 * (1.f / 128.f) - m * m;
        const float rstd = rsqrtf(var + 1e-5f);
        if (n < NN) {
            out[n * H + lane]      = x[n * H + lane]      + (v0 - m) * rstd * ga + ba;
            out[n * H + lane + 32] = x[n * H + lane + 32] + (v1 - m) * rstd * gb + bb;
            out[n * H + lane + 64] = x[n * H + lane + 64] + (v2 - m) * rstd * gc + bcv;
            out[n * H + lane + 96] = x[n * H + lane + 96] + (v3 - m) * rstd * gd + bd;
        }
    }
    if (tid < TN) {
        const int n = n0 + tid;
        if (n < NN) {
            const float c = fmaxf(g_cnt[n], 1.f);
            const float s = 0.1f / c;
            out[NN * H + n * 3 + 0] = pos[n * 3 + 0] + s * g_delta[n * 3 + 0];
            out[NN * H + n * 3 + 1] = pos[n * 3 + 1] + s * g_delta[n * 3 + 1];
            out[NN * H + n * 3 + 2] = pos[n * 3 + 2] + s * g_delta[n * 3 + 2];
        }
    }

    // ---- re-zero scratch for next launch ----
    __syncthreads();
    const float4 z4 = make_float4(0.f, 0.f, 0.f, 0.f);
    for (int idx = tid; idx < TN * 32; idx += 256) {
        const int nl = idx >> 5, j4 = idx & 31;
        const int n = n0 + nl;
        if (n < NN) *(float4*)&g_agg[n * H + j4 * 4] = z4;
    }
    if (tid < TN) {
        const int n = n0 + tid;
        if (n < NN) {
            g_cnt[n] = 0.f;
            g_delta[n * 3 + 0] = 0.f;
            g_delta[n * 3 + 1] = 0.f;
            g_delta[n * 3 + 2] = 0.f;
        }
    }
}

extern "C" void kernel_launch(void* const* d_in, const int* in_sizes, int n_in,
                              void* d_out, int out_size) {
    const float* x         = (const float*)d_in[0];
    const float* pos       = (const float*)d_in[1];
    const float* charge    = (const float*)d_in[2];
    const float* edge_attr = (const float*)d_in[3];
    const int*   edge_index= (const int*)d_in[4];
    const float* We1 = (const float*)d_in[5];
    const float* be1 = (const float*)d_in[6];
    const float* g1  = (const float*)d_in[7];
    const float* bt1 = (const float*)d_in[8];
    const float* We2 = (const float*)d_in[9];
    const float* be2 = (const float*)d_in[10];
    const float* Wn  = (const float*)d_in[11];
    const float* bn  = (const float*)d_in[12];
    const float* gn  = (const float*)d_in[13];
    const float* btn = (const float*)d_in[14];
    const float* Wc1 = (const float*)d_in[15];
    const float* bc1 = (const float*)d_in[16];
    const float* Wc2 = (const float*)d_in[17];
    const float* bc2 = (const float*)d_in[18];
    float* out = (float*)d_out;

    cudaFuncSetAttribute(edge_kernel, cudaFuncAttributeMaxDynamicSharedMemorySize, SMEM_EDGE);
    edge_kernel<<<NE / TE, 256, SMEM_EDGE>>>(x, pos, charge, edge_attr, edge_index,
                                             We1, be1, g1, bt1, We2, be2, Wc1, bc1, Wc2, bc2);
    node_kernel<<<(NN + TN - 1) / TN, 256>>>(x, pos, Wn, bn, gn, btn, out);
}

// round 10
// speedup vs baseline: 1.2973x; 1.2973x over previous
#include <cuda_runtime.h>
#include <math.h>
#include <stdint.h>

#define NN 50000
#define NE 800000
#define H 128
#define NRAD 16
#define TE 64              // edges per block
#define TN 32              // nodes per block
#define HS  132            // pre/h/eh row stride: mod32=4 -> conflict-free frags
#define SBN 136            // weight chunk stride (N=128): mod32=8
#define SBN3 72            // weight chunk stride (N=64): mod32=8
#define EFS 24             // small-feature row stride (19 used, pad 24)
#define PI_F 3.14159265358979f

// ---- edge kernel dynamic smem layout (bytes) ----
#define OFF_PRE 0
#define SZ_PRE  (TE * HS * 4)              // 33792 ; s_eh overlays later
#define OFF_H   (OFF_PRE + SZ_PRE)         // 33792
#define SZ_H    (TE * HS * 4)              // 33792
#define OFF_B0  (OFF_H + SZ_H)             // 67584
#define SZ_B    (32 * SBN * 4)             // 17408
#define OFF_B1  (OFF_B0 + SZ_B)            // 84992
#define OFF_EFS (OFF_B1 + SZ_B)            // 102400
#define SZ_EFS  (TE * EFS * 4)             // 6144
#define SMEM_EDGE (OFF_EFS + SZ_EFS)       // 108544

// ---- pre kernel (PQ = x @ [We1a|We1b]) smem layout ----
#define XS 132
#define SBNP 264
#define OFF_X   0
#define SZ_X    (64 * XS * 4)              // 33792
#define OFF_PB0 (OFF_X + SZ_X)
#define SZ_PB   (32 * SBNP * 4)            // 33792
#define OFF_PB1 (OFF_PB0 + SZ_PB)
#define SMEM_PRE (OFF_PB1 + SZ_PB)         // 101376

typedef unsigned long long u64t;

__device__ float g_pq[NN * 256];           // [N][256]: cols 0..127 = x@We1a, 128..255 = x@We1b
__device__ float g_agg[NN * H];
__device__ float g_cnt[NN];
__device__ float g_delta[NN * 3];

__device__ __forceinline__ float silu_f(float v) { return v / (1.f + __expf(-v)); }

__device__ __forceinline__ float tf32r(float f) {
    uint32_t u; asm("cvt.rna.tf32.f32 %0, %1;" : "=r"(u) : "f"(f));
    return __uint_as_float(u);
}
__device__ __forceinline__ float4 tf32r4(float4 v) {
    v.x = tf32r(v.x); v.y = tf32r(v.y); v.z = tf32r(v.z); v.w = tf32r(v.w);
    return v;
}
__device__ __forceinline__ void mma_tf32(float* d, uint32_t a0, uint32_t a1, uint32_t a2,
                                         uint32_t a3, uint32_t b0, uint32_t b1) {
    asm("mma.sync.aligned.m16n8k8.row.col.f32.tf32.tf32.f32 "
        "{%0,%1,%2,%3},{%4,%5,%6,%7},{%8,%9},{%0,%1,%2,%3};"
        : "+f"(d[0]), "+f"(d[1]), "+f"(d[2]), "+f"(d[3])
        : "r"(a0), "r"(a1), "r"(a2), "r"(a3), "r"(b0), "r"(b1));
}

__device__ __forceinline__ void fma2(u64t& d, u64t a, u64t b) {
    asm("fma.rn.f32x2 %0, %1, %2, %0;" : "+l"(d) : "l"(a), "l"(b));
}
__device__ __forceinline__ u64t pack2(float lo, float hi) {
    u64t d; asm("mov.b64 %0, {%1, %2};" : "=l"(d) : "f"(lo), "f"(hi)); return d;
}
__device__ __forceinline__ float hadd2(u64t d) {
    float lo, hi; asm("mov.b64 {%0, %1}, %2;" : "=f"(lo), "=f"(hi) : "l"(d));
    return lo + hi;
}

// ================== PQ = x @ [We1a | We1b] : [N,256] ==================
__global__ __launch_bounds__(256) void pre_kernel(
    const float* __restrict__ x, const float* __restrict__ We1)
{
    extern __shared__ __align__(16) char dsm[];
    float* const s_x  = (float*)(dsm + OFF_X);     // [64][132] tf32
    float* const s_P0 = (float*)(dsm + OFF_PB0);   // [32][264]
    float* const s_P1 = (float*)(dsm + OFF_PB1);

    const int tid = threadIdx.x;
    const int n0 = blockIdx.x * 64;
    const float4 z4 = make_float4(0.f, 0.f, 0.f, 0.f);

    for (int idx = tid; idx < 64 * 32; idx += 256) {
        const int e = idx >> 5, j4 = idx & 31;
        const int n = n0 + e;
        float4 v = (n < NN) ? tf32r4(*(const float4*)&x[n * H + j4 * 4]) : z4;
        *(float4*)&s_x[e * XS + j4 * 4] = v;
    }

    const int lane = tid & 31, w = tid >> 5;
    const int g = lane >> 2, tg = lane & 3;
    const int m0 = (w & 1) * 32;
    const int nb = (w >> 1) * 64;
    const int kk = tid >> 3, q = tid & 7;

    float d[2][8][4];
    #pragma unroll
    for (int mi = 0; mi < 2; mi++)
        #pragma unroll
        for (int t = 0; t < 8; t++)
            #pragma unroll
            for (int i = 0; i < 4; i++) d[mi][t][i] = 0.f;

    float4 ra0, ra1, ra2, ra3, rb0, rb1, rb2, rb3;
    // preload chunk 0: row kk, cols: part-a q*16.., part-b 128+q*16..
    {
        const float* sa = &We1[kk * H + q * 16];
        const float* sb = &We1[(128 + kk) * H + q * 16];
        ra0 = tf32r4(*(const float4*)(sa + 0));  ra1 = tf32r4(*(const float4*)(sa + 4));
        ra2 = tf32r4(*(const float4*)(sa + 8));  ra3 = tf32r4(*(const float4*)(sa + 12));
        rb0 = tf32r4(*(const float4*)(sb + 0));  rb1 = tf32r4(*(const float4*)(sb + 4));
        rb2 = tf32r4(*(const float4*)(sb + 8));  rb3 = tf32r4(*(const float4*)(sb + 12));
        float* dw = &s_P0[kk * SBNP];
        *(float4*)(dw + q * 16 + 0) = ra0; *(float4*)(dw + q * 16 + 4) = ra1;
        *(float4*)(dw + q * 16 + 8) = ra2; *(float4*)(dw + q * 16 + 12) = ra3;
        *(float4*)(dw + 128 + q * 16 + 0) = rb0; *(float4*)(dw + 128 + q * 16 + 4) = rb1;
        *(float4*)(dw + 128 + q * 16 + 8) = rb2; *(float4*)(dw + 128 + q * 16 + 12) = rb3;
    }
    for (int c = 0; c < 4; c++) {
        if (c < 3) {
            const int k = (c + 1) * 32 + kk;
            const float* sa = &We1[k * H + q * 16];
            const float* sb = &We1[(128 + k) * H + q * 16];
            ra0 = tf32r4(*(const float4*)(sa + 0));  ra1 = tf32r4(*(const float4*)(sa + 4));
            ra2 = tf32r4(*(const float4*)(sa + 8));  ra3 = tf32r4(*(const float4*)(sa + 12));
            rb0 = tf32r4(*(const float4*)(sb + 0));  rb1 = tf32r4(*(const float4*)(sb + 4));
            rb2 = tf32r4(*(const float4*)(sb + 8));  rb3 = tf32r4(*(const float4*)(sb + 12));
        }
        __syncthreads();
        const float* bp = (c & 1) ? s_P1 : s_P0;
        #pragma unroll
        for (int ks = 0; ks < 4; ks++) {
            const int kg = c * 32 + ks * 8, kl = ks * 8;
            uint32_t a[2][4];
            #pragma unroll
            for (int mi = 0; mi < 2; mi++) {
                const int rA = m0 + mi * 16 + g;
                a[mi][0] = __float_as_uint(s_x[rA * XS + kg + tg]);
                a[mi][1] = __float_as_uint(s_x[(rA + 8) * XS + kg + tg]);
                a[mi][2] = __float_as_uint(s_x[rA * XS + kg + 4 + tg]);
                a[mi][3] = __float_as_uint(s_x[(rA + 8) * XS + kg + 4 + tg]);
            }
            #pragma unroll
            for (int t = 0; t < 8; t++) {
                const uint32_t b0 = __float_as_uint(bp[(kl + tg) * SBNP + nb + t * 8 + g]);
                const uint32_t b1 = __float_as_uint(bp[(kl + 4 + tg) * SBNP + nb + t * 8 + g]);
                mma_tf32(d[0][t], a[0][0], a[0][1], a[0][2], a[0][3], b0, b1);
                mma_tf32(d[1][t], a[1][0], a[1][1], a[1][2], a[1][3], b0, b1);
            }
        }
        if (c < 3) {
            float* np = (c & 1) ? s_P0 : s_P1;
            float* dw = &np[kk * SBNP];
            *(float4*)(dw + q * 16 + 0) = ra0; *(float4*)(dw + q * 16 + 4) = ra1;
            *(float4*)(dw + q * 16 + 8) = ra2; *(float4*)(dw + q * 16 + 12) = ra3;
            *(float4*)(dw + 128 + q * 16 + 0) = rb0; *(float4*)(dw + 128 + q * 16 + 4) = rb1;
            *(float4*)(dw + 128 + q * 16 + 8) = rb2; *(float4*)(dw + 128 + q * 16 + 12) = rb3;
        }
    }

    // write PQ
    #pragma unroll
    for (int mi = 0; mi < 2; mi++) {
        const int r0w = n0 + m0 + mi * 16 + g;
        #pragma unroll
        for (int t = 0; t < 8; t++) {
            const int col = nb + t * 8 + tg * 2;
            if (r0w < NN)
                *(float2*)&g_pq[r0w * 256 + col] = make_float2(d[mi][t][0], d[mi][t][1]);
            if (r0w + 8 < NN)
                *(float2*)&g_pq[(r0w + 8) * 256 + col] = make_float2(d[mi][t][2], d[mi][t][3]);
        }
    }
}

// ================== edge kernel ==================
__global__ __launch_bounds__(256) void edge_kernel(
    const float* __restrict__ pos,
    const float* __restrict__ charge, const float* __restrict__ edge_attr,
    const int* __restrict__ edge_index,
    const float* __restrict__ We1, const float* __restrict__ be1,
    const float* __restrict__ g1, const float* __restrict__ bt1,
    const float* __restrict__ We2, const float* __restrict__ be2,
    const float* __restrict__ Wc1, const float* __restrict__ bc1,
    const float* __restrict__ Wc2, const float* __restrict__ bc2)
{
    extern __shared__ __align__(16) char dsm[];
    float* const s_pre = (float*)(dsm + OFF_PRE);  // [64][132] fp32 P[src]+Q[dst]
    float* const s_eh  = (float*)(dsm + OFF_PRE);  // overlays pre after epilogue1
    float* const s_h   = (float*)(dsm + OFF_H);    // [64][132]
    float* const s_B0  = (float*)(dsm + OFF_B0);
    float* const s_B1  = (float*)(dsm + OFF_B1);
    float* const efs   = (float*)(dsm + OFF_EFS);  // [64][24] small features (tf32)

    __shared__ float s_gate[TE];
    __shared__ float s_unit[TE][3];
    __shared__ int   s_src[TE];
    __shared__ float s_coord[TE];

    const int tid = threadIdx.x;
    const int e0 = blockIdx.x * TE;

    // ---- per-edge scalars -> efs ----
    if (tid < TE) {
        const int e = e0 + tid;
        const int src = edge_index[e];
        const int dst = edge_index[NE + e];
        s_src[tid] = src;
        const float rx = pos[dst * 3 + 0] - pos[src * 3 + 0];
        const float ry = pos[dst * 3 + 1] - pos[src * 3 + 1];
        const float rz = pos[dst * 3 + 2] - pos[src * 3 + 2];
        const float dist = sqrtf(rx * rx + ry * ry + rz * rz + 1e-8f);
        const float inv = 1.f / dist;
        s_unit[tid][0] = rx * inv; s_unit[tid][1] = ry * inv; s_unit[tid][2] = rz * inv;

        const float4 ea = *(const float4*)&edge_attr[e * 4];
        float ca = cosf(ea.x);
        float p2 = 0.5f * (3.f * ca * ca - 1.f);
        float p3 = (5.f * ca * p2 - 2.f * ca) * (1.f / 3.f);
        float a_score = 0.25f * (1.f + fabsf(ca) + fabsf(p2) + fabsf(p3)) * ea.z;
        float cd = cosf(ea.y);
        float q2 = 0.5f * (3.f * cd * cd - 1.f);
        float q3 = (5.f * cd * q2 - 2.f * cd) * (1.f / 3.f);
        float d_score = 0.25f * (1.f + fabsf(cd) + fabsf(q2) + fabsf(q3)) * ea.w;
        float gate = fminf(fmaxf(1.f + 0.6f * (a_score + d_score), 0.35f), 2.5f);
        s_gate[tid] = gate;
        s_coord[tid] = bc2[0];

        const float qs = charge[src], qd = charge[dst];
        float* row = &efs[tid * EFS];
        const float gi = gate * inv;
        #pragma unroll
        for (int i = 0; i < NRAD; i++) {
            float f = (float)(i + 1) * (PI_F / 5.0f);
            row[i] = tf32r(sinf(f * dist) * gi);
        }
        row[16] = tf32r(dist * 0.2f * gate);
        row[17] = tf32r(qs * qd * gate);
        row[18] = tf32r(fabsf(qs - qd) * gate);
        #pragma unroll
        for (int i = 19; i < EFS; i++) row[i] = 0.f;
    }

    // ---- gather pre = P[src] + Q[dst] ----
    for (int idx = tid; idx < TE * 32; idx += 256) {
        const int e = idx >> 5, j4 = idx & 31;
        const int src = edge_index[e0 + e];
        const int dst = edge_index[NE + e0 + e];
        float4 a = *(const float4*)&g_pq[src * 256 + j4 * 4];
        const float4 b = *(const float4*)&g_pq[dst * 256 + 128 + j4 * 4];
        a.x += b.x; a.y += b.y; a.z += b.z; a.w += b.w;
        *(float4*)&s_pre[e * HS + j4 * 4] = a;
    }

    const int lane = tid & 31, w = tid >> 5;
    const int g = lane >> 2, tg = lane & 3;
    const int m0 = (w & 1) * 32;
    const int nb = (w >> 1) * 32;
    const int nb3 = (w >> 1) * 16;
    const int kk = tid >> 3, q = tid & 7;

    // ---- stage We1c (rows 256..274, pad 32) into s_B0 ----
    {
        float* dw = &s_B0[kk * SBN + q * 16];
        if (kk < 19) {
            const float* s = &We1[(256 + kk) * H + q * 16];
            *(float4*)(dw + 0) = tf32r4(*(const float4*)(s + 0));
            *(float4*)(dw + 4) = tf32r4(*(const float4*)(s + 4));
            *(float4*)(dw + 8) = tf32r4(*(const float4*)(s + 8));
            *(float4*)(dw + 12) = tf32r4(*(const float4*)(s + 12));
        } else {
            const float4 z = make_float4(0.f, 0.f, 0.f, 0.f);
            *(float4*)(dw + 0) = z; *(float4*)(dw + 4) = z;
            *(float4*)(dw + 8) = z; *(float4*)(dw + 12) = z;
        }
    }
    __syncthreads();

    float d[2][4][4];
    #pragma unroll
    for (int mi = 0; mi < 2; mi++)
        #pragma unroll
        for (int t = 0; t < 4; t++)
            #pragma unroll
            for (int i = 0; i < 4; i++) d[mi][t][i] = 0.f;

    // ---- GEMM1-small: efs[64x24] @ We1c[24x128] ----
    #pragma unroll
    for (int ks = 0; ks < 3; ks++) {
        const int kg = ks * 8;
        uint32_t a[2][4];
        #pragma unroll
        for (int mi = 0; mi < 2; mi++) {
            const int rA = m0 + mi * 16 + g;
            a[mi][0] = __float_as_uint(efs[rA * EFS + kg + tg]);
            a[mi][1] = __float_as_uint(efs[(rA + 8) * EFS + kg + tg]);
            a[mi][2] = __float_as_uint(efs[rA * EFS + kg + 4 + tg]);
            a[mi][3] = __float_as_uint(efs[(rA + 8) * EFS + kg + 4 + tg]);
        }
        #pragma unroll
        for (int t = 0; t < 4; t++) {
            const uint32_t b0 = __float_as_uint(s_B0[(kg + tg) * SBN + nb + t * 8 + g]);
            const uint32_t b1 = __float_as_uint(s_B0[(kg + 4 + tg) * SBN + nb + t * 8 + g]);
            mma_tf32(d[0][t], a[0][0], a[0][1], a[0][2], a[0][3], b0, b1);
            mma_tf32(d[1][t], a[1][0], a[1][1], a[1][2], a[1][3], b0, b1);
        }
    }

    // ---- epilogue1: h = silu(d + pre + be1) -> s_h ----
    #pragma unroll
    for (int t = 0; t < 4; t++) {
        const int col = nb + t * 8 + tg * 2;
        const float bb0 = be1[col], bb1 = be1[col + 1];
        #pragma unroll
        for (int mi = 0; mi < 2; mi++) {
            const int rA = m0 + mi * 16 + g;
            s_h[rA * HS + col]           = silu_f(d[mi][t][0] + s_pre[rA * HS + col] + bb0);
            s_h[rA * HS + col + 1]       = silu_f(d[mi][t][1] + s_pre[rA * HS + col + 1] + bb1);
            s_h[(rA + 8) * HS + col]     = silu_f(d[mi][t][2] + s_pre[(rA + 8) * HS + col] + bb0);
            s_h[(rA + 8) * HS + col + 1] = silu_f(d[mi][t][3] + s_pre[(rA + 8) * HS + col + 1] + bb1);
        }
    }
    __syncthreads();

    // ---- LayerNorm(h): warp per 8 edges; write tf32 ----
    {
        const float ga = g1[lane], gb = g1[lane + 32], gc = g1[lane + 64], gd = g1[lane + 96];
        const float ba = bt1[lane], bb = bt1[lane + 32], bcv = bt1[lane + 64], bd = bt1[lane + 96];
        #pragma unroll
        for (int qq = 0; qq < 8; qq++) {
            const int e = w * 8 + qq;
            float v0 = s_h[e * HS + lane], v1 = s_h[e * HS + lane + 32];
            float v2 = s_h[e * HS + lane + 64], v3 = s_h[e * HS + lane + 96];
            float s1 = v0 + v1 + v2 + v3;
            float s2 = v0 * v0 + v1 * v1 + v2 * v2 + v3 * v3;
            #pragma unroll
            for (int o = 16; o; o >>= 1) {
                s1 += __shfl_xor_sync(0xffffffffu, s1, o);
                s2 += __shfl_xor_sync(0xffffffffu, s2, o);
            }
            const float m = s1 * (1.f / 128.f);
            const float var = s2 * (1.f / 128.f) - m * m;
            const float rstd = rsqrtf(var + 1e-5f);
            s_h[e * HS + lane]      = tf32r((v0 - m) * rstd * ga + ba);
            s_h[e * HS + lane + 32] = tf32r((v1 - m) * rstd * gb + bb);
            s_h[e * HS + lane + 64] = tf32r((v2 - m) * rstd * gc + bcv);
            s_h[e * HS + lane + 96] = tf32r((v3 - m) * rstd * gd + bd);
        }
    }

    // ================= GEMM2: h[64x128] @ We2[128x128] =================
    #pragma unroll
    for (int mi = 0; mi < 2; mi++)
        #pragma unroll
        for (int t = 0; t < 4; t++)
            #pragma unroll
            for (int i = 0; i < 4; i++) d[mi][t][i] = 0.f;
    float4 r0, r1, r2, r3;
    {
        {
            const float* s = &We2[kk * H + q * 16];
            r0 = tf32r4(*(const float4*)(s + 0));
            r1 = tf32r4(*(const float4*)(s + 4));
            r2 = tf32r4(*(const float4*)(s + 8));
            r3 = tf32r4(*(const float4*)(s + 12));
            float* dw = &s_B0[kk * SBN + q * 16];
            *(float4*)(dw + 0) = r0; *(float4*)(dw + 4) = r1;
            *(float4*)(dw + 8) = r2; *(float4*)(dw + 12) = r3;
        }
        for (int c = 0; c < 4; c++) {
            if (c < 3) {
                const float* s = &We2[((c + 1) * 32 + kk) * H + q * 16];
                r0 = tf32r4(*(const float4*)(s + 0));
                r1 = tf32r4(*(const float4*)(s + 4));
                r2 = tf32r4(*(const float4*)(s + 8));
                r3 = tf32r4(*(const float4*)(s + 12));
            }
            __syncthreads();
            const float* bp = (c & 1) ? s_B1 : s_B0;
            #pragma unroll
            for (int ks = 0; ks < 4; ks++) {
                const int kg = c * 32 + ks * 8, kl = ks * 8;
                uint32_t a[2][4];
                #pragma unroll
                for (int mi = 0; mi < 2; mi++) {
                    const int rA = m0 + mi * 16 + g;
                    a[mi][0] = __float_as_uint(s_h[rA * HS + kg + tg]);
                    a[mi][1] = __float_as_uint(s_h[(rA + 8) * HS + kg + tg]);
                    a[mi][2] = __float_as_uint(s_h[rA * HS + kg + 4 + tg]);
                    a[mi][3] = __float_as_uint(s_h[(rA + 8) * HS + kg + 4 + tg]);
                }
                #pragma unroll
                for (int t = 0; t < 4; t++) {
                    const uint32_t b0 = __float_as_uint(bp[(kl + tg) * SBN + nb + t * 8 + g]);
                    const uint32_t b1 = __float_as_uint(bp[(kl + 4 + tg) * SBN + nb + t * 8 + g]);
                    mma_tf32(d[0][t], a[0][0], a[0][1], a[0][2], a[0][3], b0, b1);
                    mma_tf32(d[1][t], a[1][0], a[1][1], a[1][2], a[1][3], b0, b1);
                }
            }
            if (c < 3) {
                float* np = (c & 1) ? s_B0 : s_B1;
                float* dw = &np[kk * SBN + q * 16];
                *(float4*)(dw + 0) = r0; *(float4*)(dw + 4) = r1;
                *(float4*)(dw + 8) = r2; *(float4*)(dw + 12) = r3;
            }
        }
    }
    __syncthreads();   // all GEMM2 reads of s_h / s_pre region done before eh overlay

    // ---- epilogue2: eh = silu(+be2) -> s_eh (overlays pre; tf32) ----
    #pragma unroll
    for (int t = 0; t < 4; t++) {
        const int col = nb + t * 8 + tg * 2;
        const float bb0 = be2[col], bb1 = be2[col + 1];
        #pragma unroll
        for (int mi = 0; mi < 2; mi++) {
            const int rA = m0 + mi * 16 + g;
            s_eh[rA * HS + col]           = tf32r(silu_f(d[mi][t][0] + bb0));
            s_eh[rA * HS + col + 1]       = tf32r(silu_f(d[mi][t][1] + bb1));
            s_eh[(rA + 8) * HS + col]     = tf32r(silu_f(d[mi][t][2] + bb0));
            s_eh[(rA + 8) * HS + col + 1] = tf32r(silu_f(d[mi][t][3] + bb1));
        }
    }

    // ================= GEMM3: eh[64x128] @ Wc1[128x64] =================
    float d3[2][2][4];
    #pragma unroll
    for (int mi = 0; mi < 2; mi++)
        #pragma unroll
        for (int t = 0; t < 2; t++)
            #pragma unroll
            for (int i = 0; i < 4; i++) d3[mi][t][i] = 0.f;
    {
        {
            const float* s = &Wc1[kk * 64 + q * 8];
            r0 = tf32r4(*(const float4*)(s + 0));
            r1 = tf32r4(*(const float4*)(s + 4));
            float* dw = &s_B0[kk * SBN3 + q * 8];
            *(float4*)(dw + 0) = r0; *(float4*)(dw + 4) = r1;
        }
        for (int c = 0; c < 4; c++) {
            if (c < 3) {
                const float* s = &Wc1[((c + 1) * 32 + kk) * 64 + q * 8];
                r0 = tf32r4(*(const float4*)(s + 0));
                r1 = tf32r4(*(const float4*)(s + 4));
            }
            __syncthreads();
            const float* bp = (c & 1) ? s_B1 : s_B0;
            #pragma unroll
            for (int ks = 0; ks < 4; ks++) {
                const int kg = c * 32 + ks * 8, kl = ks * 8;
                uint32_t a[2][4];
                #pragma unroll
                for (int mi = 0; mi < 2; mi++) {
                    const int rA = m0 + mi * 16 + g;
                    a[mi][0] = __float_as_uint(s_eh[rA * HS + kg + tg]);
                    a[mi][1] = __float_as_uint(s_eh[(rA + 8) * HS + kg + tg]);
                    a[mi][2] = __float_as_uint(s_eh[rA * HS + kg + 4 + tg]);
                    a[mi][3] = __float_as_uint(s_eh[(rA + 8) * HS + kg + 4 + tg]);
                }
                #pragma unroll
                for (int t = 0; t < 2; t++) {
                    const uint32_t b0 = __float_as_uint(bp[(kl + tg) * SBN3 + nb3 + t * 8 + g]);
                    const uint32_t b1 = __float_as_uint(bp[(kl + 4 + tg) * SBN3 + nb3 + t * 8 + g]);
                    mma_tf32(d3[0][t], a[0][0], a[0][1], a[0][2], a[0][3], b0, b1);
                    mma_tf32(d3[1][t], a[1][0], a[1][1], a[1][2], a[1][3], b0, b1);
                }
            }
            if (c < 3) {
                float* np = (c & 1) ? s_B0 : s_B1;
                float* dw = &np[kk * SBN3 + q * 8];
                *(float4*)(dw + 0) = r0; *(float4*)(dw + 4) = r1;
            }
        }
    }

    // ---- epilogue3: coord partial = silu(+bc1) @ Wc2 ----
    #pragma unroll
    for (int mi = 0; mi < 2; mi++) {
        float sA = 0.f, sB2 = 0.f;
        #pragma unroll
        for (int t = 0; t < 2; t++) {
            const int col = nb3 + t * 8 + tg * 2;
            const float w0 = Wc2[col], w1 = Wc2[col + 1];
            const float c0 = bc1[col], c1 = bc1[col + 1];
            sA  += silu_f(d3[mi][t][0] + c0) * w0 + silu_f(d3[mi][t][1] + c1) * w1;
            sB2 += silu_f(d3[mi][t][2] + c0) * w0 + silu_f(d3[mi][t][3] + c1) * w1;
        }
        const int rA = m0 + mi * 16 + g;
        atomicAdd(&s_coord[rA], sA);
        atomicAdd(&s_coord[rA + 8], sB2);
    }
    __syncthreads();

    // ---- scatter ----
    for (int idx = tid; idx < TE * H; idx += 256) {
        const int e = idx >> 7, jc = idx & (H - 1);
        atomicAdd(&g_agg[s_src[e] * H + jc], s_eh[e * HS + jc]);
    }
    if (tid < TE) {
        const int src = s_src[tid];
        const float f = s_coord[tid] * s_gate[tid];
        atomicAdd(&g_cnt[src], 1.0f);
        atomicAdd(&g_delta[src * 3 + 0], s_unit[tid][0] * f);
        atomicAdd(&g_delta[src * 3 + 1], s_unit[tid][1] * f);
        atomicAdd(&g_delta[src * 3 + 2], s_unit[tid][2] * f);
    }
}

__global__ __launch_bounds__(256) void node_kernel(
    const float* __restrict__ x, const float* __restrict__ pos,
    const float* __restrict__ Wn, const float* __restrict__ bn,
    const float* __restrict__ gn, const float* __restrict__ btn,
    float* __restrict__ out)
{
    __shared__ __align__(16) float s_cat[TN * 260];
    const int tid = threadIdx.x;
    const int n0 = blockIdx.x * TN;

    for (int idx = tid; idx < TN * 64; idx += 256) {
        const int nl = idx >> 6, j4 = idx & 63;
        const int n = n0 + nl;
        float4 v = make_float4(0.f, 0.f, 0.f, 0.f);
        if (n < NN) {
            if (j4 < 32) {
                v = *(const float4*)&x[n * H + j4 * 4];
            } else {
                const float c = fmaxf(g_cnt[n], 1.f);
                const float iv = 1.f / c;
                v = *(const float4*)&g_agg[n * H + (j4 - 32) * 4];
                v.x *= iv; v.y *= iv; v.z *= iv; v.w *= iv;
            }
        }
        *(float4*)&s_cat[nl * 260 + j4 * 4] = v;
    }
    __syncthreads();

    const int jj = tid & 63, g = tid >> 6;
    const int nbv = g * 8;
    u64t accA[8], accB[8];
    #pragma unroll
    for (int e = 0; e < 8; e++) { accA[e] = 0ull; accB[e] = 0ull; }
    for (int k = 0; k < 256; k += 4) {
        const float wA0 = Wn[(k + 0) * H + jj],      wA1 = Wn[(k + 1) * H + jj];
        const float wA2 = Wn[(k + 2) * H + jj],      wA3 = Wn[(k + 3) * H + jj];
        const float wB0 = Wn[(k + 0) * H + jj + 64], wB1 = Wn[(k + 1) * H + jj + 64];
        const float wB2 = Wn[(k + 2) * H + jj + 64], wB3 = Wn[(k + 3) * H + jj + 64];
        const u64t pA0 = pack2(wA0, wA1), pA1 = pack2(wA2, wA3);
        const u64t pB0 = pack2(wB0, wB1), pB1 = pack2(wB2, wB3);
        #pragma unroll
        for (int e = 0; e < 8; e++) {
            const ulonglong2 v = *(const ulonglong2*)&s_cat[(nbv + e) * 260 + k];
            fma2(accA[e], v.x, pA0); fma2(accA[e], v.y, pA1);
            fma2(accB[e], v.x, pB0); fma2(accB[e], v.y, pB1);
        }
    }
    const float bA = bn[jj], bB = bn[jj + 64];
    __syncthreads();
    float* const s_y = s_cat;
    #pragma unroll
    for (int e = 0; e < 8; e++) {
        s_y[(nbv + e) * H + jj]      = silu_f(hadd2(accA[e]) + bA);
        s_y[(nbv + e) * H + jj + 64] = silu_f(hadd2(accB[e]) + bB);
    }
    __syncthreads();

    const int lane = tid & 31, wrp = tid >> 5;
    const float ga = gn[lane], gb = gn[lane + 32], gc = gn[lane + 64], gd = gn[lane + 96];
    const float ba = btn[lane], bb = btn[lane + 32], bcv = btn[lane + 64], bd = btn[lane + 96];
    #pragma unroll
    for (int qq = 0; qq < 4; qq++) {
        const int nl = wrp * 4 + qq;
        const int n = n0 + nl;
        float v0 = s_y[nl * H + lane], v1 = s_y[nl * H + lane + 32];
        float v2 = s_y[nl * H + lane + 64], v3 = s_y[nl * H + lane + 96];
        float s1 = v0 + v1 + v2 + v3;
        float s2 = v0 * v0 + v1 * v1 + v2 * v2 + v3 * v3;
        #pragma unroll
        for (int o = 16; o; o >>= 1) {
            s1 += __shfl_xor_sync(0xffffffffu, s1, o);
            s2 += __shfl_xor_sync(0xffffffffu, s2, o);
        }
        const float m = s1 * (1.f / 128.f);
        const float var = s2 * (1.f / 128.f) - m * m;
        const float rstd = rsqrtf(var + 1e-5f);
        if (n < NN) {
            out[n * H + lane]      = x[n * H + lane]      + (v0 - m) * rstd * ga + ba;
            out[n * H + lane + 32] = x[n * H + lane + 32] + (v1 - m) * rstd * gb + bb;
            out[n * H + lane + 64] = x[n * H + lane + 64] + (v2 - m) * rstd * gc + bcv;
            out[n * H + lane + 96] = x[n * H + lane + 96] + (v3 - m) * rstd * gd + bd;
        }
    }
    if (tid < TN) {
        const int n = n0 + tid;
        if (n < NN) {
            const float c = fmaxf(g_cnt[n], 1.f);
            const float s = 0.1f / c;
            out[NN * H + n * 3 + 0] = pos[n * 3 + 0] + s * g_delta[n * 3 + 0];
            out[NN * H + n * 3 + 1] = pos[n * 3 + 1] + s * g_delta[n * 3 + 1];
            out[NN * H + n * 3 + 2] = pos[n * 3 + 2] + s * g_delta[n * 3 + 2];
        }
    }

    // ---- re-zero scratch for next launch ----
    __syncthreads();
    const float4 z4 = make_float4(0.f, 0.f, 0.f, 0.f);
    for (int idx = tid; idx < TN * 32; idx += 256) {
        const int nl = idx >> 5, j4 = idx & 31;
        const int n = n0 + nl;
        if (n < NN) *(float4*)&g_agg[n * H + j4 * 4] = z4;
    }
    if (tid < TN) {
        const int n = n0 + tid;
        if (n < NN) {
            g_cnt[n] = 0.f;
            g_delta[n * 3 + 0] = 0.f;
            g_delta[n * 3 + 1] = 0.f;
            g_delta[n * 3 + 2] = 0.f;
        }
    }
}

extern "C" void kernel_launch(void* const* d_in, const int* in_sizes, int n_in,
                              void* d_out, int out_size) {
    const float* x         = (const float*)d_in[0];
    const float* pos       = (const float*)d_in[1];
    const float* charge    = (const float*)d_in[2];
    const float* edge_attr = (const float*)d_in[3];
    const int*   edge_index= (const int*)d_in[4];
    const float* We1 = (const float*)d_in[5];
    const float* be1 = (const float*)d_in[6];
    const float* g1  = (const float*)d_in[7];
    const float* bt1 = (const float*)d_in[8];
    const float* We2 = (const float*)d_in[9];
    const float* be2 = (const float*)d_in[10];
    const float* Wn  = (const float*)d_in[11];
    const float* bn  = (const float*)d_in[12];
    const float* gn  = (const float*)d_in[13];
    const float* btn = (const float*)d_in[14];
    const float* Wc1 = (const float*)d_in[15];
    const float* bc1 = (const float*)d_in[16];
    const float* Wc2 = (const float*)d_in[17];
    const float* bc2 = (const float*)d_in[18];
    float* out = (float*)d_out;

    cudaFuncSetAttribute(pre_kernel, cudaFuncAttributeMaxDynamicSharedMemorySize, SMEM_PRE);
    cudaFuncSetAttribute(edge_kernel, cudaFuncAttributeMaxDynamicSharedMemorySize, SMEM_EDGE);

    pre_kernel<<<(NN + 63) / 64, 256, SMEM_PRE>>>(x, We1);
    edge_kernel<<<NE / TE, 256, SMEM_EDGE>>>(pos, charge, edge_attr, edge_index,
                                             We1, be1, g1, bt1, We2, be2, Wc1, bc1, Wc2, bc2);
    node_kernel<<<(NN + TN - 1) / TN, 256>>>(x, pos, Wn, bn, gn, btn, out);
}

// round 12
// speedup vs baseline: 1.6956x; 1.3070x over previous
#include <cuda_runtime.h>
#include <math.h>
#include <stdint.h>

#define NN 50000
#define NE 800000
#define H 128
#define NRAD 16
#define TE 64              // edges per tile
#define TN 32
#define NTILES (NE / TE)   // 12500
#define GRID_EDGE 148
#define HS  132            // pre/h/eh row stride: mod32=4
#define SBN 136            // weight row stride (N=128): mod32=8
#define SBN3 72            // weight row stride (N=64): mod32=8
#define EFS 24
#define PI_F 3.14159265358979f

// ---- persistent edge kernel dynamic smem layout (bytes) ----
#define OFF_PRE 0
#define SZ_PRE  (TE * HS * 4)               // 33792 (eh overlays per tile)
#define OFF_H   (OFF_PRE + SZ_PRE)          // 33792
#define SZ_H    (TE * HS * 4)               // 33792
#define OFF_W1C (OFF_H + SZ_H)              // 67584
#define SZ_W1C  (32 * SBN * 4)              // 17408
#define OFF_W2  (OFF_W1C + SZ_W1C)          // 84992
#define SZ_W2   (128 * SBN * 4)             // 69632
#define OFF_WC1 (OFF_W2 + SZ_W2)            // 154624
#define SZ_WC1  (128 * SBN3 * 4)            // 36864
#define OFF_EFS (OFF_WC1 + SZ_WC1)          // 191488
#define SZ_EFS  (TE * EFS * 4)              // 6144
#define SMEM_EDGE (OFF_EFS + SZ_EFS)        // 197632

// ---- pre kernel smem ----
#define XS 132
#define SBNP 264
#define OFF_X   0
#define SZ_X    (64 * XS * 4)
#define OFF_PB0 (OFF_X + SZ_X)
#define SZ_PB   (32 * SBNP * 4)
#define OFF_PB1 (OFF_PB0 + SZ_PB)
#define SMEM_PRE (OFF_PB1 + SZ_PB)

typedef unsigned long long u64t;

__device__ float g_pq[NN * 256];
__device__ float g_agg[NN * H];
__device__ float g_cnt[NN];
__device__ float g_delta[NN * 3];

__device__ __forceinline__ float silu_f(float v) { return v / (1.f + __expf(-v)); }

__device__ __forceinline__ float tf32r(float f) {
    uint32_t u; asm("cvt.rna.tf32.f32 %0, %1;" : "=r"(u) : "f"(f));
    return __uint_as_float(u);
}
__device__ __forceinline__ float4 tf32r4(float4 v) {
    v.x = tf32r(v.x); v.y = tf32r(v.y); v.z = tf32r(v.z); v.w = tf32r(v.w);
    return v;
}
__device__ __forceinline__ void mma_tf32(float* d, uint32_t a0, uint32_t a1, uint32_t a2,
                                         uint32_t a3, uint32_t b0, uint32_t b1) {
    asm("mma.sync.aligned.m16n8k8.row.col.f32.tf32.tf32.f32 "
        "{%0,%1,%2,%3},{%4,%5,%6,%7},{%8,%9},{%0,%1,%2,%3};"
        : "+f"(d[0]), "+f"(d[1]), "+f"(d[2]), "+f"(d[3])
        : "r"(a0), "r"(a1), "r"(a2), "r"(a3), "r"(b0), "r"(b1));
}

__device__ __forceinline__ void fma2(u64t& d, u64t a, u64t b) {
    asm("fma.rn.f32x2 %0, %1, %2, %0;" : "+l"(d) : "l"(a), "l"(b));
}
__device__ __forceinline__ u64t pack2(float lo, float hi) {
    u64t d; asm("mov.b64 %0, {%1, %2};" : "=l"(d) : "f"(lo), "f"(hi)); return d;
}
__device__ __forceinline__ float hadd2(u64t d) {
    float lo, hi; asm("mov.b64 {%0, %1}, %2;" : "=f"(lo), "=f"(hi) : "l"(d));
    return lo + hi;
}

// ================== PQ = x @ [We1a | We1b] ==================
__global__ __launch_bounds__(256) void pre_kernel(
    const float* __restrict__ x, const float* __restrict__ We1)
{
    extern __shared__ __align__(16) char dsm[];
    float* const s_x  = (float*)(dsm + OFF_X);
    float* const s_P0 = (float*)(dsm + OFF_PB0);
    float* const s_P1 = (float*)(dsm + OFF_PB1);

    const int tid = threadIdx.x;
    const int n0 = blockIdx.x * 64;
    const float4 z4 = make_float4(0.f, 0.f, 0.f, 0.f);

    for (int idx = tid; idx < 64 * 32; idx += 256) {
        const int e = idx >> 5, j4 = idx & 31;
        const int n = n0 + e;
        float4 v = (n < NN) ? tf32r4(*(const float4*)&x[n * H + j4 * 4]) : z4;
        *(float4*)&s_x[e * XS + j4 * 4] = v;
    }

    const int lane = tid & 31, w = tid >> 5;
    const int g = lane >> 2, tg = lane & 3;
    const int m0 = (w & 1) * 32;
    const int nb = (w >> 1) * 64;
    const int kk = tid >> 3, q = tid & 7;

    float d[2][8][4];
    #pragma unroll
    for (int mi = 0; mi < 2; mi++)
        #pragma unroll
        for (int t = 0; t < 8; t++)
            #pragma unroll
            for (int i = 0; i < 4; i++) d[mi][t][i] = 0.f;

    float4 ra0, ra1, ra2, ra3, rb0, rb1, rb2, rb3;
    {
        const float* sa = &We1[kk * H + q * 16];
        const float* sb = &We1[(128 + kk) * H + q * 16];
        ra0 = tf32r4(*(const float4*)(sa + 0));  ra1 = tf32r4(*(const float4*)(sa + 4));
        ra2 = tf32r4(*(const float4*)(sa + 8));  ra3 = tf32r4(*(const float4*)(sa + 12));
        rb0 = tf32r4(*(const float4*)(sb + 0));  rb1 = tf32r4(*(const float4*)(sb + 4));
        rb2 = tf32r4(*(const float4*)(sb + 8));  rb3 = tf32r4(*(const float4*)(sb + 12));
        float* dw = &s_P0[kk * SBNP];
        *(float4*)(dw + q * 16 + 0) = ra0; *(float4*)(dw + q * 16 + 4) = ra1;
        *(float4*)(dw + q * 16 + 8) = ra2; *(float4*)(dw + q * 16 + 12) = ra3;
        *(float4*)(dw + 128 + q * 16 + 0) = rb0; *(float4*)(dw + 128 + q * 16 + 4) = rb1;
        *(float4*)(dw + 128 + q * 16 + 8) = rb2; *(float4*)(dw + 128 + q * 16 + 12) = rb3;
    }
    for (int c = 0; c < 4; c++) {
        if (c < 3) {
            const int k = (c + 1) * 32 + kk;
            const float* sa = &We1[k * H + q * 16];
            const float* sb = &We1[(128 + k) * H + q * 16];
            ra0 = tf32r4(*(const float4*)(sa + 0));  ra1 = tf32r4(*(const float4*)(sa + 4));
            ra2 = tf32r4(*(const float4*)(sa + 8));  ra3 = tf32r4(*(const float4*)(sa + 12));
            rb0 = tf32r4(*(const float4*)(sb + 0));  rb1 = tf32r4(*(const float4*)(sb + 4));
            rb2 = tf32r4(*(const float4*)(sb + 8));  rb3 = tf32r4(*(const float4*)(sb + 12));
        }
        __syncthreads();
        const float* bp = (c & 1) ? s_P1 : s_P0;
        #pragma unroll
        for (int ks = 0; ks < 4; ks++) {
            const int kg = c * 32 + ks * 8, kl = ks * 8;
            uint32_t a[2][4];
            #pragma unroll
            for (int mi = 0; mi < 2; mi++) {
                const int rA = m0 + mi * 16 + g;
                a[mi][0] = __float_as_uint(s_x[rA * XS + kg + tg]);
                a[mi][1] = __float_as_uint(s_x[(rA + 8) * XS + kg + tg]);
                a[mi][2] = __float_as_uint(s_x[rA * XS + kg + 4 + tg]);
                a[mi][3] = __float_as_uint(s_x[(rA + 8) * XS + kg + 4 + tg]);
            }
            #pragma unroll
            for (int t = 0; t < 8; t++) {
                const uint32_t b0 = __float_as_uint(bp[(kl + tg) * SBNP + nb + t * 8 + g]);
                const uint32_t b1 = __float_as_uint(bp[(kl + 4 + tg) * SBNP + nb + t * 8 + g]);
                mma_tf32(d[0][t], a[0][0], a[0][1], a[0][2], a[0][3], b0, b1);
                mma_tf32(d[1][t], a[1][0], a[1][1], a[1][2], a[1][3], b0, b1);
            }
        }
        if (c < 3) {
            float* np = (c & 1) ? s_P0 : s_P1;
            float* dw = &np[kk * SBNP];
            *(float4*)(dw + q * 16 + 0) = ra0; *(float4*)(dw + q * 16 + 4) = ra1;
            *(float4*)(dw + q * 16 + 8) = ra2; *(float4*)(dw + q * 16 + 12) = ra3;
            *(float4*)(dw + 128 + q * 16 + 0) = rb0; *(float4*)(dw + 128 + q * 16 + 4) = rb1;
            *(float4*)(dw + 128 + q * 16 + 8) = rb2; *(float4*)(dw + 128 + q * 16 + 12) = rb3;
        }
    }

    #pragma unroll
    for (int mi = 0; mi < 2; mi++) {
        const int r0w = n0 + m0 + mi * 16 + g;
        #pragma unroll
        for (int t = 0; t < 8; t++) {
            const int col = nb + t * 8 + tg * 2;
            if (r0w < NN)
                *(float2*)&g_pq[r0w * 256 + col] = make_float2(d[mi][t][0], d[mi][t][1]);
            if (r0w + 8 < NN)
                *(float2*)&g_pq[(r0w + 8) * 256 + col] = make_float2(d[mi][t][2], d[mi][t][3]);
        }
    }
}

// ================== persistent edge kernel ==================
__global__ __launch_bounds__(256) void edge_kernel(
    const float* __restrict__ pos,
    const float* __restrict__ charge, const float* __restrict__ edge_attr,
    const int* __restrict__ edge_index,
    const float* __restrict__ We1, const float* __restrict__ be1,
    const float* __restrict__ g1, const float* __restrict__ bt1,
    const float* __restrict__ We2, const float* __restrict__ be2,
    const float* __restrict__ Wc1, const float* __restrict__ bc1,
    const float* __restrict__ Wc2, const float* __restrict__ bc2)
{
    extern __shared__ __align__(16) char dsm[];
    float* const s_pre = (float*)(dsm + OFF_PRE);   // [64][132]; eh overlays per tile
    float* const s_eh  = (float*)(dsm + OFF_PRE);
    float* const s_h   = (float*)(dsm + OFF_H);     // [64][132]
    float* const s_W1c = (float*)(dsm + OFF_W1C);   // [32][136]
    float* const s_W2  = (float*)(dsm + OFF_W2);    // [128][136]
    float* const s_Wc1 = (float*)(dsm + OFF_WC1);   // [128][72]
    float* const efs   = (float*)(dsm + OFF_EFS);   // [64][24]

    __shared__ float s_gate[TE];
    __shared__ float s_unit[TE][3];
    __shared__ int   s_src[TE];
    __shared__ float s_coord[TE];

    const int tid = threadIdx.x;
    const float4 z4 = make_float4(0.f, 0.f, 0.f, 0.f);

    // ---- stage ALL weights once (tf32) ----
    for (int idx = tid; idx < 32 * 32; idx += 256) {        // We1c: 32 rows x 128
        const int r = idx >> 5, c4 = (idx & 31) * 4;
        float4 v = (r < 19) ? tf32r4(*(const float4*)&We1[(256 + r) * H + c4]) : z4;
        *(float4*)&s_W1c[r * SBN + c4] = v;
    }
    for (int idx = tid; idx < 128 * 32; idx += 256) {       // We2: 128 x 128
        const int r = idx >> 5, c4 = (idx & 31) * 4;
        *(float4*)&s_W2[r * SBN + c4] = tf32r4(*(const float4*)&We2[r * H + c4]);
    }
    for (int idx = tid; idx < 128 * 16; idx += 256) {       // Wc1: 128 x 64
        const int r = idx >> 4, c4 = (idx & 15) * 4;
        *(float4*)&s_Wc1[r * SBN3 + c4] = tf32r4(*(const float4*)&Wc1[r * 64 + c4]);
    }

    const int lane = tid & 31, w = tid >> 5;
    const int g = lane >> 2, tg = lane & 3;
    const int m0 = (w & 1) * 32;
    const int nb = (w >> 1) * 32;
    const int nb3 = (w >> 1) * 16;

    // hoisted per-column constants
    float ln_g[4], ln_b[4];
    ln_g[0] = g1[lane]; ln_g[1] = g1[lane + 32]; ln_g[2] = g1[lane + 64]; ln_g[3] = g1[lane + 96];
    ln_b[0] = bt1[lane]; ln_b[1] = bt1[lane + 32]; ln_b[2] = bt1[lane + 64]; ln_b[3] = bt1[lane + 96];
    float be1v[4][2], be2v[4][2];
    #pragma unroll
    for (int t = 0; t < 4; t++) {
        const int col = nb + t * 8 + tg * 2;
        be1v[t][0] = be1[col]; be1v[t][1] = be1[col + 1];
        be2v[t][0] = be2[col]; be2v[t][1] = be2[col + 1];
    }
    float wc2v[2][2], bc1v[2][2];
    #pragma unroll
    for (int t = 0; t < 2; t++) {
        const int col = nb3 + t * 8 + tg * 2;
        wc2v[t][0] = Wc2[col]; wc2v[t][1] = Wc2[col + 1];
        bc1v[t][0] = bc1[col]; bc1v[t][1] = bc1[col + 1];
    }
    const float bc2v = bc2[0];

    __syncthreads();

    for (int tile = blockIdx.x; tile < NTILES; tile += GRID_EDGE) {
        const int e0 = tile * TE;

        // ---- phase 1: scalars + gather ----
        if (tid < TE) {
            const int e = e0 + tid;
            const int src = edge_index[e];
            const int dst = edge_index[NE + e];
            s_src[tid] = src;
            const float rx = pos[dst * 3 + 0] - pos[src * 3 + 0];
            const float ry = pos[dst * 3 + 1] - pos[src * 3 + 1];
            const float rz = pos[dst * 3 + 2] - pos[src * 3 + 2];
            const float dist = sqrtf(rx * rx + ry * ry + rz * rz + 1e-8f);
            const float inv = 1.f / dist;
            s_unit[tid][0] = rx * inv; s_unit[tid][1] = ry * inv; s_unit[tid][2] = rz * inv;

            const float4 ea = *(const float4*)&edge_attr[e * 4];
            float ca = cosf(ea.x);
            float p2 = 0.5f * (3.f * ca * ca - 1.f);
            float p3 = (5.f * ca * p2 - 2.f * ca) * (1.f / 3.f);
            float a_score = 0.25f * (1.f + fabsf(ca) + fabsf(p2) + fabsf(p3)) * ea.z;
            float cd = cosf(ea.y);
            float q2 = 0.5f * (3.f * cd * cd - 1.f);
            float q3 = (5.f * cd * q2 - 2.f * cd) * (1.f / 3.f);
            float d_score = 0.25f * (1.f + fabsf(cd) + fabsf(q2) + fabsf(q3)) * ea.w;
            float gate = fminf(fmaxf(1.f + 0.6f * (a_score + d_score), 0.35f), 2.5f);
            s_gate[tid] = gate;
            s_coord[tid] = bc2v;

            const float qs = charge[src], qd = charge[dst];
            float* row = &efs[tid * EFS];
            const float gi = gate * inv;
            #pragma unroll
            for (int i = 0; i < NRAD; i++) {
                float f = (float)(i + 1) * (PI_F / 5.0f);
                row[i] = tf32r(sinf(f * dist) * gi);
            }
            row[16] = tf32r(dist * 0.2f * gate);
            row[17] = tf32r(qs * qd * gate);
            row[18] = tf32r(fabsf(qs - qd) * gate);
            #pragma unroll
            for (int i = 19; i < EFS; i++) row[i] = 0.f;
        }
        for (int idx = tid; idx < TE * 32; idx += 256) {
            const int e = idx >> 5, j4 = idx & 31;
            const int src = edge_index[e0 + e];
            const int dst = edge_index[NE + e0 + e];
            float4 a = *(const float4*)&g_pq[src * 256 + j4 * 4];
            const float4 b = *(const float4*)&g_pq[dst * 256 + 128 + j4 * 4];
            a.x += b.x; a.y += b.y; a.z += b.z; a.w += b.w;
            *(float4*)&s_pre[e * HS + j4 * 4] = a;
        }
        __syncthreads();   // A

        // ---- GEMM1-small + epilogue1 -> s_h ----
        float d[2][4][4];
        #pragma unroll
        for (int mi = 0; mi < 2; mi++)
            #pragma unroll
            for (int t = 0; t < 4; t++)
                #pragma unroll
                for (int i = 0; i < 4; i++) d[mi][t][i] = 0.f;
        #pragma unroll
        for (int ks = 0; ks < 3; ks++) {
            const int kg = ks * 8;
            uint32_t a[2][4];
            #pragma unroll
            for (int mi = 0; mi < 2; mi++) {
                const int rA = m0 + mi * 16 + g;
                a[mi][0] = __float_as_uint(efs[rA * EFS + kg + tg]);
                a[mi][1] = __float_as_uint(efs[(rA + 8) * EFS + kg + tg]);
                a[mi][2] = __float_as_uint(efs[rA * EFS + kg + 4 + tg]);
                a[mi][3] = __float_as_uint(efs[(rA + 8) * EFS + kg + 4 + tg]);
            }
            #pragma unroll
            for (int t = 0; t < 4; t++) {
                const uint32_t b0 = __float_as_uint(s_W1c[(kg + tg) * SBN + nb + t * 8 + g]);
                const uint32_t b1 = __float_as_uint(s_W1c[(kg + 4 + tg) * SBN + nb + t * 8 + g]);
                mma_tf32(d[0][t], a[0][0], a[0][1], a[0][2], a[0][3], b0, b1);
                mma_tf32(d[1][t], a[1][0], a[1][1], a[1][2], a[1][3], b0, b1);
            }
        }
        #pragma unroll
        for (int t = 0; t < 4; t++) {
            const int col = nb + t * 8 + tg * 2;
            #pragma unroll
            for (int mi = 0; mi < 2; mi++) {
                const int rA = m0 + mi * 16 + g;
                s_h[rA * HS + col]           = silu_f(d[mi][t][0] + s_pre[rA * HS + col] + be1v[t][0]);
                s_h[rA * HS + col + 1]       = silu_f(d[mi][t][1] + s_pre[rA * HS + col + 1] + be1v[t][1]);
                s_h[(rA + 8) * HS + col]     = silu_f(d[mi][t][2] + s_pre[(rA + 8) * HS + col] + be1v[t][0]);
                s_h[(rA + 8) * HS + col + 1] = silu_f(d[mi][t][3] + s_pre[(rA + 8) * HS + col + 1] + be1v[t][1]);
            }
        }
        __syncthreads();   // B

        // ---- LayerNorm(h): warp per 8 edges; tf32 out ----
        #pragma unroll
        for (int qq = 0; qq < 8; qq++) {
            const int e = w * 8 + qq;
            float v0 = s_h[e * HS + lane], v1 = s_h[e * HS + lane + 32];
            float v2 = s_h[e * HS + lane + 64], v3 = s_h[e * HS + lane + 96];
            float s1 = v0 + v1 + v2 + v3;
            float s2 = v0 * v0 + v1 * v1 + v2 * v2 + v3 * v3;
            #pragma unroll
            for (int o = 16; o; o >>= 1) {
                s1 += __shfl_xor_sync(0xffffffffu, s1, o);
                s2 += __shfl_xor_sync(0xffffffffu, s2, o);
            }
            const float m = s1 * (1.f / 128.f);
            const float var = s2 * (1.f / 128.f) - m * m;
            const float rstd = rsqrtf(var + 1e-5f);
            s_h[e * HS + lane]      = tf32r((v0 - m) * rstd * ln_g[0] + ln_b[0]);
            s_h[e * HS + lane + 32] = tf32r((v1 - m) * rstd * ln_g[1] + ln_b[1]);
            s_h[e * HS + lane + 64] = tf32r((v2 - m) * rstd * ln_g[2] + ln_b[2]);
            s_h[e * HS + lane + 96] = tf32r((v3 - m) * rstd * ln_g[3] + ln_b[3]);
        }
        __syncthreads();   // C

        // ---- GEMM2: h @ We2 (weights resident) ----
        #pragma unroll
        for (int mi = 0; mi < 2; mi++)
            #pragma unroll
            for (int t = 0; t < 4; t++)
                #pragma unroll
                for (int i = 0; i < 4; i++) d[mi][t][i] = 0.f;
        #pragma unroll 4
        for (int ks = 0; ks < 16; ks++) {
            const int kg = ks * 8;
            uint32_t a[2][4];
            #pragma unroll
            for (int mi = 0; mi < 2; mi++) {
                const int rA = m0 + mi * 16 + g;
                a[mi][0] = __float_as_uint(s_h[rA * HS + kg + tg]);
                a[mi][1] = __float_as_uint(s_h[(rA + 8) * HS + kg + tg]);
                a[mi][2] = __float_as_uint(s_h[rA * HS + kg + 4 + tg]);
                a[mi][3] = __float_as_uint(s_h[(rA + 8) * HS + kg + 4 + tg]);
            }
            #pragma unroll
            for (int t = 0; t < 4; t++) {
                const uint32_t b0 = __float_as_uint(s_W2[(kg + tg) * SBN + nb + t * 8 + g]);
                const uint32_t b1 = __float_as_uint(s_W2[(kg + 4 + tg) * SBN + nb + t * 8 + g]);
                mma_tf32(d[0][t], a[0][0], a[0][1], a[0][2], a[0][3], b0, b1);
                mma_tf32(d[1][t], a[1][0], a[1][1], a[1][2], a[1][3], b0, b1);
            }
        }
        __syncthreads();   // D (s_h reads done; s_pre dead -> eh overlay safe)

        // ---- epilogue2: eh = silu(+be2) -> s_eh ----
        #pragma unroll
        for (int t = 0; t < 4; t++) {
            const int col = nb + t * 8 + tg * 2;
            #pragma unroll
            for (int mi = 0; mi < 2; mi++) {
                const int rA = m0 + mi * 16 + g;
                s_eh[rA * HS + col]           = tf32r(silu_f(d[mi][t][0] + be2v[t][0]));
                s_eh[rA * HS + col + 1]       = tf32r(silu_f(d[mi][t][1] + be2v[t][1]));
                s_eh[(rA + 8) * HS + col]     = tf32r(silu_f(d[mi][t][2] + be2v[t][0]));
                s_eh[(rA + 8) * HS + col + 1] = tf32r(silu_f(d[mi][t][3] + be2v[t][1]));
            }
        }
        __syncthreads();   // E

        // ---- GEMM3: eh @ Wc1 + coord epilogue ----
        float d3[2][2][4];
        #pragma unroll
        for (int mi = 0; mi < 2; mi++)
            #pragma unroll
            for (int t = 0; t < 2; t++)
                #pragma unroll
                for (int i = 0; i < 4; i++) d3[mi][t][i] = 0.f;
        #pragma unroll 4
        for (int ks = 0; ks < 16; ks++) {
            const int kg = ks * 8;
            uint32_t a[2][4];
            #pragma unroll
            for (int mi = 0; mi < 2; mi++) {
                const int rA = m0 + mi * 16 + g;
                a[mi][0] = __float_as_uint(s_eh[rA * HS + kg + tg]);
                a[mi][1] = __float_as_uint(s_eh[(rA + 8) * HS + kg + tg]);
                a[mi][2] = __float_as_uint(s_eh[rA * HS + kg + 4 + tg]);
                a[mi][3] = __float_as_uint(s_eh[(rA + 8) * HS + kg + 4 + tg]);
            }
            #pragma unroll
            for (int t = 0; t < 2; t++) {
                const uint32_t b0 = __float_as_uint(s_Wc1[(kg + tg) * SBN3 + nb3 + t * 8 + g]);
                const uint32_t b1 = __float_as_uint(s_Wc1[(kg + 4 + tg) * SBN3 + nb3 + t * 8 + g]);
                mma_tf32(d3[0][t], a[0][0], a[0][1], a[0][2], a[0][3], b0, b1);
                mma_tf32(d3[1][t], a[1][0], a[1][1], a[1][2], a[1][3], b0, b1);
            }
        }
        #pragma unroll
        for (int mi = 0; mi < 2; mi++) {
            float sA = 0.f, sB2 = 0.f;
            #pragma unroll
            for (int t = 0; t < 2; t++) {
                sA  += silu_f(d3[mi][t][0] + bc1v[t][0]) * wc2v[t][0]
                     + silu_f(d3[mi][t][1] + bc1v[t][1]) * wc2v[t][1];
                sB2 += silu_f(d3[mi][t][2] + bc1v[t][0]) * wc2v[t][0]
                     + silu_f(d3[mi][t][3] + bc1v[t][1]) * wc2v[t][1];
            }
            const int rA = m0 + mi * 16 + g;
            atomicAdd(&s_coord[rA], sA);
            atomicAdd(&s_coord[rA + 8], sB2);
        }
        __syncthreads();   // F

        // ---- scatter ----
        for (int idx = tid; idx < TE * H; idx += 256) {
            const int e = idx >> 7, jc = idx & (H - 1);
            atomicAdd(&g_agg[s_src[e] * H + jc], s_eh[e * HS + jc]);
        }
        if (tid < TE) {
            const int src = s_src[tid];
            const float f = s_coord[tid] * s_gate[tid];
            atomicAdd(&g_cnt[src], 1.0f);
            atomicAdd(&g_delta[src * 3 + 0], s_unit[tid][0] * f);
            atomicAdd(&g_delta[src * 3 + 1], s_unit[tid][1] * f);
            atomicAdd(&g_delta[src * 3 + 2], s_unit[tid][2] * f);
        }
        __syncthreads();   // G (protect smem for next tile)
    }
}

__global__ __launch_bounds__(256) void node_kernel(
    const float* __restrict__ x, const float* __restrict__ pos,
    const float* __restrict__ Wn, const float* __restrict__ bn,
    const float* __restrict__ gn, const float* __restrict__ btn,
    float* __restrict__ out)
{
    __shared__ __align__(16) float s_cat[TN * 260];
    const int tid = threadIdx.x;
    const int n0 = blockIdx.x * TN;

    for (int idx = tid; idx < TN * 64; idx += 256) {
        const int nl = idx >> 6, j4 = idx & 63;
        const int n = n0 + nl;
        float4 v = make_float4(0.f, 0.f, 0.f, 0.f);
        if (n < NN) {
            if (j4 < 32) {
                v = *(const float4*)&x[n * H + j4 * 4];
            } else {
                const float c = fmaxf(g_cnt[n], 1.f);
                const float iv = 1.f / c;
                v = *(const float4*)&g_agg[n * H + (j4 - 32) * 4];
                v.x *= iv; v.y *= iv; v.z *= iv; v.w *= iv;
            }
        }
        *(float4*)&s_cat[nl * 260 + j4 * 4] = v;
    }
    __syncthreads();

    const int jj = tid & 63, g = tid >> 6;
    const int nbv = g * 8;
    u64t accA[8], accB[8];
    #pragma unroll
    for (int e = 0; e < 8; e++) { accA[e] = 0ull; accB[e] = 0ull; }
    for (int k = 0; k < 256; k += 4) {
        const float wA0 = Wn[(k + 0) * H + jj],      wA1 = Wn[(k + 1) * H + jj];
        const float wA2 = Wn[(k + 2) * H + jj],      wA3 = Wn[(k + 3) * H + jj];
        const float wB0 = Wn[(k + 0) * H + jj + 64], wB1 = Wn[(k + 1) * H + jj + 64];
        const float wB2 = Wn[(k + 2) * H + jj + 64], wB3 = Wn[(k + 3) * H + jj + 64];
        const u64t pA0 = pack2(wA0, wA1), pA1 = pack2(wA2, wA3);
        const u64t pB0 = pack2(wB0, wB1), pB1 = pack2(wB2, wB3);
        #pragma unroll
        for (int e = 0; e < 8; e++) {
            const ulonglong2 v = *(const ulonglong2*)&s_cat[(nbv + e) * 260 + k];
            fma2(accA[e], v.x, pA0); fma2(accA[e], v.y, pA1);
            fma2(accB[e], v.x, pB0); fma2(accB[e], v.y, pB1);
        }
    }
    const float bA = bn[jj], bB = bn[jj + 64];
    __syncthreads();
    float* const s_y = s_cat;
    #pragma unroll
    for (int e = 0; e < 8; e++) {
        s_y[(nbv + e) * H + jj]      = silu_f(hadd2(accA[e]) + bA);
        s_y[(nbv + e) * H + jj + 64] = silu_f(hadd2(accB[e]) + bB);
    }
    __syncthreads();

    const int lane = tid & 31, wrp = tid >> 5;
    const float ga = gn[lane], gb = gn[lane + 32], gc = gn[lane + 64], gd = gn[lane + 96];
    const float ba = btn[lane], bb = btn[lane + 32], bcv = btn[lane + 64], bd = btn[lane + 96];
    #pragma unroll
    for (int qq = 0; qq < 4; qq++) {
        const int nl = wrp * 4 + qq;
        const int n = n0 + nl;
        float v0 = s_y[nl * H + lane], v1 = s_y[nl * H + lane + 32];
        float v2 = s_y[nl * H + lane + 64], v3 = s_y[nl * H + lane + 96];
        float s1 = v0 + v1 + v2 + v3;
        float s2 = v0 * v0 + v1 * v1 + v2 * v2 + v3 * v3;
        #pragma unroll
        for (int o = 16; o; o >>= 1) {
            s1 += __shfl_xor_sync(0xffffffffu, s1, o);
            s2 += __shfl_xor_sync(0xffffffffu, s2, o);
        }
        const float m = s1 * (1.f / 128.f);
        const float var = s2 * (1.f / 128.f) - m * m;
        const float rstd = rsqrtf(var + 1e-5f);
        if (n < NN) {
            out[n * H + lane]      = x[n * H + lane]      + (v0 - m) * rstd * ga + ba;
            out[n * H + lane + 32] = x[n * H + lane + 32] + (v1 - m) * rstd * gb + bb;
            out[n * H + lane + 64] = x[n * H + lane + 64] + (v2 - m) * rstd * gc + bcv;
            out[n * H + lane + 96] = x[n * H + lane + 96] + (v3 - m) * rstd * gd + bd;
        }
    }
    if (tid < TN) {
        const int n = n0 + tid;
        if (n < NN) {
            const float c = fmaxf(g_cnt[n], 1.f);
            const float s = 0.1f / c;
            out[NN * H + n * 3 + 0] = pos[n * 3 + 0] + s * g_delta[n * 3 + 0];
            out[NN * H + n * 3 + 1] = pos[n * 3 + 1] + s * g_delta[n * 3 + 1];
            out[NN * H + n * 3 + 2] = pos[n * 3 + 2] + s * g_delta[n * 3 + 2];
        }
    }

    // ---- re-zero scratch for next launch ----
    __syncthreads();
    const float4 z4 = make_float4(0.f, 0.f, 0.f, 0.f);
    for (int idx = tid; idx < TN * 32; idx += 256) {
        const int nl = idx >> 5, j4 = idx & 31;
        const int n = n0 + nl;
        if (n < NN) *(float4*)&g_agg[n * H + j4 * 4] = z4;
    }
    if (tid < TN) {
        const int n = n0 + tid;
        if (n < NN) {
            g_cnt[n] = 0.f;
            g_delta[n * 3 + 0] = 0.f;
            g_delta[n * 3 + 1] = 0.f;
            g_delta[n * 3 + 2] = 0.f;
        }
    }
}

extern "C" void kernel_launch(void* const* d_in, const int* in_sizes, int n_in,
                              void* d_out, int out_size) {
    const float* x         = (const float*)d_in[0];
    const float* pos       = (const float*)d_in[1];
    const float* charge    = (const float*)d_in[2];
    const float* edge_attr = (const float*)d_in[3];
    const int*   edge_index= (const int*)d_in[4];
    const float* We1 = (const float*)d_in[5];
    const float* be1 = (const float*)d_in[6];
    const float* g1  = (const float*)d_in[7];
    const float* bt1 = (const float*)d_in[8];
    const float* We2 = (const float*)d_in[9];
    const float* be2 = (const float*)d_in[10];
    const float* Wn  = (const float*)d_in[11];
    const float* bn  = (const float*)d_in[12];
    const float* gn  = (const float*)d_in[13];
    const float* btn = (const float*)d_in[14];
    const float* Wc1 = (const float*)d_in[15];
    const float* bc1 = (const float*)d_in[16];
    const float* Wc2 = (const float*)d_in[17];
    const float* bc2 = (const float*)d_in[18];
    float* out = (float*)d_out;

    cudaFuncSetAttribute(pre_kernel, cudaFuncAttributeMaxDynamicSharedMemorySize, SMEM_PRE);
    cudaFuncSetAttribute(edge_kernel, cudaFuncAttributeMaxDynamicSharedMemorySize, SMEM_EDGE);

    pre_kernel<<<(NN + 63) / 64, 256, SMEM_PRE>>>(x, We1);
    edge_kernel<<<GRID_EDGE, 256, SMEM_EDGE>>>(pos, charge, edge_attr, edge_index,
                                               We1, be1, g1, bt1, We2, be2, Wc1, bc1, Wc2, bc2);
    node_kernel<<<(NN + TN - 1) / TN, 256>>>(x, pos, Wn, bn, gn, btn, out);
}

// round 13
// speedup vs baseline: 1.7886x; 1.0549x over previous
#include <cuda_runtime.h>
#include <math.h>
#include <stdint.h>

#define NN 50000
#define NE 800000
#define H 128
#define NRAD 16
#define TE 64              // edges per tile
#define TN 32
#define NTILES (NE / TE)   // 12500
#define GRID_EDGE 148
#define HS  132            // P/Q/h/eh row stride: mod32=4
#define SBN 136            // weight row stride (N=128): mod32=8
#define SBN3 72            // weight row stride (N=64): mod32=8
#define EFS 24
#define PI_F 3.14159265358979f

// ---- persistent edge kernel dynamic smem layout (bytes) ----
#define SZ_T    (TE * HS * 4)               // 33792
#define OFF_P   0
#define OFF_Q   (OFF_P + SZ_T)              // 33792
#define OFF_H2  (OFF_Q + SZ_T)              // 67584 (h; eh overlays)
#define OFF_W1C (OFF_H2 + SZ_T)             // 101376
#define SZ_W1C  (24 * SBN * 4)              // 13056
#define OFF_W2  (OFF_W1C + SZ_W1C)          // 114432
#define SZ_W2   (128 * SBN * 4)             // 69632
#define OFF_WC1 (OFF_W2 + SZ_W2)            // 184064
#define SZ_WC1  (128 * SBN3 * 4)            // 36864
#define OFF_EFS (OFF_WC1 + SZ_WC1)          // 220928
#define SZ_EFS  (TE * EFS * 4)              // 6144
#define SMEM_EDGE (OFF_EFS + SZ_EFS)        // 227072

// ---- pre kernel smem ----
#define XS 132
#define SBNP 264
#define OFF_X   0
#define SZ_X    (64 * XS * 4)
#define OFF_PB0 (OFF_X + SZ_X)
#define SZ_PB   (32 * SBNP * 4)
#define OFF_PB1 (OFF_PB0 + SZ_PB)
#define SMEM_PRE (OFF_PB1 + SZ_PB)

typedef unsigned long long u64t;

__device__ float g_pq[NN * 256];
__device__ float g_agg[NN * H];
__device__ float g_cnt[NN];
__device__ float g_delta[NN * 3];

__device__ __forceinline__ float silu_f(float v) { return v / (1.f + __expf(-v)); }

__device__ __forceinline__ float tf32r(float f) {
    uint32_t u; asm("cvt.rna.tf32.f32 %0, %1;" : "=r"(u) : "f"(f));
    return __uint_as_float(u);
}
__device__ __forceinline__ float4 tf32r4(float4 v) {
    v.x = tf32r(v.x); v.y = tf32r(v.y); v.z = tf32r(v.z); v.w = tf32r(v.w);
    return v;
}
__device__ __forceinline__ void mma_tf32(float* d, uint32_t a0, uint32_t a1, uint32_t a2,
                                         uint32_t a3, uint32_t b0, uint32_t b1) {
    asm("mma.sync.aligned.m16n8k8.row.col.f32.tf32.tf32.f32 "
        "{%0,%1,%2,%3},{%4,%5,%6,%7},{%8,%9},{%0,%1,%2,%3};"
        : "+f"(d[0]), "+f"(d[1]), "+f"(d[2]), "+f"(d[3])
        : "r"(a0), "r"(a1), "r"(a2), "r"(a3), "r"(b0), "r"(b1));
}

__device__ __forceinline__ void fma2(u64t& d, u64t a, u64t b) {
    asm("fma.rn.f32x2 %0, %1, %2, %0;" : "+l"(d) : "l"(a), "l"(b));
}
__device__ __forceinline__ u64t pack2(float lo, float hi) {
    u64t d; asm("mov.b64 %0, {%1, %2};" : "=l"(d) : "f"(lo), "f"(hi)); return d;
}
__device__ __forceinline__ float hadd2(u64t d) {
    float lo, hi; asm("mov.b64 {%0, %1}, %2;" : "=f"(lo), "=f"(hi) : "l"(d));
    return lo + hi;
}

__device__ __forceinline__ void cpasync16(uint32_t smem_dst, const void* gsrc) {
    asm volatile("cp.async.cg.shared.global [%0], [%1], 16;" :: "r"(smem_dst), "l"(gsrc));
}
#define CPASYNC_COMMIT() asm volatile("cp.async.commit_group;" ::: "memory")
#define CPASYNC_WAIT0()  asm volatile("cp.async.wait_group 0;" ::: "memory")

// shared scalar-feature math: dist/unit/gate + small features (tf32)
__device__ __forceinline__ void edge_scalar_body(
    float rx, float ry, float rz, float qs, float qd, float4 ea,
    float* efs_row, float* gate_out, float* unit_out)
{
    const float dist = sqrtf(rx * rx + ry * ry + rz * rz + 1e-8f);
    const float inv = 1.f / dist;
    unit_out[0] = rx * inv; unit_out[1] = ry * inv; unit_out[2] = rz * inv;

    float ca = cosf(ea.x);
    float p2 = 0.5f * (3.f * ca * ca - 1.f);
    float p3 = (5.f * ca * p2 - 2.f * ca) * (1.f / 3.f);
    float a_score = 0.25f * (1.f + fabsf(ca) + fabsf(p2) + fabsf(p3)) * ea.z;
    float cd = cosf(ea.y);
    float q2 = 0.5f * (3.f * cd * cd - 1.f);
    float q3 = (5.f * cd * q2 - 2.f * cd) * (1.f / 3.f);
    float d_score = 0.25f * (1.f + fabsf(cd) + fabsf(q2) + fabsf(q3)) * ea.w;
    float gate = fminf(fmaxf(1.f + 0.6f * (a_score + d_score), 0.35f), 2.5f);
    *gate_out = gate;

    const float gi = gate * inv;
    #pragma unroll
    for (int i = 0; i < NRAD; i++) {
        float f = (float)(i + 1) * (PI_F / 5.0f);
        efs_row[i] = tf32r(sinf(f * dist) * gi);
    }
    efs_row[16] = tf32r(dist * 0.2f * gate);
    efs_row[17] = tf32r(qs * qd * gate);
    efs_row[18] = tf32r(fabsf(qs - qd) * gate);
    #pragma unroll
    for (int i = 19; i < EFS; i++) efs_row[i] = 0.f;
}

// ================== PQ = x @ [We1a | We1b] ==================
__global__ __launch_bounds__(256) void pre_kernel(
    const float* __restrict__ x, const float* __restrict__ We1)
{
    extern __shared__ __align__(16) char dsm[];
    float* const s_x  = (float*)(dsm + OFF_X);
    float* const s_P0 = (float*)(dsm + OFF_PB0);
    float* const s_P1 = (float*)(dsm + OFF_PB1);

    const int tid = threadIdx.x;
    const int n0 = blockIdx.x * 64;
    const float4 z4 = make_float4(0.f, 0.f, 0.f, 0.f);

    for (int idx = tid; idx < 64 * 32; idx += 256) {
        const int e = idx >> 5, j4 = idx & 31;
        const int n = n0 + e;
        float4 v = (n < NN) ? tf32r4(*(const float4*)&x[n * H + j4 * 4]) : z4;
        *(float4*)&s_x[e * XS + j4 * 4] = v;
    }

    const int lane = tid & 31, w = tid >> 5;
    const int g = lane >> 2, tg = lane & 3;
    const int m0 = (w & 1) * 32;
    const int nb = (w >> 1) * 64;
    const int kk = tid >> 3, q = tid & 7;

    float d[2][8][4];
    #pragma unroll
    for (int mi = 0; mi < 2; mi++)
        #pragma unroll
        for (int t = 0; t < 8; t++)
            #pragma unroll
            for (int i = 0; i < 4; i++) d[mi][t][i] = 0.f;

    float4 ra0, ra1, ra2, ra3, rb0, rb1, rb2, rb3;
    {
        const float* sa = &We1[kk * H + q * 16];
        const float* sb = &We1[(128 + kk) * H + q * 16];
        ra0 = tf32r4(*(const float4*)(sa + 0));  ra1 = tf32r4(*(const float4*)(sa + 4));
        ra2 = tf32r4(*(const float4*)(sa + 8));  ra3 = tf32r4(*(const float4*)(sa + 12));
        rb0 = tf32r4(*(const float4*)(sb + 0));  rb1 = tf32r4(*(const float4*)(sb + 4));
        rb2 = tf32r4(*(const float4*)(sb + 8));  rb3 = tf32r4(*(const float4*)(sb + 12));
        float* dw = &s_P0[kk * SBNP];
        *(float4*)(dw + q * 16 + 0) = ra0; *(float4*)(dw + q * 16 + 4) = ra1;
        *(float4*)(dw + q * 16 + 8) = ra2; *(float4*)(dw + q * 16 + 12) = ra3;
        *(float4*)(dw + 128 + q * 16 + 0) = rb0; *(float4*)(dw + 128 + q * 16 + 4) = rb1;
        *(float4*)(dw + 128 + q * 16 + 8) = rb2; *(float4*)(dw + 128 + q * 16 + 12) = rb3;
    }
    for (int c = 0; c < 4; c++) {
        if (c < 3) {
            const int k = (c + 1) * 32 + kk;
            const float* sa = &We1[k * H + q * 16];
            const float* sb = &We1[(128 + k) * H + q * 16];
            ra0 = tf32r4(*(const float4*)(sa + 0));  ra1 = tf32r4(*(const float4*)(sa + 4));
            ra2 = tf32r4(*(const float4*)(sa + 8));  ra3 = tf32r4(*(const float4*)(sa + 12));
            rb0 = tf32r4(*(const float4*)(sb + 0));  rb1 = tf32r4(*(const float4*)(sb + 4));
            rb2 = tf32r4(*(const float4*)(sb + 8));  rb3 = tf32r4(*(const float4*)(sb + 12));
        }
        __syncthreads();
        const float* bp = (c & 1) ? s_P1 : s_P0;
        #pragma unroll
        for (int ks = 0; ks < 4; ks++) {
            const int kg = c * 32 + ks * 8, kl = ks * 8;
            uint32_t a[2][4];
            #pragma unroll
            for (int mi = 0; mi < 2; mi++) {
                const int rA = m0 + mi * 16 + g;
                a[mi][0] = __float_as_uint(s_x[rA * XS + kg + tg]);
                a[mi][1] = __float_as_uint(s_x[(rA + 8) * XS + kg + tg]);
                a[mi][2] = __float_as_uint(s_x[rA * XS + kg + 4 + tg]);
                a[mi][3] = __float_as_uint(s_x[(rA + 8) * XS + kg + 4 + tg]);
            }
            #pragma unroll
            for (int t = 0; t < 8; t++) {
                const uint32_t b0 = __float_as_uint(bp[(kl + tg) * SBNP + nb + t * 8 + g]);
                const uint32_t b1 = __float_as_uint(bp[(kl + 4 + tg) * SBNP + nb + t * 8 + g]);
                mma_tf32(d[0][t], a[0][0], a[0][1], a[0][2], a[0][3], b0, b1);
                mma_tf32(d[1][t], a[1][0], a[1][1], a[1][2], a[1][3], b0, b1);
            }
        }
        if (c < 3) {
            float* np = (c & 1) ? s_P0 : s_P1;
            float* dw = &np[kk * SBNP];
            *(float4*)(dw + q * 16 + 0) = ra0; *(float4*)(dw + q * 16 + 4) = ra1;
            *(float4*)(dw + q * 16 + 8) = ra2; *(float4*)(dw + q * 16 + 12) = ra3;
            *(float4*)(dw + 128 + q * 16 + 0) = rb0; *(float4*)(dw + 128 + q * 16 + 4) = rb1;
            *(float4*)(dw + 128 + q * 16 + 8) = rb2; *(float4*)(dw + 128 + q * 16 + 12) = rb3;
        }
    }

    #pragma unroll
    for (int mi = 0; mi < 2; mi++) {
        const int r0w = n0 + m0 + mi * 16 + g;
        #pragma unroll
        for (int t = 0; t < 8; t++) {
            const int col = nb + t * 8 + tg * 2;
            if (r0w < NN)
                *(float2*)&g_pq[r0w * 256 + col] = make_float2(d[mi][t][0], d[mi][t][1]);
            if (r0w + 8 < NN)
                *(float2*)&g_pq[(r0w + 8) * 256 + col] = make_float2(d[mi][t][2], d[mi][t][3]);
        }
    }
}

// ================== persistent, software-pipelined edge kernel ==================
__global__ __launch_bounds__(256) void edge_kernel(
    const float* __restrict__ pos,
    const float* __restrict__ charge, const float* __restrict__ edge_attr,
    const int* __restrict__ edge_index,
    const float* __restrict__ We1, const float* __restrict__ be1,
    const float* __restrict__ g1, const float* __restrict__ bt1,
    const float* __restrict__ We2, const float* __restrict__ be2,
    const float* __restrict__ Wc1, const float* __restrict__ bc1,
    const float* __restrict__ Wc2, const float* __restrict__ bc2)
{
    extern __shared__ __align__(16) char dsm[];
    float* const s_P   = (float*)(dsm + OFF_P);     // [64][132]
    float* const s_Q   = (float*)(dsm + OFF_Q);     // [64][132]
    float* const s_h   = (float*)(dsm + OFF_H2);    // [64][132]; eh overlays
    float* const s_eh  = (float*)(dsm + OFF_H2);
    float* const s_W1c = (float*)(dsm + OFF_W1C);   // [24][136]
    float* const s_W2  = (float*)(dsm + OFF_W2);    // [128][136]
    float* const s_Wc1 = (float*)(dsm + OFF_WC1);   // [128][72]
    float* const efs   = (float*)(dsm + OFF_EFS);   // [64][24]

    __shared__ float s_gateb[2][TE];
    __shared__ float s_unitb[2][TE][3];
    __shared__ int   s_srcb[2][TE];
    __shared__ float s_coordb[2][TE];
    __shared__ int   s_idx2[128];                    // next-tile src(0..63)/dst(64..127)

    const int tid = threadIdx.x;
    const float4 z4 = make_float4(0.f, 0.f, 0.f, 0.f);
    const uint32_t sPb = (uint32_t)__cvta_generic_to_shared(s_P);
    const uint32_t sQb = (uint32_t)__cvta_generic_to_shared(s_Q);

    // ---- stage ALL weights once (tf32) ----
    for (int idx = tid; idx < 24 * 32; idx += 256) {        // We1c rows 256..274
        const int r = idx >> 5, c4 = (idx & 31) * 4;
        float4 v = (r < 19) ? tf32r4(*(const float4*)&We1[(256 + r) * H + c4]) : z4;
        *(float4*)&s_W1c[r * SBN + c4] = v;
    }
    for (int idx = tid; idx < 128 * 32; idx += 256) {       // We2
        const int r = idx >> 5, c4 = (idx & 31) * 4;
        *(float4*)&s_W2[r * SBN + c4] = tf32r4(*(const float4*)&We2[r * H + c4]);
    }
    for (int idx = tid; idx < 128 * 16; idx += 256) {       // Wc1
        const int r = idx >> 4, c4 = (idx & 15) * 4;
        *(float4*)&s_Wc1[r * SBN3 + c4] = tf32r4(*(const float4*)&Wc1[r * 64 + c4]);
    }

    const int lane = tid & 31, w = tid >> 5;
    const int g = lane >> 2, tg = lane & 3;
    const int m0 = (w & 1) * 32;
    const int nb = (w >> 1) * 32;
    const int nb3 = (w >> 1) * 16;

    // hoisted constants
    float ln_g[4], ln_b[4];
    ln_g[0] = g1[lane]; ln_g[1] = g1[lane + 32]; ln_g[2] = g1[lane + 64]; ln_g[3] = g1[lane + 96];
    ln_b[0] = bt1[lane]; ln_b[1] = bt1[lane + 32]; ln_b[2] = bt1[lane + 64]; ln_b[3] = bt1[lane + 96];
    float be1v[4][2], be2v[4][2];
    #pragma unroll
    for (int t = 0; t < 4; t++) {
        const int col = nb + t * 8 + tg * 2;
        be1v[t][0] = be1[col]; be1v[t][1] = be1[col + 1];
        be2v[t][0] = be2[col]; be2v[t][1] = be2[col + 1];
    }
    float wc2v[2][2], bc1v[2][2];
    #pragma unroll
    for (int t = 0; t < 2; t++) {
        const int col = nb3 + t * 8 + tg * 2;
        wc2v[t][0] = Wc2[col]; wc2v[t][1] = Wc2[col + 1];
        bc1v[t][0] = bc1[col]; bc1v[t][1] = bc1[col + 1];
    }
    const float bc2v = bc2[0];

    // ---- prologue: tile 0 scalars + gather (synchronous) ----
    {
        const int e0p = blockIdx.x * TE;
        if (tid < TE) {
            const int e = e0p + tid;
            const int src = edge_index[e];
            const int dst = edge_index[NE + e];
            s_srcb[0][tid] = src;
            const float rx = pos[dst * 3 + 0] - pos[src * 3 + 0];
            const float ry = pos[dst * 3 + 1] - pos[src * 3 + 1];
            const float rz = pos[dst * 3 + 2] - pos[src * 3 + 2];
            edge_scalar_body(rx, ry, rz, charge[src], charge[dst],
                             *(const float4*)&edge_attr[e * 4],
                             &efs[tid * EFS], &s_gateb[0][tid], &s_unitb[0][tid][0]);
            s_coordb[0][tid] = bc2v;
        }
        for (int idx = tid; idx < TE * 32; idx += 256) {
            const int e = idx >> 5, j4 = idx & 31;
            const int src = edge_index[e0p + e];
            const int dst = edge_index[NE + e0p + e];
            *(float4*)&s_P[e * HS + j4 * 4] = *(const float4*)&g_pq[src * 256 + j4 * 4];
            *(float4*)&s_Q[e * HS + j4 * 4] = *(const float4*)&g_pq[dst * 256 + 128 + j4 * 4];
        }
    }

    int p = 0;
    for (int tile = blockIdx.x; tile < NTILES; tile += GRID_EDGE, p ^= 1) {
        const int np = p ^ 1;
        const int nt = tile + GRID_EDGE;
        const bool has_next = (nt < NTILES);

        // prefetch next-tile indices (LDG issued here, consumed post-C/post-D)
        int ni = 0, ndsti = 0;
        if (has_next) {
            if (tid < 128) {
                const int off = (tid < 64) ? (nt * TE + tid) : (NE + nt * TE + (tid - 64));
                ni = edge_index[off];
            }
            if (tid < 64) ndsti = edge_index[NE + nt * TE + tid];
        }

        CPASYNC_WAIT0();     // this tile's gather (issued last iteration) complete
        __syncthreads();     // A

        // ---- GEMM1-small + epilogue1 -> s_h ----
        float d[2][4][4];
        #pragma unroll
        for (int mi = 0; mi < 2; mi++)
            #pragma unroll
            for (int t = 0; t < 4; t++)
                #pragma unroll
                for (int i = 0; i < 4; i++) d[mi][t][i] = 0.f;
        #pragma unroll
        for (int ks = 0; ks < 3; ks++) {
            const int kg = ks * 8;
            uint32_t a[2][4];
            #pragma unroll
            for (int mi = 0; mi < 2; mi++) {
                const int rA = m0 + mi * 16 + g;
                a[mi][0] = __float_as_uint(efs[rA * EFS + kg + tg]);
                a[mi][1] = __float_as_uint(efs[(rA + 8) * EFS + kg + tg]);
                a[mi][2] = __float_as_uint(efs[rA * EFS + kg + 4 + tg]);
                a[mi][3] = __float_as_uint(efs[(rA + 8) * EFS + kg + 4 + tg]);
            }
            #pragma unroll
            for (int t = 0; t < 4; t++) {
                const uint32_t b0 = __float_as_uint(s_W1c[(kg + tg) * SBN + nb + t * 8 + g]);
                const uint32_t b1 = __float_as_uint(s_W1c[(kg + 4 + tg) * SBN + nb + t * 8 + g]);
                mma_tf32(d[0][t], a[0][0], a[0][1], a[0][2], a[0][3], b0, b1);
                mma_tf32(d[1][t], a[1][0], a[1][1], a[1][2], a[1][3], b0, b1);
            }
        }
        #pragma unroll
        for (int t = 0; t < 4; t++) {
            const int col = nb + t * 8 + tg * 2;
            #pragma unroll
            for (int mi = 0; mi < 2; mi++) {
                const int rA = m0 + mi * 16 + g;
                s_h[rA * HS + col] =
                    silu_f(d[mi][t][0] + s_P[rA * HS + col] + s_Q[rA * HS + col] + be1v[t][0]);
                s_h[rA * HS + col + 1] =
                    silu_f(d[mi][t][1] + s_P[rA * HS + col + 1] + s_Q[rA * HS + col + 1] + be1v[t][1]);
                s_h[(rA + 8) * HS + col] =
                    silu_f(d[mi][t][2] + s_P[(rA + 8) * HS + col] + s_Q[(rA + 8) * HS + col] + be1v[t][0]);
                s_h[(rA + 8) * HS + col + 1] =
                    silu_f(d[mi][t][3] + s_P[(rA + 8) * HS + col + 1] + s_Q[(rA + 8) * HS + col + 1] + be1v[t][1]);
            }
        }
        __syncthreads();     // B

        // issue next-tile scalar-input loads (latency hidden under LN+GEMM2)
        float psx = 0.f, psy = 0.f, psz = 0.f, pdx = 0.f, pdy = 0.f, pdz = 0.f;
        float qsv = 0.f, qdv = 0.f;
        float4 nea = z4;
        if (has_next && tid < 64) {
            psx = pos[ni * 3 + 0]; psy = pos[ni * 3 + 1]; psz = pos[ni * 3 + 2];
            pdx = pos[ndsti * 3 + 0]; pdy = pos[ndsti * 3 + 1]; pdz = pos[ndsti * 3 + 2];
            qsv = charge[ni]; qdv = charge[ndsti];
            nea = *(const float4*)&edge_attr[(nt * TE + tid) * 4];
        }

        // ---- LayerNorm(h): warp per 8 edges; tf32 out ----
        #pragma unroll
        for (int qq = 0; qq < 8; qq++) {
            const int e = w * 8 + qq;
            float v0 = s_h[e * HS + lane], v1 = s_h[e * HS + lane + 32];
            float v2 = s_h[e * HS + lane + 64], v3 = s_h[e * HS + lane + 96];
            float s1 = v0 + v1 + v2 + v3;
            float s2 = v0 * v0 + v1 * v1 + v2 * v2 + v3 * v3;
            #pragma unroll
            for (int o = 16; o; o >>= 1) {
                s1 += __shfl_xor_sync(0xffffffffu, s1, o);
                s2 += __shfl_xor_sync(0xffffffffu, s2, o);
            }
            const float m = s1 * (1.f / 128.f);
            const float var = s2 * (1.f / 128.f) - m * m;
            const float rstd = rsqrtf(var + 1e-5f);
            s_h[e * HS + lane]      = tf32r((v0 - m) * rstd * ln_g[0] + ln_b[0]);
            s_h[e * HS + lane + 32] = tf32r((v1 - m) * rstd * ln_g[1] + ln_b[1]);
            s_h[e * HS + lane + 64] = tf32r((v2 - m) * rstd * ln_g[2] + ln_b[2]);
            s_h[e * HS + lane + 96] = tf32r((v3 - m) * rstd * ln_g[3] + ln_b[3]);
        }
        __syncthreads();     // C

        if (has_next && tid < 128) s_idx2[tid] = ni;

        // ---- GEMM2: h @ We2 ----
        #pragma unroll
        for (int mi = 0; mi < 2; mi++)
            #pragma unroll
            for (int t = 0; t < 4; t++)
                #pragma unroll
                for (int i = 0; i < 4; i++) d[mi][t][i] = 0.f;
        #pragma unroll 4
        for (int ks = 0; ks < 16; ks++) {
            const int kg = ks * 8;
            uint32_t a[2][4];
            #pragma unroll
            for (int mi = 0; mi < 2; mi++) {
                const int rA = m0 + mi * 16 + g;
                a[mi][0] = __float_as_uint(s_h[rA * HS + kg + tg]);
                a[mi][1] = __float_as_uint(s_h[(rA + 8) * HS + kg + tg]);
                a[mi][2] = __float_as_uint(s_h[rA * HS + kg + 4 + tg]);
                a[mi][3] = __float_as_uint(s_h[(rA + 8) * HS + kg + 4 + tg]);
            }
            #pragma unroll
            for (int t = 0; t < 4; t++) {
                const uint32_t b0 = __float_as_uint(s_W2[(kg + tg) * SBN + nb + t * 8 + g]);
                const uint32_t b1 = __float_as_uint(s_W2[(kg + 4 + tg) * SBN + nb + t * 8 + g]);
                mma_tf32(d[0][t], a[0][0], a[0][1], a[0][2], a[0][3], b0, b1);
                mma_tf32(d[1][t], a[1][0], a[1][1], a[1][2], a[1][3], b0, b1);
            }
        }
        __syncthreads();     // D (s_h reads done -> eh overlay OK; s_idx2 visible)

        // ---- epilogue2: eh = silu(+be2) -> s_eh (overlays s_h) ----
        #pragma unroll
        for (int t = 0; t < 4; t++) {
            const int col = nb + t * 8 + tg * 2;
            #pragma unroll
            for (int mi = 0; mi < 2; mi++) {
                const int rA = m0 + mi * 16 + g;
                s_eh[rA * HS + col]           = tf32r(silu_f(d[mi][t][0] + be2v[t][0]));
                s_eh[rA * HS + col + 1]       = tf32r(silu_f(d[mi][t][1] + be2v[t][1]));
                s_eh[(rA + 8) * HS + col]     = tf32r(silu_f(d[mi][t][2] + be2v[t][0]));
                s_eh[(rA + 8) * HS + col + 1] = tf32r(silu_f(d[mi][t][3] + be2v[t][1]));
            }
        }

        // ---- pipelined prefetch for next tile (hidden under GEMM3+scatter) ----
        if (has_next) {
            #pragma unroll
            for (int k = 0; k < 8; k++) {
                const int idx = tid + k * 256;
                const int e = idx >> 5, j4 = idx & 31;
                const int se = s_idx2[e];
                const int de = s_idx2[64 + e];
                cpasync16(sPb + e * (HS * 4) + j4 * 16,
                          (const char*)g_pq + (size_t)se * 1024 + (size_t)j4 * 16);
                cpasync16(sQb + e * (HS * 4) + j4 * 16,
                          (const char*)g_pq + (size_t)de * 1024 + 512 + (size_t)j4 * 16);
            }
            CPASYNC_COMMIT();
            if (tid < 64) {
                edge_scalar_body(pdx - psx, pdy - psy, pdz - psz, qsv, qdv, nea,
                                 &efs[tid * EFS], &s_gateb[np][tid], &s_unitb[np][tid][0]);
                s_srcb[np][tid] = ni;
                s_coordb[np][tid] = bc2v;
            }
        }
        __syncthreads();     // E

        // ---- GEMM3: eh @ Wc1 + coord epilogue ----
        float d3[2][2][4];
        #pragma unroll
        for (int mi = 0; mi < 2; mi++)
            #pragma unroll
            for (int t = 0; t < 2; t++)
                #pragma unroll
                for (int i = 0; i < 4; i++) d3[mi][t][i] = 0.f;
        #pragma unroll 4
        for (int ks = 0; ks < 16; ks++) {
            const int kg = ks * 8;
            uint32_t a[2][4];
            #pragma unroll
            for (int mi = 0; mi < 2; mi++) {
                const int rA = m0 + mi * 16 + g;
                a[mi][0] = __float_as_uint(s_eh[rA * HS + kg + tg]);
                a[mi][1] = __float_as_uint(s_eh[(rA + 8) * HS + kg + tg]);
                a[mi][2] = __float_as_uint(s_eh[rA * HS + kg + 4 + tg]);
                a[mi][3] = __float_as_uint(s_eh[(rA + 8) * HS + kg + 4 + tg]);
            }
            #pragma unroll
            for (int t = 0; t < 2; t++) {
                const uint32_t b0 = __float_as_uint(s_Wc1[(kg + tg) * SBN3 + nb3 + t * 8 + g]);
                const uint32_t b1 = __float_as_uint(s_Wc1[(kg + 4 + tg) * SBN3 + nb3 + t * 8 + g]);
                mma_tf32(d3[0][t], a[0][0], a[0][1], a[0][2], a[0][3], b0, b1);
                mma_tf32(d3[1][t], a[1][0], a[1][1], a[1][2], a[1][3], b0, b1);
            }
        }
        #pragma unroll
        for (int mi = 0; mi < 2; mi++) {
            float sA = 0.f, sB2 = 0.f;
            #pragma unroll
            for (int t = 0; t < 2; t++) {
                sA  += silu_f(d3[mi][t][0] + bc1v[t][0]) * wc2v[t][0]
                     + silu_f(d3[mi][t][1] + bc1v[t][1]) * wc2v[t][1];
                sB2 += silu_f(d3[mi][t][2] + bc1v[t][0]) * wc2v[t][0]
                     + silu_f(d3[mi][t][3] + bc1v[t][1]) * wc2v[t][1];
            }
            const int rA = m0 + mi * 16 + g;
            atomicAdd(&s_coordb[p][rA], sA);
            atomicAdd(&s_coordb[p][rA + 8], sB2);
        }
        __syncthreads();     // F

        // ---- scatter ----
        for (int idx = tid; idx < TE * H; idx += 256) {
            const int e = idx >> 7, jc = idx & (H - 1);
            atomicAdd(&g_agg[s_srcb[p][e] * H + jc], s_eh[e * HS + jc]);
        }
        if (tid < TE) {
            const int src = s_srcb[p][tid];
            const float f = s_coordb[p][tid] * s_gateb[p][tid];
            atomicAdd(&g_cnt[src], 1.0f);
            atomicAdd(&g_delta[src * 3 + 0], s_unitb[p][tid][0] * f);
            atomicAdd(&g_delta[src * 3 + 1], s_unitb[p][tid][1] * f);
            atomicAdd(&g_delta[src * 3 + 2], s_unitb[p][tid][2] * f);
        }
        __syncthreads();     // G
    }
}

__global__ __launch_bounds__(256) void node_kernel(
    const float* __restrict__ x, const float* __restrict__ pos,
    const float* __restrict__ Wn, const float* __restrict__ bn,
    const float* __restrict__ gn, const float* __restrict__ btn,
    float* __restrict__ out)
{
    __shared__ __align__(16) float s_cat[TN * 260];
    const int tid = threadIdx.x;
    const int n0 = blockIdx.x * TN;

    for (int idx = tid; idx < TN * 64; idx += 256) {
        const int nl = idx >> 6, j4 = idx & 63;
        const int n = n0 + nl;
        float4 v = make_float4(0.f, 0.f, 0.f, 0.f);
        if (n < NN) {
            if (j4 < 32) {
                v = *(const float4*)&x[n * H + j4 * 4];
            } else {
                const float c = fmaxf(g_cnt[n], 1.f);
                const float iv = 1.f / c;
                v = *(const float4*)&g_agg[n * H + (j4 - 32) * 4];
                v.x *= iv; v.y *= iv; v.z *= iv; v.w *= iv;
            }
        }
        *(float4*)&s_cat[nl * 260 + j4 * 4] = v;
    }
    __syncthreads();

    const int jj = tid & 63, g = tid >> 6;
    const int nbv = g * 8;
    u64t accA[8], accB[8];
    #pragma unroll
    for (int e = 0; e < 8; e++) { accA[e] = 0ull; accB[e] = 0ull; }
    for (int k = 0; k < 256; k += 4) {
        const float wA0 = Wn[(k + 0) * H + jj],      wA1 = Wn[(k + 1) * H + jj];
        const float wA2 = Wn[(k + 2) * H + jj],      wA3 = Wn[(k + 3) * H + jj];
        const float wB0 = Wn[(k + 0) * H + jj + 64], wB1 = Wn[(k + 1) * H + jj + 64];
        const float wB2 = Wn[(k + 2) * H + jj + 64], wB3 = Wn[(k + 3) * H + jj + 64];
        const u64t pA0 = pack2(wA0, wA1), pA1 = pack2(wA2, wA3);
        const u64t pB0 = pack2(wB0, wB1), pB1 = pack2(wB2, wB3);
        #pragma unroll
        for (int e = 0; e < 8; e++) {
            const ulonglong2 v = *(const ulonglong2*)&s_cat[(nbv + e) * 260 + k];
            fma2(accA[e], v.x, pA0); fma2(accA[e], v.y, pA1);
            fma2(accB[e], v.x, pB0); fma2(accB[e], v.y, pB1);
        }
    }
    const float bA = bn[jj], bB = bn[jj + 64];
    __syncthreads();
    float* const s_y = s_cat;
    #pragma unroll
    for (int e = 0; e < 8; e++) {
        s_y[(nbv + e) * H + jj]      = silu_f(hadd2(accA[e]) + bA);
        s_y[(nbv + e) * H + jj + 64] = silu_f(hadd2(accB[e]) + bB);
    }
    __syncthreads();

    const int lane = tid & 31, wrp = tid >> 5;
    const float ga = gn[lane], gb = gn[lane + 32], gc = gn[lane + 64], gd = gn[lane + 96];
    const float ba = btn[lane], bb = btn[lane + 32], bcv = btn[lane + 64], bd = btn[lane + 96];
    #pragma unroll
    for (int qq = 0; qq < 4; qq++) {
        const int nl = wrp * 4 + qq;
        const int n = n0 + nl;
        float v0 = s_y[nl * H + lane], v1 = s_y[nl * H + lane + 32];
        float v2 = s_y[nl * H + lane + 64], v3 = s_y[nl * H + lane + 96];
        float s1 = v0 + v1 + v2 + v3;
        float s2 = v0 * v0 + v1 * v1 + v2 * v2 + v3 * v3;
        #pragma unroll
        for (int o = 16; o; o >>= 1) {
            s1 += __shfl_xor_sync(0xffffffffu, s1, o);
            s2 += __shfl_xor_sync(0xffffffffu, s2, o);
        }
        const float m = s1 * (1.f / 128.f);
        const float var = s2 * (1.f / 128.f) - m * m;
        const float rstd = rsqrtf(var + 1e-5f);
        if (n < NN) {
            out[n * H + lane]      = x[n * H + lane]      + (v0 - m) * rstd * ga + ba;
            out[n * H + lane + 32] = x[n * H + lane + 32] + (v1 - m) * rstd * gb + bb;
            out[n * H + lane + 64] = x[n * H + lane + 64] + (v2 - m) * rstd * gc + bcv;
            out[n * H + lane + 96] = x[n * H + lane + 96] + (v3 - m) * rstd * gd + bd;
        }
    }
    if (tid < TN) {
        const int n = n0 + tid;
        if (n < NN) {
            const float c = fmaxf(g_cnt[n], 1.f);
            const float s = 0.1f / c;
            out[NN * H + n * 3 + 0] = pos[n * 3 + 0] + s * g_delta[n * 3 + 0];
            out[NN * H + n * 3 + 1] = pos[n * 3 + 1] + s * g_delta[n * 3 + 1];
            out[NN * H + n * 3 + 2] = pos[n * 3 + 2] + s * g_delta[n * 3 + 2];
        }
    }

    // ---- re-zero scratch for next launch ----
    __syncthreads();
    const float4 z4 = make_float4(0.f, 0.f, 0.f, 0.f);
    for (int idx = tid; idx < TN * 32; idx += 256) {
        const int nl = idx >> 5, j4 = idx & 31;
        const int n = n0 + nl;
        if (n < NN) *(float4*)&g_agg[n * H + j4 * 4] = z4;
    }
    if (tid < TN) {
        const int n = n0 + tid;
        if (n < NN) {
            g_cnt[n] = 0.f;
            g_delta[n * 3 + 0] = 0.f;
            g_delta[n * 3 + 1] = 0.f;
            g_delta[n * 3 + 2] = 0.f;
        }
    }
}

extern "C" void kernel_launch(void* const* d_in, const int* in_sizes, int n_in,
                              void* d_out, int out_size) {
    const float* x         = (const float*)d_in[0];
    const float* pos       = (const float*)d_in[1];
    const float* charge    = (const float*)d_in[2];
    const float* edge_attr = (const float*)d_in[3];
    const int*   edge_index= (const int*)d_in[4];
    const float* We1 = (const float*)d_in[5];
    const float* be1 = (const float*)d_in[6];
    const float* g1  = (const float*)d_in[7];
    const float* bt1 = (const float*)d_in[8];
    const float* We2 = (const float*)d_in[9];
    const float* be2 = (const float*)d_in[10];
    const float* Wn  = (const float*)d_in[11];
    const float* bn  = (const float*)d_in[12];
    const float* gn  = (const float*)d_in[13];
    const float* btn = (const float*)d_in[14];
    const float* Wc1 = (const float*)d_in[15];
    const float* bc1 = (const float*)d_in[16];
    const float* Wc2 = (const float*)d_in[17];
    const float* bc2 = (const float*)d_in[18];
    float* out = (float*)d_out;

    cudaFuncSetAttribute(pre_kernel, cudaFuncAttributeMaxDynamicSharedMemorySize, SMEM_PRE);
    cudaFuncSetAttribute(edge_kernel, cudaFuncAttributeMaxDynamicSharedMemorySize, SMEM_EDGE);

    pre_kernel<<<(NN + 63) / 64, 256, SMEM_PRE>>>(x, We1);
    edge_kernel<<<GRID_EDGE, 256, SMEM_EDGE>>>(pos, charge, edge_attr, edge_index,
                                               We1, be1, g1, bt1, We2, be2, Wc1, bc1, Wc2, bc2);
    node_kernel<<<(NN + TN - 1) / TN, 256>>>(x, pos, Wn, bn, gn, btn, out);
}

// round 14
// speedup vs baseline: 1.8245x; 1.0200x over previous
#include <cuda_runtime.h>
#include <math.h>
#include <stdint.h>

#define NN 50000
#define NE 800000
#define H 128
#define NRAD 16
#define TE 64              // edges per tile
#define TN 32
#define NTILES (NE / TE)   // 12500
#define GRID_EDGE 148
#define HS  132            // P/Q/h/eh row stride: mod32=4
#define SBN 136            // weight row stride (N=128): mod32=8
#define SBN3 72            // weight row stride (N=64): mod32=8
#define EFS 24
#define PI_F 3.14159265358979f

// ---- persistent edge kernel dynamic smem layout (bytes) ----
#define SZ_T    (TE * HS * 4)               // 33792
#define OFF_P   0
#define OFF_Q   (OFF_P + SZ_T)              // 33792
#define OFF_H2  (OFF_Q + SZ_T)              // 67584 (h; eh overlays)
#define OFF_W1C (OFF_H2 + SZ_T)             // 101376
#define SZ_W1C  (24 * SBN * 4)              // 13056
#define OFF_W2  (OFF_W1C + SZ_W1C)          // 114432
#define SZ_W2   (128 * SBN * 4)             // 69632
#define OFF_WC1 (OFF_W2 + SZ_W2)            // 184064
#define SZ_WC1  (128 * SBN3 * 4)            // 36864
#define OFF_EFS (OFF_WC1 + SZ_WC1)          // 220928
#define SZ_EFS  (TE * EFS * 4)              // 6144
#define SMEM_EDGE (OFF_EFS + SZ_EFS)        // 227072

// ---- pre kernel smem ----
#define XS 132
#define SBNP 264
#define OFF_X   0
#define SZ_X    (64 * XS * 4)
#define OFF_PB0 (OFF_X + SZ_X)
#define SZ_PB   (32 * SBNP * 4)
#define OFF_PB1 (OFF_PB0 + SZ_PB)
#define SMEM_PRE (OFF_PB1 + SZ_PB)

typedef unsigned long long u64t;

__device__ float g_pq[NN * 256];
__device__ float g_agg[NN * H];
__device__ float g_cnt[NN];
__device__ float g_delta[NN * 3];

__device__ __forceinline__ float silu_f(float v) { return v / (1.f + __expf(-v)); }

__device__ __forceinline__ float tf32r(float f) {
    uint32_t u; asm("cvt.rna.tf32.f32 %0, %1;" : "=r"(u) : "f"(f));
    return __uint_as_float(u);
}
__device__ __forceinline__ float4 tf32r4(float4 v) {
    v.x = tf32r(v.x); v.y = tf32r(v.y); v.z = tf32r(v.z); v.w = tf32r(v.w);
    return v;
}
__device__ __forceinline__ void mma_tf32(float* d, uint32_t a0, uint32_t a1, uint32_t a2,
                                         uint32_t a3, uint32_t b0, uint32_t b1) {
    asm("mma.sync.aligned.m16n8k8.row.col.f32.tf32.tf32.f32 "
        "{%0,%1,%2,%3},{%4,%5,%6,%7},{%8,%9},{%0,%1,%2,%3};"
        : "+f"(d[0]), "+f"(d[1]), "+f"(d[2]), "+f"(d[3])
        : "r"(a0), "r"(a1), "r"(a2), "r"(a3), "r"(b0), "r"(b1));
}

__device__ __forceinline__ void fma2(u64t& d, u64t a, u64t b) {
    asm("fma.rn.f32x2 %0, %1, %2, %0;" : "+l"(d) : "l"(a), "l"(b));
}
__device__ __forceinline__ u64t pack2(float lo, float hi) {
    u64t d; asm("mov.b64 %0, {%1, %2};" : "=l"(d) : "f"(lo), "f"(hi)); return d;
}
__device__ __forceinline__ float hadd2(u64t d) {
    float lo, hi; asm("mov.b64 {%0, %1}, %2;" : "=f"(lo), "=f"(hi) : "l"(d));
    return lo + hi;
}

__device__ __forceinline__ void cpasync16(uint32_t smem_dst, const void* gsrc) {
    asm volatile("cp.async.cg.shared.global [%0], [%1], 16;" :: "r"(smem_dst), "l"(gsrc));
}
#define CPASYNC_COMMIT() asm volatile("cp.async.commit_group;" ::: "memory")
#define CPASYNC_WAIT0()  asm volatile("cp.async.wait_group 0;" ::: "memory")

// vectorized global fp32 reduction (fire-and-forget)
__device__ __forceinline__ void red_add_v4(float* gptr, float4 v) {
    asm volatile("red.global.add.v4.f32 [%0], {%1, %2, %3, %4};"
                 :: "l"(gptr), "f"(v.x), "f"(v.y), "f"(v.z), "f"(v.w) : "memory");
}

// shared scalar-feature math
__device__ __forceinline__ void edge_scalar_body(
    float rx, float ry, float rz, float qs, float qd, float4 ea,
    float* efs_row, float* gate_out, float* unit_out)
{
    const float dist = sqrtf(rx * rx + ry * ry + rz * rz + 1e-8f);
    const float inv = 1.f / dist;
    unit_out[0] = rx * inv; unit_out[1] = ry * inv; unit_out[2] = rz * inv;

    float ca = cosf(ea.x);
    float p2 = 0.5f * (3.f * ca * ca - 1.f);
    float p3 = (5.f * ca * p2 - 2.f * ca) * (1.f / 3.f);
    float a_score = 0.25f * (1.f + fabsf(ca) + fabsf(p2) + fabsf(p3)) * ea.z;
    float cd = cosf(ea.y);
    float q2 = 0.5f * (3.f * cd * cd - 1.f);
    float q3 = (5.f * cd * q2 - 2.f * cd) * (1.f / 3.f);
    float d_score = 0.25f * (1.f + fabsf(cd) + fabsf(q2) + fabsf(q3)) * ea.w;
    float gate = fminf(fmaxf(1.f + 0.6f * (a_score + d_score), 0.35f), 2.5f);
    *gate_out = gate;

    const float gi = gate * inv;
    #pragma unroll
    for (int i = 0; i < NRAD; i++) {
        float f = (float)(i + 1) * (PI_F / 5.0f);
        efs_row[i] = tf32r(sinf(f * dist) * gi);
    }
    efs_row[16] = tf32r(dist * 0.2f * gate);
    efs_row[17] = tf32r(qs * qd * gate);
    efs_row[18] = tf32r(fabsf(qs - qd) * gate);
    #pragma unroll
    for (int i = 19; i < EFS; i++) efs_row[i] = 0.f;
}

// ================== PQ = x @ [We1a | We1b] ==================
__global__ __launch_bounds__(256) void pre_kernel(
    const float* __restrict__ x, const float* __restrict__ We1)
{
    extern __shared__ __align__(16) char dsm[];
    float* const s_x  = (float*)(dsm + OFF_X);
    float* const s_P0 = (float*)(dsm + OFF_PB0);
    float* const s_P1 = (float*)(dsm + OFF_PB1);

    const int tid = threadIdx.x;
    const int n0 = blockIdx.x * 64;
    const float4 z4 = make_float4(0.f, 0.f, 0.f, 0.f);

    for (int idx = tid; idx < 64 * 32; idx += 256) {
        const int e = idx >> 5, j4 = idx & 31;
        const int n = n0 + e;
        float4 v = (n < NN) ? tf32r4(*(const float4*)&x[n * H + j4 * 4]) : z4;
        *(float4*)&s_x[e * XS + j4 * 4] = v;
    }

    const int lane = tid & 31, w = tid >> 5;
    const int g = lane >> 2, tg = lane & 3;
    const int m0 = (w & 1) * 32;
    const int nb = (w >> 1) * 64;
    const int kk = tid >> 3, q = tid & 7;

    float d[2][8][4];
    #pragma unroll
    for (int mi = 0; mi < 2; mi++)
        #pragma unroll
        for (int t = 0; t < 8; t++)
            #pragma unroll
            for (int i = 0; i < 4; i++) d[mi][t][i] = 0.f;

    float4 ra0, ra1, ra2, ra3, rb0, rb1, rb2, rb3;
    {
        const float* sa = &We1[kk * H + q * 16];
        const float* sb = &We1[(128 + kk) * H + q * 16];
        ra0 = tf32r4(*(const float4*)(sa + 0));  ra1 = tf32r4(*(const float4*)(sa + 4));
        ra2 = tf32r4(*(const float4*)(sa + 8));  ra3 = tf32r4(*(const float4*)(sa + 12));
        rb0 = tf32r4(*(const float4*)(sb + 0));  rb1 = tf32r4(*(const float4*)(sb + 4));
        rb2 = tf32r4(*(const float4*)(sb + 8));  rb3 = tf32r4(*(const float4*)(sb + 12));
        float* dw = &s_P0[kk * SBNP];
        *(float4*)(dw + q * 16 + 0) = ra0; *(float4*)(dw + q * 16 + 4) = ra1;
        *(float4*)(dw + q * 16 + 8) = ra2; *(float4*)(dw + q * 16 + 12) = ra3;
        *(float4*)(dw + 128 + q * 16 + 0) = rb0; *(float4*)(dw + 128 + q * 16 + 4) = rb1;
        *(float4*)(dw + 128 + q * 16 + 8) = rb2; *(float4*)(dw + 128 + q * 16 + 12) = rb3;
    }
    for (int c = 0; c < 4; c++) {
        if (c < 3) {
            const int k = (c + 1) * 32 + kk;
            const float* sa = &We1[k * H + q * 16];
            const float* sb = &We1[(128 + k) * H + q * 16];
            ra0 = tf32r4(*(const float4*)(sa + 0));  ra1 = tf32r4(*(const float4*)(sa + 4));
            ra2 = tf32r4(*(const float4*)(sa + 8));  ra3 = tf32r4(*(const float4*)(sa + 12));
            rb0 = tf32r4(*(const float4*)(sb + 0));  rb1 = tf32r4(*(const float4*)(sb + 4));
            rb2 = tf32r4(*(const float4*)(sb + 8));  rb3 = tf32r4(*(const float4*)(sb + 12));
        }
        __syncthreads();
        const float* bp = (c & 1) ? s_P1 : s_P0;
        #pragma unroll
        for (int ks = 0; ks < 4; ks++) {
            const int kg = c * 32 + ks * 8, kl = ks * 8;
            uint32_t a[2][4];
            #pragma unroll
            for (int mi = 0; mi < 2; mi++) {
                const int rA = m0 + mi * 16 + g;
                a[mi][0] = __float_as_uint(s_x[rA * XS + kg + tg]);
                a[mi][1] = __float_as_uint(s_x[(rA + 8) * XS + kg + tg]);
                a[mi][2] = __float_as_uint(s_x[rA * XS + kg + 4 + tg]);
                a[mi][3] = __float_as_uint(s_x[(rA + 8) * XS + kg + 4 + tg]);
            }
            #pragma unroll
            for (int t = 0; t < 8; t++) {
                const uint32_t b0 = __float_as_uint(bp[(kl + tg) * SBNP + nb + t * 8 + g]);
                const uint32_t b1 = __float_as_uint(bp[(kl + 4 + tg) * SBNP + nb + t * 8 + g]);
                mma_tf32(d[0][t], a[0][0], a[0][1], a[0][2], a[0][3], b0, b1);
                mma_tf32(d[1][t], a[1][0], a[1][1], a[1][2], a[1][3], b0, b1);
            }
        }
        if (c < 3) {
            float* np = (c & 1) ? s_P0 : s_P1;
            float* dw = &np[kk * SBNP];
            *(float4*)(dw + q * 16 + 0) = ra0; *(float4*)(dw + q * 16 + 4) = ra1;
            *(float4*)(dw + q * 16 + 8) = ra2; *(float4*)(dw + q * 16 + 12) = ra3;
            *(float4*)(dw + 128 + q * 16 + 0) = rb0; *(float4*)(dw + 128 + q * 16 + 4) = rb1;
            *(float4*)(dw + 128 + q * 16 + 8) = rb2; *(float4*)(dw + 128 + q * 16 + 12) = rb3;
        }
    }

    #pragma unroll
    for (int mi = 0; mi < 2; mi++) {
        const int r0w = n0 + m0 + mi * 16 + g;
        #pragma unroll
        for (int t = 0; t < 8; t++) {
            const int col = nb + t * 8 + tg * 2;
            if (r0w < NN)
                *(float2*)&g_pq[r0w * 256 + col] = make_float2(d[mi][t][0], d[mi][t][1]);
            if (r0w + 8 < NN)
                *(float2*)&g_pq[(r0w + 8) * 256 + col] = make_float2(d[mi][t][2], d[mi][t][3]);
        }
    }
}

// ================== persistent, software-pipelined edge kernel ==================
__global__ __launch_bounds__(256) void edge_kernel(
    const float* __restrict__ pos,
    const float* __restrict__ charge, const float* __restrict__ edge_attr,
    const int* __restrict__ edge_index,
    const float* __restrict__ We1, const float* __restrict__ be1,
    const float* __restrict__ g1, const float* __restrict__ bt1,
    const float* __restrict__ We2, const float* __restrict__ be2,
    const float* __restrict__ Wc1, const float* __restrict__ bc1,
    const float* __restrict__ Wc2, const float* __restrict__ bc2)
{
    extern __shared__ __align__(16) char dsm[];
    float* const s_P   = (float*)(dsm + OFF_P);
    float* const s_Q   = (float*)(dsm + OFF_Q);
    float* const s_h   = (float*)(dsm + OFF_H2);
    float* const s_eh  = (float*)(dsm + OFF_H2);
    float* const s_W1c = (float*)(dsm + OFF_W1C);
    float* const s_W2  = (float*)(dsm + OFF_W2);
    float* const s_Wc1 = (float*)(dsm + OFF_WC1);
    float* const efs   = (float*)(dsm + OFF_EFS);

    __shared__ float s_gateb[2][TE];
    __shared__ float s_unitb[2][TE][3];
    __shared__ int   s_srcb[2][TE];
    __shared__ float s_coordb[2][TE];
    __shared__ int   s_idx2[128];

    const int tid = threadIdx.x;
    const float4 z4 = make_float4(0.f, 0.f, 0.f, 0.f);
    const uint32_t sPb = (uint32_t)__cvta_generic_to_shared(s_P);
    const uint32_t sQb = (uint32_t)__cvta_generic_to_shared(s_Q);

    // ---- stage ALL weights once (tf32) ----
    for (int idx = tid; idx < 24 * 32; idx += 256) {
        const int r = idx >> 5, c4 = (idx & 31) * 4;
        float4 v = (r < 19) ? tf32r4(*(const float4*)&We1[(256 + r) * H + c4]) : z4;
        *(float4*)&s_W1c[r * SBN + c4] = v;
    }
    for (int idx = tid; idx < 128 * 32; idx += 256) {
        const int r = idx >> 5, c4 = (idx & 31) * 4;
        *(float4*)&s_W2[r * SBN + c4] = tf32r4(*(const float4*)&We2[r * H + c4]);
    }
    for (int idx = tid; idx < 128 * 16; idx += 256) {
        const int r = idx >> 4, c4 = (idx & 15) * 4;
        *(float4*)&s_Wc1[r * SBN3 + c4] = tf32r4(*(const float4*)&Wc1[r * 64 + c4]);
    }

    const int lane = tid & 31, w = tid >> 5;
    const int g = lane >> 2, tg = lane & 3;
    const int m0 = (w & 1) * 32;
    const int nb = (w >> 1) * 32;
    const int nb3 = (w >> 1) * 16;

    float ln_g[4], ln_b[4];
    ln_g[0] = g1[lane]; ln_g[1] = g1[lane + 32]; ln_g[2] = g1[lane + 64]; ln_g[3] = g1[lane + 96];
    ln_b[0] = bt1[lane]; ln_b[1] = bt1[lane + 32]; ln_b[2] = bt1[lane + 64]; ln_b[3] = bt1[lane + 96];
    float be1v[4][2], be2v[4][2];
    #pragma unroll
    for (int t = 0; t < 4; t++) {
        const int col = nb + t * 8 + tg * 2;
        be1v[t][0] = be1[col]; be1v[t][1] = be1[col + 1];
        be2v[t][0] = be2[col]; be2v[t][1] = be2[col + 1];
    }
    float wc2v[2][2], bc1v[2][2];
    #pragma unroll
    for (int t = 0; t < 2; t++) {
        const int col = nb3 + t * 8 + tg * 2;
        wc2v[t][0] = Wc2[col]; wc2v[t][1] = Wc2[col + 1];
        bc1v[t][0] = bc1[col]; bc1v[t][1] = bc1[col + 1];
    }
    const float bc2v = bc2[0];

    // ---- prologue: tile 0 scalars + gather ----
    {
        const int e0p = blockIdx.x * TE;
        if (tid < TE) {
            const int e = e0p + tid;
            const int src = edge_index[e];
            const int dst = edge_index[NE + e];
            s_srcb[0][tid] = src;
            const float rx = pos[dst * 3 + 0] - pos[src * 3 + 0];
            const float ry = pos[dst * 3 + 1] - pos[src * 3 + 1];
            const float rz = pos[dst * 3 + 2] - pos[src * 3 + 2];
            edge_scalar_body(rx, ry, rz, charge[src], charge[dst],
                             *(const float4*)&edge_attr[e * 4],
                             &efs[tid * EFS], &s_gateb[0][tid], &s_unitb[0][tid][0]);
            s_coordb[0][tid] = bc2v;
        }
        for (int idx = tid; idx < TE * 32; idx += 256) {
            const int e = idx >> 5, j4 = idx & 31;
            const int src = edge_index[e0p + e];
            const int dst = edge_index[NE + e0p + e];
            *(float4*)&s_P[e * HS + j4 * 4] = *(const float4*)&g_pq[src * 256 + j4 * 4];
            *(float4*)&s_Q[e * HS + j4 * 4] = *(const float4*)&g_pq[dst * 256 + 128 + j4 * 4];
        }
    }

    int p = 0;
    for (int tile = blockIdx.x; tile < NTILES; tile += GRID_EDGE, p ^= 1) {
        const int np = p ^ 1;
        const int nt = tile + GRID_EDGE;
        const bool has_next = (nt < NTILES);

        int ni = 0, ndsti = 0;
        if (has_next) {
            if (tid < 128) {
                const int off = (tid < 64) ? (nt * TE + tid) : (NE + nt * TE + (tid - 64));
                ni = edge_index[off];
            }
            if (tid < 64) ndsti = edge_index[NE + nt * TE + tid];
        }

        CPASYNC_WAIT0();
        __syncthreads();     // A

        // ---- GEMM1-small + epilogue1 -> s_h ----
        float d[2][4][4];
        #pragma unroll
        for (int mi = 0; mi < 2; mi++)
            #pragma unroll
            for (int t = 0; t < 4; t++)
                #pragma unroll
                for (int i = 0; i < 4; i++) d[mi][t][i] = 0.f;
        #pragma unroll
        for (int ks = 0; ks < 3; ks++) {
            const int kg = ks * 8;
            uint32_t a[2][4];
            #pragma unroll
            for (int mi = 0; mi < 2; mi++) {
                const int rA = m0 + mi * 16 + g;
                a[mi][0] = __float_as_uint(efs[rA * EFS + kg + tg]);
                a[mi][1] = __float_as_uint(efs[(rA + 8) * EFS + kg + tg]);
                a[mi][2] = __float_as_uint(efs[rA * EFS + kg + 4 + tg]);
                a[mi][3] = __float_as_uint(efs[(rA + 8) * EFS + kg + 4 + tg]);
            }
            #pragma unroll
            for (int t = 0; t < 4; t++) {
                const uint32_t b0 = __float_as_uint(s_W1c[(kg + tg) * SBN + nb + t * 8 + g]);
                const uint32_t b1 = __float_as_uint(s_W1c[(kg + 4 + tg) * SBN + nb + t * 8 + g]);
                mma_tf32(d[0][t], a[0][0], a[0][1], a[0][2], a[0][3], b0, b1);
                mma_tf32(d[1][t], a[1][0], a[1][1], a[1][2], a[1][3], b0, b1);
            }
        }
        #pragma unroll
        for (int t = 0; t < 4; t++) {
            const int col = nb + t * 8 + tg * 2;
            #pragma unroll
            for (int mi = 0; mi < 2; mi++) {
                const int rA = m0 + mi * 16 + g;
                s_h[rA * HS + col] =
                    silu_f(d[mi][t][0] + s_P[rA * HS + col] + s_Q[rA * HS + col] + be1v[t][0]);
                s_h[rA * HS + col + 1] =
                    silu_f(d[mi][t][1] + s_P[rA * HS + col + 1] + s_Q[rA * HS + col + 1] + be1v[t][1]);
                s_h[(rA + 8) * HS + col] =
                    silu_f(d[mi][t][2] + s_P[(rA + 8) * HS + col] + s_Q[(rA + 8) * HS + col] + be1v[t][0]);
                s_h[(rA + 8) * HS + col + 1] =
                    silu_f(d[mi][t][3] + s_P[(rA + 8) * HS + col + 1] + s_Q[(rA + 8) * HS + col + 1] + be1v[t][1]);
            }
        }
        __syncthreads();     // B

        float psx = 0.f, psy = 0.f, psz = 0.f, pdx = 0.f, pdy = 0.f, pdz = 0.f;
        float qsv = 0.f, qdv = 0.f;
        float4 nea = z4;
        if (has_next && tid < 64) {
            psx = pos[ni * 3 + 0]; psy = pos[ni * 3 + 1]; psz = pos[ni * 3 + 2];
            pdx = pos[ndsti * 3 + 0]; pdy = pos[ndsti * 3 + 1]; pdz = pos[ndsti * 3 + 2];
            qsv = charge[ni]; qdv = charge[ndsti];
            nea = *(const float4*)&edge_attr[(nt * TE + tid) * 4];
        }

        // ---- LayerNorm(h) ----
        #pragma unroll
        for (int qq = 0; qq < 8; qq++) {
            const int e = w * 8 + qq;
            float v0 = s_h[e * HS + lane], v1 = s_h[e * HS + lane + 32];
            float v2 = s_h[e * HS + lane + 64], v3 = s_h[e * HS + lane + 96];
            float s1 = v0 + v1 + v2 + v3;
            float s2 = v0 * v0 + v1 * v1 + v2 * v2 + v3 * v3;
            #pragma unroll
            for (int o = 16; o; o >>= 1) {
                s1 += __shfl_xor_sync(0xffffffffu, s1, o);
                s2 += __shfl_xor_sync(0xffffffffu, s2, o);
            }
            const float m = s1 * (1.f / 128.f);
            const float var = s2 * (1.f / 128.f) - m * m;
            const float rstd = rsqrtf(var + 1e-5f);
            s_h[e * HS + lane]      = tf32r((v0 - m) * rstd * ln_g[0] + ln_b[0]);
            s_h[e * HS + lane + 32] = tf32r((v1 - m) * rstd * ln_g[1] + ln_b[1]);
            s_h[e * HS + lane + 64] = tf32r((v2 - m) * rstd * ln_g[2] + ln_b[2]);
            s_h[e * HS + lane + 96] = tf32r((v3 - m) * rstd * ln_g[3] + ln_b[3]);
        }
        __syncthreads();     // C

        if (has_next && tid < 128) s_idx2[tid] = ni;

        // ---- GEMM2: h @ We2 ----
        #pragma unroll
        for (int mi = 0; mi < 2; mi++)
            #pragma unroll
            for (int t = 0; t < 4; t++)
                #pragma unroll
                for (int i = 0; i < 4; i++) d[mi][t][i] = 0.f;
        #pragma unroll 4
        for (int ks = 0; ks < 16; ks++) {
            const int kg = ks * 8;
            uint32_t a[2][4];
            #pragma unroll
            for (int mi = 0; mi < 2; mi++) {
                const int rA = m0 + mi * 16 + g;
                a[mi][0] = __float_as_uint(s_h[rA * HS + kg + tg]);
                a[mi][1] = __float_as_uint(s_h[(rA + 8) * HS + kg + tg]);
                a[mi][2] = __float_as_uint(s_h[rA * HS + kg + 4 + tg]);
                a[mi][3] = __float_as_uint(s_h[(rA + 8) * HS + kg + 4 + tg]);
            }
            #pragma unroll
            for (int t = 0; t < 4; t++) {
                const uint32_t b0 = __float_as_uint(s_W2[(kg + tg) * SBN + nb + t * 8 + g]);
                const uint32_t b1 = __float_as_uint(s_W2[(kg + 4 + tg) * SBN + nb + t * 8 + g]);
                mma_tf32(d[0][t], a[0][0], a[0][1], a[0][2], a[0][3], b0, b1);
                mma_tf32(d[1][t], a[1][0], a[1][1], a[1][2], a[1][3], b0, b1);
            }
        }
        __syncthreads();     // D

        // ---- epilogue2: eh = silu(+be2) -> s_eh ----
        #pragma unroll
        for (int t = 0; t < 4; t++) {
            const int col = nb + t * 8 + tg * 2;
            #pragma unroll
            for (int mi = 0; mi < 2; mi++) {
                const int rA = m0 + mi * 16 + g;
                s_eh[rA * HS + col]           = tf32r(silu_f(d[mi][t][0] + be2v[t][0]));
                s_eh[rA * HS + col + 1]       = tf32r(silu_f(d[mi][t][1] + be2v[t][1]));
                s_eh[(rA + 8) * HS + col]     = tf32r(silu_f(d[mi][t][2] + be2v[t][0]));
                s_eh[(rA + 8) * HS + col + 1] = tf32r(silu_f(d[mi][t][3] + be2v[t][1]));
            }
        }

        // ---- pipelined prefetch for next tile ----
        if (has_next) {
            #pragma unroll
            for (int k = 0; k < 8; k++) {
                const int idx = tid + k * 256;
                const int e = idx >> 5, j4 = idx & 31;
                const int se = s_idx2[e];
                const int de = s_idx2[64 + e];
                cpasync16(sPb + e * (HS * 4) + j4 * 16,
                          (const char*)g_pq + (size_t)se * 1024 + (size_t)j4 * 16);
                cpasync16(sQb + e * (HS * 4) + j4 * 16,
                          (const char*)g_pq + (size_t)de * 1024 + 512 + (size_t)j4 * 16);
            }
            CPASYNC_COMMIT();
            if (tid < 64) {
                edge_scalar_body(pdx - psx, pdy - psy, pdz - psz, qsv, qdv, nea,
                                 &efs[tid * EFS], &s_gateb[np][tid], &s_unitb[np][tid][0]);
                s_srcb[np][tid] = ni;
                s_coordb[np][tid] = bc2v;
            }
        }
        __syncthreads();     // E

        // ---- agg scatter FIRST (fire-and-forget v4 REDs overlap GEMM3) ----
        #pragma unroll
        for (int k = 0; k < 8; k++) {
            const int idx = tid + k * 256;
            const int e = idx >> 5, j4 = idx & 31;
            const float4 v = *(const float4*)&s_eh[e * HS + j4 * 4];
            red_add_v4(&g_agg[s_srcb[p][e] * H + j4 * 4], v);
        }

        // ---- GEMM3: eh @ Wc1 + coord epilogue ----
        float d3[2][2][4];
        #pragma unroll
        for (int mi = 0; mi < 2; mi++)
            #pragma unroll
            for (int t = 0; t < 2; t++)
                #pragma unroll
                for (int i = 0; i < 4; i++) d3[mi][t][i] = 0.f;
        #pragma unroll 4
        for (int ks = 0; ks < 16; ks++) {
            const int kg = ks * 8;
            uint32_t a[2][4];
            #pragma unroll
            for (int mi = 0; mi < 2; mi++) {
                const int rA = m0 + mi * 16 + g;
                a[mi][0] = __float_as_uint(s_eh[rA * HS + kg + tg]);
                a[mi][1] = __float_as_uint(s_eh[(rA + 8) * HS + kg + tg]);
                a[mi][2] = __float_as_uint(s_eh[rA * HS + kg + 4 + tg]);
                a[mi][3] = __float_as_uint(s_eh[(rA + 8) * HS + kg + 4 + tg]);
            }
            #pragma unroll
            for (int t = 0; t < 2; t++) {
                const uint32_t b0 = __float_as_uint(s_Wc1[(kg + tg) * SBN3 + nb3 + t * 8 + g]);
                const uint32_t b1 = __float_as_uint(s_Wc1[(kg + 4 + tg) * SBN3 + nb3 + t * 8 + g]);
                mma_tf32(d3[0][t], a[0][0], a[0][1], a[0][2], a[0][3], b0, b1);
                mma_tf32(d3[1][t], a[1][0], a[1][1], a[1][2], a[1][3], b0, b1);
            }
        }
        #pragma unroll
        for (int mi = 0; mi < 2; mi++) {
            float sA = 0.f, sB2 = 0.f;
            #pragma unroll
            for (int t = 0; t < 2; t++) {
                sA  += silu_f(d3[mi][t][0] + bc1v[t][0]) * wc2v[t][0]
                     + silu_f(d3[mi][t][1] + bc1v[t][1]) * wc2v[t][1];
                sB2 += silu_f(d3[mi][t][2] + bc1v[t][0]) * wc2v[t][0]
                     + silu_f(d3[mi][t][3] + bc1v[t][1]) * wc2v[t][1];
            }
            const int rA = m0 + mi * 16 + g;
            atomicAdd(&s_coordb[p][rA], sA);
            atomicAdd(&s_coordb[p][rA + 8], sB2);
        }
        __syncthreads();     // F

        // ---- cnt/delta scatter ----
        if (tid < TE) {
            const int src = s_srcb[p][tid];
            const float f = s_coordb[p][tid] * s_gateb[p][tid];
            atomicAdd(&g_cnt[src], 1.0f);
            atomicAdd(&g_delta[src * 3 + 0], s_unitb[p][tid][0] * f);
            atomicAdd(&g_delta[src * 3 + 1], s_unitb[p][tid][1] * f);
            atomicAdd(&g_delta[src * 3 + 2], s_unitb[p][tid][2] * f);
        }
        // no barrier: next-iter barrier A separates all smem reuse
    }
}

__global__ __launch_bounds__(256) void node_kernel(
    const float* __restrict__ x, const float* __restrict__ pos,
    const float* __restrict__ Wn, const float* __restrict__ bn,
    const float* __restrict__ gn, const float* __restrict__ btn,
    float* __restrict__ out)
{
    __shared__ __align__(16) float s_cat[TN * 260];
    const int tid = threadIdx.x;
    const int n0 = blockIdx.x * TN;

    for (int idx = tid; idx < TN * 64; idx += 256) {
        const int nl = idx >> 6, j4 = idx & 63;
        const int n = n0 + nl;
        float4 v = make_float4(0.f, 0.f, 0.f, 0.f);
        if (n < NN) {
            if (j4 < 32) {
                v = *(const float4*)&x[n * H + j4 * 4];
            } else {
                const float c = fmaxf(g_cnt[n], 1.f);
                const float iv = 1.f / c;
                v = *(const float4*)&g_agg[n * H + (j4 - 32) * 4];
                v.x *= iv; v.y *= iv; v.z *= iv; v.w *= iv;
            }
        }
        *(float4*)&s_cat[nl * 260 + j4 * 4] = v;
    }
    __syncthreads();

    const int jj = tid & 63, g = tid >> 6;
    const int nbv = g * 8;
    u64t accA[8], accB[8];
    #pragma unroll
    for (int e = 0; e < 8; e++) { accA[e] = 0ull; accB[e] = 0ull; }
    for (int k = 0; k < 256; k += 4) {
        const float wA0 = Wn[(k + 0) * H + jj],      wA1 = Wn[(k + 1) * H + jj];
        const float wA2 = Wn[(k + 2) * H + jj],      wA3 = Wn[(k + 3) * H + jj];
        const float wB0 = Wn[(k + 0) * H + jj + 64], wB1 = Wn[(k + 1) * H + jj + 64];
        const float wB2 = Wn[(k + 2) * H + jj + 64], wB3 = Wn[(k + 3) * H + jj + 64];
        const u64t pA0 = pack2(wA0, wA1), pA1 = pack2(wA2, wA3);
        const u64t pB0 = pack2(wB0, wB1), pB1 = pack2(wB2, wB3);
        #pragma unroll
        for (int e = 0; e < 8; e++) {
            const ulonglong2 v = *(const ulonglong2*)&s_cat[(nbv + e) * 260 + k];
            fma2(accA[e], v.x, pA0); fma2(accA[e], v.y, pA1);
            fma2(accB[e], v.x, pB0); fma2(accB[e], v.y, pB1);
        }
    }
    const float bA = bn[jj], bB = bn[jj + 64];
    __syncthreads();
    float* const s_y = s_cat;
    #pragma unroll
    for (int e = 0; e < 8; e++) {
        s_y[(nbv + e) * H + jj]      = silu_f(hadd2(accA[e]) + bA);
        s_y[(nbv + e) * H + jj + 64] = silu_f(hadd2(accB[e]) + bB);
    }
    __syncthreads();

    const int lane = tid & 31, wrp = tid >> 5;
    const float ga = gn[lane], gb = gn[lane + 32], gc = gn[lane + 64], gd = gn[lane + 96];
    const float ba = btn[lane], bb = btn[lane + 32], bcv = btn[lane + 64], bd = btn[lane + 96];
    #pragma unroll
    for (int qq = 0; qq < 4; qq++) {
        const int nl = wrp * 4 + qq;
        const int n = n0 + nl;
        float v0 = s_y[nl * H + lane], v1 = s_y[nl * H + lane + 32];
        float v2 = s_y[nl * H + lane + 64], v3 = s_y[nl * H + lane + 96];
        float s1 = v0 + v1 + v2 + v3;
        float s2 = v0 * v0 + v1 * v1 + v2 * v2 + v3 * v3;
        #pragma unroll
        for (int o = 16; o; o >>= 1) {
            s1 += __shfl_xor_sync(0xffffffffu, s1, o);
            s2 += __shfl_xor_sync(0xffffffffu, s2, o);
        }
        const float m = s1 * (1.f / 128.f);
        const float var = s2 * (1.f / 128.f) - m * m;
        const float rstd = rsqrtf(var + 1e-5f);
        if (n < NN) {
            out[n * H + lane]      = x[n * H + lane]      + (v0 - m) * rstd * ga + ba;
            out[n * H + lane + 32] = x[n * H + lane + 32] + (v1 - m) * rstd * gb + bb;
            out[n * H + lane + 64] = x[n * H + lane + 64] + (v2 - m) * rstd * gc + bcv;
            out[n * H + lane + 96] = x[n * H + lane + 96] + (v3 - m) * rstd * gd + bd;
        }
    }
    if (tid < TN) {
        const int n = n0 + tid;
        if (n < NN) {
            const float c = fmaxf(g_cnt[n], 1.f);
            const float s = 0.1f / c;
            out[NN * H + n * 3 + 0] = pos[n * 3 + 0] + s * g_delta[n * 3 + 0];
            out[NN * H + n * 3 + 1] = pos[n * 3 + 1] + s * g_delta[n * 3 + 1];
            out[NN * H + n * 3 + 2] = pos[n * 3 + 2] + s * g_delta[n * 3 + 2];
        }
    }

    // ---- re-zero scratch for next launch ----
    __syncthreads();
    const float4 z4 = make_float4(0.f, 0.f, 0.f, 0.f);
    for (int idx = tid; idx < TN * 32; idx += 256) {
        const int nl = idx >> 5, j4 = idx & 31;
        const int n = n0 + nl;
        if (n < NN) *(float4*)&g_agg[n * H + j4 * 4] = z4;
    }
    if (tid < TN) {
        const int n = n0 + tid;
        if (n < NN) {
            g_cnt[n] = 0.f;
            g_delta[n * 3 + 0] = 0.f;
            g_delta[n * 3 + 1] = 0.f;
            g_delta[n * 3 + 2] = 0.f;
        }
    }
}

extern "C" void kernel_launch(void* const* d_in, const int* in_sizes, int n_in,
                              void* d_out, int out_size) {
    const float* x         = (const float*)d_in[0];
    const float* pos       = (const float*)d_in[1];
    const float* charge    = (const float*)d_in[2];
    const float* edge_attr = (const float*)d_in[3];
    const int*   edge_index= (const int*)d_in[4];
    const float* We1 = (const float*)d_in[5];
    const float* be1 = (const float*)d_in[6];
    const float* g1  = (const float*)d_in[7];
    const float* bt1 = (const float*)d_in[8];
    const float* We2 = (const float*)d_in[9];
    const float* be2 = (const float*)d_in[10];
    const float* Wn  = (const float*)d_in[11];
    const float* bn  = (const float*)d_in[12];
    const float* gn  = (const float*)d_in[13];
    const float* btn = (const float*)d_in[14];
    const float* Wc1 = (const float*)d_in[15];
    const float* bc1 = (const float*)d_in[16];
    const float* Wc2 = (const float*)d_in[17];
    const float* bc2 = (const float*)d_in[18];
    float* out = (float*)d_out;

    cudaFuncSetAttribute(pre_kernel, cudaFuncAttributeMaxDynamicSharedMemorySize, SMEM_PRE);
    cudaFuncSetAttribute(edge_kernel, cudaFuncAttributeMaxDynamicSharedMemorySize, SMEM_EDGE);

    pre_kernel<<<(NN + 63) / 64, 256, SMEM_PRE>>>(x, We1);
    edge_kernel<<<GRID_EDGE, 256, SMEM_EDGE>>>(pos, charge, edge_attr, edge_index,
                                               We1, be1, g1, bt1, We2, be2, Wc1, bc1, Wc2, bc2);
    node_kernel<<<(NN + TN - 1) / TN, 256>>>(x, pos, Wn, bn, gn, btn, out);
}

// round 15
// speedup vs baseline: 2.1411x; 1.1735x over previous
#include <cuda_runtime.h>
#include <math.h>
#include <stdint.h>

#define NN 50000
#define NE 800000
#define H 128
#define NRAD 16
#define TE 64              // edges per tile
#define TN 32
#define NTILES (NE / TE)   // 12500
#define GRID_EDGE 148
#define THREADS 512        // 16 warps: 4 m-tiles x 4 n-blocks
#define HS  132            // P/Q/h/eh row stride: mod32=4
#define SBN 136            // weight row stride (N=128): mod32=8
#define SBN3 72            // weight row stride (N=64): mod32=8
#define EFS 24
#define PI_F 3.14159265358979f

// ---- persistent edge kernel dynamic smem layout (bytes) ----
#define SZ_T    (TE * HS * 4)               // 33792
#define OFF_P   0
#define OFF_Q   (OFF_P + SZ_T)              // 33792
#define OFF_H2  (OFF_Q + SZ_T)              // 67584 (h; eh overlays)
#define OFF_W1C (OFF_H2 + SZ_T)             // 101376
#define SZ_W1C  (24 * SBN * 4)              // 13056
#define OFF_W2  (OFF_W1C + SZ_W1C)          // 114432
#define SZ_W2   (128 * SBN * 4)             // 69632
#define OFF_WC1 (OFF_W2 + SZ_W2)            // 184064
#define SZ_WC1  (128 * SBN3 * 4)            // 36864
#define OFF_EFS (OFF_WC1 + SZ_WC1)          // 220928
#define SZ_EFS  (TE * EFS * 4)              // 6144
#define SMEM_EDGE (OFF_EFS + SZ_EFS)        // 227072

// ---- pre kernel smem ----
#define XS 132
#define SBNP 264
#define OFF_X   0
#define SZ_X    (64 * XS * 4)
#define OFF_PB0 (OFF_X + SZ_X)
#define SZ_PB   (32 * SBNP * 4)
#define OFF_PB1 (OFF_PB0 + SZ_PB)
#define SMEM_PRE (OFF_PB1 + SZ_PB)

typedef unsigned long long u64t;

__device__ float g_pq[NN * 256];
__device__ float g_agg[NN * H];
__device__ float g_cnt[NN];
__device__ float g_delta[NN * 3];

__device__ __forceinline__ float silu_f(float v) { return v / (1.f + __expf(-v)); }

__device__ __forceinline__ float tf32r(float f) {
    uint32_t u; asm("cvt.rna.tf32.f32 %0, %1;" : "=r"(u) : "f"(f));
    return __uint_as_float(u);
}
__device__ __forceinline__ float4 tf32r4(float4 v) {
    v.x = tf32r(v.x); v.y = tf32r(v.y); v.z = tf32r(v.z); v.w = tf32r(v.w);
    return v;
}
__device__ __forceinline__ void mma_tf32(float* d, uint32_t a0, uint32_t a1, uint32_t a2,
                                         uint32_t a3, uint32_t b0, uint32_t b1) {
    asm("mma.sync.aligned.m16n8k8.row.col.f32.tf32.tf32.f32 "
        "{%0,%1,%2,%3},{%4,%5,%6,%7},{%8,%9},{%0,%1,%2,%3};"
        : "+f"(d[0]), "+f"(d[1]), "+f"(d[2]), "+f"(d[3])
        : "r"(a0), "r"(a1), "r"(a2), "r"(a3), "r"(b0), "r"(b1));
}

__device__ __forceinline__ void fma2(u64t& d, u64t a, u64t b) {
    asm("fma.rn.f32x2 %0, %1, %2, %0;" : "+l"(d) : "l"(a), "l"(b));
}
__device__ __forceinline__ u64t pack2(float lo, float hi) {
    u64t d; asm("mov.b64 %0, {%1, %2};" : "=l"(d) : "f"(lo), "f"(hi)); return d;
}
__device__ __forceinline__ float hadd2(u64t d) {
    float lo, hi; asm("mov.b64 {%0, %1}, %2;" : "=f"(lo), "=f"(hi) : "l"(d));
    return lo + hi;
}

__device__ __forceinline__ void cpasync16(uint32_t smem_dst, const void* gsrc) {
    asm volatile("cp.async.cg.shared.global [%0], [%1], 16;" :: "r"(smem_dst), "l"(gsrc));
}
#define CPASYNC_COMMIT() asm volatile("cp.async.commit_group;" ::: "memory")
#define CPASYNC_WAIT0()  asm volatile("cp.async.wait_group 0;" ::: "memory")

__device__ __forceinline__ void red_add_v4(float* gptr, float4 v) {
    asm volatile("red.global.add.v4.f32 [%0], {%1, %2, %3, %4};"
                 :: "l"(gptr), "f"(v.x), "f"(v.y), "f"(v.z), "f"(v.w) : "memory");
}

__device__ __forceinline__ void edge_scalar_body(
    float rx, float ry, float rz, float qs, float qd, float4 ea,
    float* efs_row, float* gate_out, float* unit_out)
{
    const float dist = sqrtf(rx * rx + ry * ry + rz * rz + 1e-8f);
    const float inv = 1.f / dist;
    unit_out[0] = rx * inv; unit_out[1] = ry * inv; unit_out[2] = rz * inv;

    float ca = cosf(ea.x);
    float p2 = 0.5f * (3.f * ca * ca - 1.f);
    float p3 = (5.f * ca * p2 - 2.f * ca) * (1.f / 3.f);
    float a_score = 0.25f * (1.f + fabsf(ca) + fabsf(p2) + fabsf(p3)) * ea.z;
    float cd = cosf(ea.y);
    float q2 = 0.5f * (3.f * cd * cd - 1.f);
    float q3 = (5.f * cd * q2 - 2.f * cd) * (1.f / 3.f);
    float d_score = 0.25f * (1.f + fabsf(cd) + fabsf(q2) + fabsf(q3)) * ea.w;
    float gate = fminf(fmaxf(1.f + 0.6f * (a_score + d_score), 0.35f), 2.5f);
    *gate_out = gate;

    const float gi = gate * inv;
    #pragma unroll
    for (int i = 0; i < NRAD; i++) {
        float f = (float)(i + 1) * (PI_F / 5.0f);
        efs_row[i] = tf32r(sinf(f * dist) * gi);
    }
    efs_row[16] = tf32r(dist * 0.2f * gate);
    efs_row[17] = tf32r(qs * qd * gate);
    efs_row[18] = tf32r(fabsf(qs - qd) * gate);
    #pragma unroll
    for (int i = 19; i < EFS; i++) efs_row[i] = 0.f;
}

// ================== PQ = x @ [We1a | We1b] ==================
__global__ __launch_bounds__(256) void pre_kernel(
    const float* __restrict__ x, const float* __restrict__ We1)
{
    extern __shared__ __align__(16) char dsm[];
    float* const s_x  = (float*)(dsm + OFF_X);
    float* const s_P0 = (float*)(dsm + OFF_PB0);
    float* const s_P1 = (float*)(dsm + OFF_PB1);

    const int tid = threadIdx.x;
    const int n0 = blockIdx.x * 64;
    const float4 z4 = make_float4(0.f, 0.f, 0.f, 0.f);

    for (int idx = tid; idx < 64 * 32; idx += 256) {
        const int e = idx >> 5, j4 = idx & 31;
        const int n = n0 + e;
        float4 v = (n < NN) ? tf32r4(*(const float4*)&x[n * H + j4 * 4]) : z4;
        *(float4*)&s_x[e * XS + j4 * 4] = v;
    }

    const int lane = tid & 31, w = tid >> 5;
    const int g = lane >> 2, tg = lane & 3;
    const int m0 = (w & 1) * 32;
    const int nb = (w >> 1) * 64;
    const int kk = tid >> 3, q = tid & 7;

    float d[2][8][4];
    #pragma unroll
    for (int mi = 0; mi < 2; mi++)
        #pragma unroll
        for (int t = 0; t < 8; t++)
            #pragma unroll
            for (int i = 0; i < 4; i++) d[mi][t][i] = 0.f;

    float4 ra0, ra1, ra2, ra3, rb0, rb1, rb2, rb3;
    {
        const float* sa = &We1[kk * H + q * 16];
        const float* sb = &We1[(128 + kk) * H + q * 16];
        ra0 = tf32r4(*(const float4*)(sa + 0));  ra1 = tf32r4(*(const float4*)(sa + 4));
        ra2 = tf32r4(*(const float4*)(sa + 8));  ra3 = tf32r4(*(const float4*)(sa + 12));
        rb0 = tf32r4(*(const float4*)(sb + 0));  rb1 = tf32r4(*(const float4*)(sb + 4));
        rb2 = tf32r4(*(const float4*)(sb + 8));  rb3 = tf32r4(*(const float4*)(sb + 12));
        float* dw = &s_P0[kk * SBNP];
        *(float4*)(dw + q * 16 + 0) = ra0; *(float4*)(dw + q * 16 + 4) = ra1;
        *(float4*)(dw + q * 16 + 8) = ra2; *(float4*)(dw + q * 16 + 12) = ra3;
        *(float4*)(dw + 128 + q * 16 + 0) = rb0; *(float4*)(dw + 128 + q * 16 + 4) = rb1;
        *(float4*)(dw + 128 + q * 16 + 8) = rb2; *(float4*)(dw + 128 + q * 16 + 12) = rb3;
    }
    for (int c = 0; c < 4; c++) {
        if (c < 3) {
            const int k = (c + 1) * 32 + kk;
            const float* sa = &We1[k * H + q * 16];
            const float* sb = &We1[(128 + k) * H + q * 16];
            ra0 = tf32r4(*(const float4*)(sa + 0));  ra1 = tf32r4(*(const float4*)(sa + 4));
            ra2 = tf32r4(*(const float4*)(sa + 8));  ra3 = tf32r4(*(const float4*)(sa + 12));
            rb0 = tf32r4(*(const float4*)(sb + 0));  rb1 = tf32r4(*(const float4*)(sb + 4));
            rb2 = tf32r4(*(const float4*)(sb + 8));  rb3 = tf32r4(*(const float4*)(sb + 12));
        }
        __syncthreads();
        const float* bp = (c & 1) ? s_P1 : s_P0;
        #pragma unroll
        for (int ks = 0; ks < 4; ks++) {
            const int kg = c * 32 + ks * 8, kl = ks * 8;
            uint32_t a[2][4];
            #pragma unroll
            for (int mi = 0; mi < 2; mi++) {
                const int rA = m0 + mi * 16 + g;
                a[mi][0] = __float_as_uint(s_x[rA * XS + kg + tg]);
                a[mi][1] = __float_as_uint(s_x[(rA + 8) * XS + kg + tg]);
                a[mi][2] = __float_as_uint(s_x[rA * XS + kg + 4 + tg]);
                a[mi][3] = __float_as_uint(s_x[(rA + 8) * XS + kg + 4 + tg]);
            }
            #pragma unroll
            for (int t = 0; t < 8; t++) {
                const uint32_t b0 = __float_as_uint(bp[(kl + tg) * SBNP + nb + t * 8 + g]);
                const uint32_t b1 = __float_as_uint(bp[(kl + 4 + tg) * SBNP + nb + t * 8 + g]);
                mma_tf32(d[0][t], a[0][0], a[0][1], a[0][2], a[0][3], b0, b1);
                mma_tf32(d[1][t], a[1][0], a[1][1], a[1][2], a[1][3], b0, b1);
            }
        }
        if (c < 3) {
            float* np = (c & 1) ? s_P0 : s_P1;
            float* dw = &np[kk * SBNP];
            *(float4*)(dw + q * 16 + 0) = ra0; *(float4*)(dw + q * 16 + 4) = ra1;
            *(float4*)(dw + q * 16 + 8) = ra2; *(float4*)(dw + q * 16 + 12) = ra3;
            *(float4*)(dw + 128 + q * 16 + 0) = rb0; *(float4*)(dw + 128 + q * 16 + 4) = rb1;
            *(float4*)(dw + 128 + q * 16 + 8) = rb2; *(float4*)(dw + 128 + q * 16 + 12) = rb3;
        }
    }

    #pragma unroll
    for (int mi = 0; mi < 2; mi++) {
        const int r0w = n0 + m0 + mi * 16 + g;
        #pragma unroll
        for (int t = 0; t < 8; t++) {
            const int col = nb + t * 8 + tg * 2;
            if (r0w < NN)
                *(float2*)&g_pq[r0w * 256 + col] = make_float2(d[mi][t][0], d[mi][t][1]);
            if (r0w + 8 < NN)
                *(float2*)&g_pq[(r0w + 8) * 256 + col] = make_float2(d[mi][t][2], d[mi][t][3]);
        }
    }
}

// ================== persistent edge kernel, 512 threads ==================
__global__ __launch_bounds__(THREADS) void edge_kernel(
    const float* __restrict__ pos,
    const float* __restrict__ charge, const float* __restrict__ edge_attr,
    const int* __restrict__ edge_index,
    const float* __restrict__ We1, const float* __restrict__ be1,
    const float* __restrict__ g1, const float* __restrict__ bt1,
    const float* __restrict__ We2, const float* __restrict__ be2,
    const float* __restrict__ Wc1, const float* __restrict__ bc1,
    const float* __restrict__ Wc2, const float* __restrict__ bc2)
{
    extern __shared__ __align__(16) char dsm[];
    float* const s_P   = (float*)(dsm + OFF_P);
    float* const s_Q   = (float*)(dsm + OFF_Q);
    float* const s_h   = (float*)(dsm + OFF_H2);
    float* const s_eh  = (float*)(dsm + OFF_H2);
    float* const s_W1c = (float*)(dsm + OFF_W1C);
    float* const s_W2  = (float*)(dsm + OFF_W2);
    float* const s_Wc1 = (float*)(dsm + OFF_WC1);
    float* const efs   = (float*)(dsm + OFF_EFS);

    __shared__ float s_gateb[2][TE];
    __shared__ float s_unitb[2][TE][3];
    __shared__ int   s_srcb[2][TE];
    __shared__ float s_coordb[2][TE];
    __shared__ int   s_idx2[128];

    const int tid = threadIdx.x;
    const float4 z4 = make_float4(0.f, 0.f, 0.f, 0.f);
    const uint32_t sPb = (uint32_t)__cvta_generic_to_shared(s_P);
    const uint32_t sQb = (uint32_t)__cvta_generic_to_shared(s_Q);

    // ---- stage ALL weights once (tf32) ----
    for (int idx = tid; idx < 24 * 32; idx += THREADS) {
        const int r = idx >> 5, c4 = (idx & 31) * 4;
        float4 v = (r < 19) ? tf32r4(*(const float4*)&We1[(256 + r) * H + c4]) : z4;
        *(float4*)&s_W1c[r * SBN + c4] = v;
    }
    for (int idx = tid; idx < 128 * 32; idx += THREADS) {
        const int r = idx >> 5, c4 = (idx & 31) * 4;
        *(float4*)&s_W2[r * SBN + c4] = tf32r4(*(const float4*)&We2[r * H + c4]);
    }
    for (int idx = tid; idx < 128 * 16; idx += THREADS) {
        const int r = idx >> 4, c4 = (idx & 15) * 4;
        *(float4*)&s_Wc1[r * SBN3 + c4] = tf32r4(*(const float4*)&Wc1[r * 64 + c4]);
    }

    const int lane = tid & 31, w = tid >> 5;       // 16 warps
    const int g = lane >> 2, tg = lane & 3;
    const int m0 = (w & 3) * 16;                   // 4 m-tiles
    const int ng = w >> 2;                         // 4 n-groups
    const int nb = ng * 32;
    const int nb3 = ng * 16;

    float ln_g[4], ln_b[4];
    ln_g[0] = g1[lane]; ln_g[1] = g1[lane + 32]; ln_g[2] = g1[lane + 64]; ln_g[3] = g1[lane + 96];
    ln_b[0] = bt1[lane]; ln_b[1] = bt1[lane + 32]; ln_b[2] = bt1[lane + 64]; ln_b[3] = bt1[lane + 96];
    float be1v[4][2], be2v[4][2];
    #pragma unroll
    for (int t = 0; t < 4; t++) {
        const int col = nb + t * 8 + tg * 2;
        be1v[t][0] = be1[col]; be1v[t][1] = be1[col + 1];
        be2v[t][0] = be2[col]; be2v[t][1] = be2[col + 1];
    }
    float wc2v[2][2], bc1v[2][2];
    #pragma unroll
    for (int t = 0; t < 2; t++) {
        const int col = nb3 + t * 8 + tg * 2;
        wc2v[t][0] = Wc2[col]; wc2v[t][1] = Wc2[col + 1];
        bc1v[t][0] = bc1[col]; bc1v[t][1] = bc1[col + 1];
    }
    const float bc2v = bc2[0];

    // ---- prologue: tile 0 scalars + gather ----
    {
        const int e0p = blockIdx.x * TE;
        if (tid < TE) {
            const int e = e0p + tid;
            const int src = edge_index[e];
            const int dst = edge_index[NE + e];
            s_srcb[0][tid] = src;
            const float rx = pos[dst * 3 + 0] - pos[src * 3 + 0];
            const float ry = pos[dst * 3 + 1] - pos[src * 3 + 1];
            const float rz = pos[dst * 3 + 2] - pos[src * 3 + 2];
            edge_scalar_body(rx, ry, rz, charge[src], charge[dst],
                             *(const float4*)&edge_attr[e * 4],
                             &efs[tid * EFS], &s_gateb[0][tid], &s_unitb[0][tid][0]);
            s_coordb[0][tid] = bc2v;
        }
        for (int idx = tid; idx < TE * 32; idx += THREADS) {
            const int e = idx >> 5, j4 = idx & 31;
            const int src = edge_index[e0p + e];
            const int dst = edge_index[NE + e0p + e];
            *(float4*)&s_P[e * HS + j4 * 4] = *(const float4*)&g_pq[src * 256 + j4 * 4];
            *(float4*)&s_Q[e * HS + j4 * 4] = *(const float4*)&g_pq[dst * 256 + 128 + j4 * 4];
        }
    }

    int p = 0;
    for (int tile = blockIdx.x; tile < NTILES; tile += GRID_EDGE, p ^= 1) {
        const int np = p ^ 1;
        const int nt = tile + GRID_EDGE;
        const bool has_next = (nt < NTILES);

        int ni = 0, ndsti = 0;
        if (has_next) {
            if (tid < 128) {
                const int off = (tid < 64) ? (nt * TE + tid) : (NE + nt * TE + (tid - 64));
                ni = edge_index[off];
            }
            if (tid < 64) ndsti = edge_index[NE + nt * TE + tid];
        }

        CPASYNC_WAIT0();
        __syncthreads();     // A

        // ---- GEMM1-small + epilogue1 -> s_h ----
        float d[4][4];
        #pragma unroll
        for (int t = 0; t < 4; t++)
            #pragma unroll
            for (int i = 0; i < 4; i++) d[t][i] = 0.f;
        #pragma unroll
        for (int ks = 0; ks < 3; ks++) {
            const int kg = ks * 8;
            const int rA = m0 + g;
            const uint32_t a0 = __float_as_uint(efs[rA * EFS + kg + tg]);
            const uint32_t a1 = __float_as_uint(efs[(rA + 8) * EFS + kg + tg]);
            const uint32_t a2 = __float_as_uint(efs[rA * EFS + kg + 4 + tg]);
            const uint32_t a3 = __float_as_uint(efs[(rA + 8) * EFS + kg + 4 + tg]);
            #pragma unroll
            for (int t = 0; t < 4; t++) {
                const uint32_t b0 = __float_as_uint(s_W1c[(kg + tg) * SBN + nb + t * 8 + g]);
                const uint32_t b1 = __float_as_uint(s_W1c[(kg + 4 + tg) * SBN + nb + t * 8 + g]);
                mma_tf32(d[t], a0, a1, a2, a3, b0, b1);
            }
        }
        #pragma unroll
        for (int t = 0; t < 4; t++) {
            const int col = nb + t * 8 + tg * 2;
            const int rA = m0 + g;
            s_h[rA * HS + col] =
                silu_f(d[t][0] + s_P[rA * HS + col] + s_Q[rA * HS + col] + be1v[t][0]);
            s_h[rA * HS + col + 1] =
                silu_f(d[t][1] + s_P[rA * HS + col + 1] + s_Q[rA * HS + col + 1] + be1v[t][1]);
            s_h[(rA + 8) * HS + col] =
                silu_f(d[t][2] + s_P[(rA + 8) * HS + col] + s_Q[(rA + 8) * HS + col] + be1v[t][0]);
            s_h[(rA + 8) * HS + col + 1] =
                silu_f(d[t][3] + s_P[(rA + 8) * HS + col + 1] + s_Q[(rA + 8) * HS + col + 1] + be1v[t][1]);
        }
        __syncthreads();     // B

        float psx = 0.f, psy = 0.f, psz = 0.f, pdx = 0.f, pdy = 0.f, pdz = 0.f;
        float qsv = 0.f, qdv = 0.f;
        float4 nea = z4;
        if (has_next && tid < 64) {
            psx = pos[ni * 3 + 0]; psy = pos[ni * 3 + 1]; psz = pos[ni * 3 + 2];
            pdx = pos[ndsti * 3 + 0]; pdy = pos[ndsti * 3 + 1]; pdz = pos[ndsti * 3 + 2];
            qsv = charge[ni]; qdv = charge[ndsti];
            nea = *(const float4*)&edge_attr[(nt * TE + tid) * 4];
        }

        // ---- LayerNorm(h): warp per 4 edges ----
        #pragma unroll
        for (int qq = 0; qq < 4; qq++) {
            const int e = w * 4 + qq;
            float v0 = s_h[e * HS + lane], v1 = s_h[e * HS + lane + 32];
            float v2 = s_h[e * HS + lane + 64], v3 = s_h[e * HS + lane + 96];
            float s1 = v0 + v1 + v2 + v3;
            float s2 = v0 * v0 + v1 * v1 + v2 * v2 + v3 * v3;
            #pragma unroll
            for (int o = 16; o; o >>= 1) {
                s1 += __shfl_xor_sync(0xffffffffu, s1, o);
                s2 += __shfl_xor_sync(0xffffffffu, s2, o);
            }
            const float m = s1 * (1.f / 128.f);
            const float var = s2 * (1.f / 128.f) - m * m;
            const float rstd = rsqrtf(var + 1e-5f);
            s_h[e * HS + lane]      = tf32r((v0 - m) * rstd * ln_g[0] + ln_b[0]);
            s_h[e * HS + lane + 32] = tf32r((v1 - m) * rstd * ln_g[1] + ln_b[1]);
            s_h[e * HS + lane + 64] = tf32r((v2 - m) * rstd * ln_g[2] + ln_b[2]);
            s_h[e * HS + lane + 96] = tf32r((v3 - m) * rstd * ln_g[3] + ln_b[3]);
        }
        __syncthreads();     // C

        if (has_next && tid < 128) s_idx2[tid] = ni;

        // ---- GEMM2: h @ We2 ----
        #pragma unroll
        for (int t = 0; t < 4; t++)
            #pragma unroll
            for (int i = 0; i < 4; i++) d[t][i] = 0.f;
        #pragma unroll 4
        for (int ks = 0; ks < 16; ks++) {
            const int kg = ks * 8;
            const int rA = m0 + g;
            const uint32_t a0 = __float_as_uint(s_h[rA * HS + kg + tg]);
            const uint32_t a1 = __float_as_uint(s_h[(rA + 8) * HS + kg + tg]);
            const uint32_t a2 = __float_as_uint(s_h[rA * HS + kg + 4 + tg]);
            const uint32_t a3 = __float_as_uint(s_h[(rA + 8) * HS + kg + 4 + tg]);
            #pragma unroll
            for (int t = 0; t < 4; t++) {
                const uint32_t b0 = __float_as_uint(s_W2[(kg + tg) * SBN + nb + t * 8 + g]);
                const uint32_t b1 = __float_as_uint(s_W2[(kg + 4 + tg) * SBN + nb + t * 8 + g]);
                mma_tf32(d[t], a0, a1, a2, a3, b0, b1);
            }
        }
        __syncthreads();     // D

        // ---- epilogue2: eh = silu(+be2) -> s_eh ----
        #pragma unroll
        for (int t = 0; t < 4; t++) {
            const int col = nb + t * 8 + tg * 2;
            const int rA = m0 + g;
            s_eh[rA * HS + col]           = tf32r(silu_f(d[t][0] + be2v[t][0]));
            s_eh[rA * HS + col + 1]       = tf32r(silu_f(d[t][1] + be2v[t][1]));
            s_eh[(rA + 8) * HS + col]     = tf32r(silu_f(d[t][2] + be2v[t][0]));
            s_eh[(rA + 8) * HS + col + 1] = tf32r(silu_f(d[t][3] + be2v[t][1]));
        }

        // ---- pipelined prefetch for next tile ----
        if (has_next) {
            #pragma unroll
            for (int k = 0; k < 4; k++) {
                const int idx = tid + k * THREADS;
                const int e = idx >> 5, j4 = idx & 31;
                const int se = s_idx2[e];
                const int de = s_idx2[64 + e];
                cpasync16(sPb + e * (HS * 4) + j4 * 16,
                          (const char*)g_pq + (size_t)se * 1024 + (size_t)j4 * 16);
                cpasync16(sQb + e * (HS * 4) + j4 * 16,
                          (const char*)g_pq + (size_t)de * 1024 + 512 + (size_t)j4 * 16);
            }
            CPASYNC_COMMIT();
            if (tid < 64) {
                edge_scalar_body(pdx - psx, pdy - psy, pdz - psz, qsv, qdv, nea,
                                 &efs[tid * EFS], &s_gateb[np][tid], &s_unitb[np][tid][0]);
                s_srcb[np][tid] = ni;
                s_coordb[np][tid] = bc2v;
            }
        }
        __syncthreads();     // E

        // ---- agg scatter FIRST (fire-and-forget v4 REDs overlap GEMM3) ----
        #pragma unroll
        for (int k = 0; k < 4; k++) {
            const int idx = tid + k * THREADS;
            const int e = idx >> 5, j4 = idx & 31;
            const float4 v = *(const float4*)&s_eh[e * HS + j4 * 4];
            red_add_v4(&g_agg[s_srcb[p][e] * H + j4 * 4], v);
        }

        // ---- GEMM3: eh @ Wc1 + coord epilogue ----
        float d3[2][4];
        #pragma unroll
        for (int t = 0; t < 2; t++)
            #pragma unroll
            for (int i = 0; i < 4; i++) d3[t][i] = 0.f;
        #pragma unroll 4
        for (int ks = 0; ks < 16; ks++) {
            const int kg = ks * 8;
            const int rA = m0 + g;
            const uint32_t a0 = __float_as_uint(s_eh[rA * HS + kg + tg]);
            const uint32_t a1 = __float_as_uint(s_eh[(rA + 8) * HS + kg + tg]);
            const uint32_t a2 = __float_as_uint(s_eh[rA * HS + kg + 4 + tg]);
            const uint32_t a3 = __float_as_uint(s_eh[(rA + 8) * HS + kg + 4 + tg]);
            #pragma unroll
            for (int t = 0; t < 2; t++) {
                const uint32_t b0 = __float_as_uint(s_Wc1[(kg + tg) * SBN3 + nb3 + t * 8 + g]);
                const uint32_t b1 = __float_as_uint(s_Wc1[(kg + 4 + tg) * SBN3 + nb3 + t * 8 + g]);
                mma_tf32(d3[t], a0, a1, a2, a3, b0, b1);
            }
        }
        {
            float sA = 0.f, sB2 = 0.f;
            #pragma unroll
            for (int t = 0; t < 2; t++) {
                sA  += silu_f(d3[t][0] + bc1v[t][0]) * wc2v[t][0]
                     + silu_f(d3[t][1] + bc1v[t][1]) * wc2v[t][1];
                sB2 += silu_f(d3[t][2] + bc1v[t][0]) * wc2v[t][0]
                     + silu_f(d3[t][3] + bc1v[t][1]) * wc2v[t][1];
            }
            const int rA = m0 + g;
            atomicAdd(&s_coordb[p][rA], sA);
            atomicAdd(&s_coordb[p][rA + 8], sB2);
        }
        __syncthreads();     // F

        // ---- cnt/delta scatter ----
        if (tid < TE) {
            const int src = s_srcb[p][tid];
            const float f = s_coordb[p][tid] * s_gateb[p][tid];
            atomicAdd(&g_cnt[src], 1.0f);
            atomicAdd(&g_delta[src * 3 + 0], s_unitb[p][tid][0] * f);
            atomicAdd(&g_delta[src * 3 + 1], s_unitb[p][tid][1] * f);
            atomicAdd(&g_delta[src * 3 + 2], s_unitb[p][tid][2] * f);
        }
        // next-iter barrier A separates smem reuse
    }
}

__global__ __launch_bounds__(256) void node_kernel(
    const float* __restrict__ x, const float* __restrict__ pos,
    const float* __restrict__ Wn, const float* __restrict__ bn,
    const float* __restrict__ gn, const float* __restrict__ btn,
    float* __restrict__ out)
{
    __shared__ __align__(16) float s_cat[TN * 260];
    const int tid = threadIdx.x;
    const int n0 = blockIdx.x * TN;

    for (int idx = tid; idx < TN * 64; idx += 256) {
        const int nl = idx >> 6, j4 = idx & 63;
        const int n = n0 + nl;
        float4 v = make_float4(0.f, 0.f, 0.f, 0.f);
        if (n < NN) {
            if (j4 < 32) {
                v = *(const float4*)&x[n * H + j4 * 4];
            } else {
                const float c = fmaxf(g_cnt[n], 1.f);
                const float iv = 1.f / c;
                v = *(const float4*)&g_agg[n * H + (j4 - 32) * 4];
                v.x *= iv; v.y *= iv; v.z *= iv; v.w *= iv;
            }
        }
        *(float4*)&s_cat[nl * 260 + j4 * 4] = v;
    }
    __syncthreads();

    const int jj = tid & 63, g = tid >> 6;
    const int nbv = g * 8;
    u64t accA[8], accB[8];
    #pragma unroll
    for (int e = 0; e < 8; e++) { accA[e] = 0ull; accB[e] = 0ull; }
    for (int k = 0; k < 256; k += 4) {
        const float wA0 = Wn[(k + 0) * H + jj],      wA1 = Wn[(k + 1) * H + jj];
        const float wA2 = Wn[(k + 2) * H + jj],      wA3 = Wn[(k + 3) * H + jj];
        const float wB0 = Wn[(k + 0) * H + jj + 64], wB1 = Wn[(k + 1) * H + jj + 64];
        const float wB2 = Wn[(k + 2) * H + jj + 64], wB3 = Wn[(k + 3) * H + jj + 64];
        const u64t pA0 = pack2(wA0, wA1), pA1 = pack2(wA2, wA3);
        const u64t pB0 = pack2(wB0, wB1), pB1 = pack2(wB2, wB3);
        #pragma unroll
        for (int e = 0; e < 8; e++) {
            const ulonglong2 v = *(const ulonglong2*)&s_cat[(nbv + e) * 260 + k];
            fma2(accA[e], v.x, pA0); fma2(accA[e], v.y, pA1);
            fma2(accB[e], v.x, pB0); fma2(accB[e], v.y, pB1);
        }
    }
    const float bA = bn[jj], bB = bn[jj + 64];
    __syncthreads();
    float* const s_y = s_cat;
    #pragma unroll
    for (int e = 0; e < 8; e++) {
        s_y[(nbv + e) * H + jj]      = silu_f(hadd2(accA[e]) + bA);
        s_y[(nbv + e) * H + jj + 64] = silu_f(hadd2(accB[e]) + bB);
    }
    __syncthreads();

    const int lane = tid & 31, wrp = tid >> 5;
    const float ga = gn[lane], gb = gn[lane + 32], gc = gn[lane + 64], gd = gn[lane + 96];
    const float ba = btn[lane], bb = btn[lane + 32], bcv = btn[lane + 64], bd = btn[lane + 96];
    #pragma unroll
    for (int qq = 0; qq < 4; qq++) {
        const int nl = wrp * 4 + qq;
        const int n = n0 + nl;
        float v0 = s_y[nl * H + lane], v1 = s_y[nl * H + lane + 32];
        float v2 = s_y[nl * H + lane + 64], v3 = s_y[nl * H + lane + 96];
        float s1 = v0 + v1 + v2 + v3;
        float s2 = v0 * v0 + v1 * v1 + v2 * v2 + v3 * v3;
        #pragma unroll
        for (int o = 16; o; o >>= 1) {
            s1 += __shfl_xor_sync(0xffffffffu, s1, o);
            s2 += __shfl_xor_sync(0xffffffffu, s2, o);
        }
        const float m = s1 * (1.f / 128.f);
        const float var = s2 * (1.f / 128.f) - m * m;
        const float rstd = rsqrtf(var + 1e-5f);
        if (n < NN) {
            out[n * H + lane]      = x[n * H + lane]      + (v0 - m) * rstd * ga + ba;
            out[n * H + lane + 32] = x[n * H + lane + 32] + (v1 - m) * rstd * gb + bb;
            out[n * H + lane + 64] = x[n * H + lane + 64] + (v2 - m) * rstd * gc + bcv;
            out[n * H + lane + 96] = x[n * H + lane + 96] + (v3 - m) * rstd * gd + bd;
        }
    }
    if (tid < TN) {
        const int n = n0 + tid;
        if (n < NN) {
            const float c = fmaxf(g_cnt[n], 1.f);
            const float s = 0.1f / c;
            out[NN * H + n * 3 + 0] = pos[n * 3 + 0] + s * g_delta[n * 3 + 0];
            out[NN * H + n * 3 + 1] = pos[n * 3 + 1] + s * g_delta[n * 3 + 1];
            out[NN * H + n * 3 + 2] = pos[n * 3 + 2] + s * g_delta[n * 3 + 2];
        }
    }

    // ---- re-zero scratch for next launch ----
    __syncthreads();
    const float4 z4 = make_float4(0.f, 0.f, 0.f, 0.f);
    for (int idx = tid; idx < TN * 32; idx += 256) {
        const int nl = idx >> 5, j4 = idx & 31;
        const int n = n0 + nl;
        if (n < NN) *(float4*)&g_agg[n * H + j4 * 4] = z4;
    }
    if (tid < TN) {
        const int n = n0 + tid;
        if (n < NN) {
            g_cnt[n] = 0.f;
            g_delta[n * 3 + 0] = 0.f;
            g_delta[n * 3 + 1] = 0.f;
            g_delta[n * 3 + 2] = 0.f;
        }
    }
}

extern "C" void kernel_launch(void* const* d_in, const int* in_sizes, int n_in,
                              void* d_out, int out_size) {
    const float* x         = (const float*)d_in[0];
    const float* pos       = (const float*)d_in[1];
    const float* charge    = (const float*)d_in[2];
    const float* edge_attr = (const float*)d_in[3];
    const int*   edge_index= (const int*)d_in[4];
    const float* We1 = (const float*)d_in[5];
    const float* be1 = (const float*)d_in[6];
    const float* g1  = (const float*)d_in[7];
    const float* bt1 = (const float*)d_in[8];
    const float* We2 = (const float*)d_in[9];
    const float* be2 = (const float*)d_in[10];
    const float* Wn  = (const float*)d_in[11];
    const float* bn  = (const float*)d_in[12];
    const float* gn  = (const float*)d_in[13];
    const float* btn = (const float*)d_in[14];
    const float* Wc1 = (const float*)d_in[15];
    const float* bc1 = (const float*)d_in[16];
    const float* Wc2 = (const float*)d_in[17];
    const float* bc2 = (const float*)d_in[18];
    float* out = (float*)d_out;

    cudaFuncSetAttribute(pre_kernel, cudaFuncAttributeMaxDynamicSharedMemorySize, SMEM_PRE);
    cudaFuncSetAttribute(edge_kernel, cudaFuncAttributeMaxDynamicSharedMemorySize, SMEM_EDGE);

    pre_kernel<<<(NN + 63) / 64, 256, SMEM_PRE>>>(x, We1);
    edge_kernel<<<GRID_EDGE, THREADS, SMEM_EDGE>>>(pos, charge, edge_attr, edge_index,
                                                   We1, be1, g1, bt1, We2, be2, Wc1, bc1, Wc2, bc2);
    node_kernel<<<(NN + TN - 1) / TN, 256>>>(x, pos, Wn, bn, gn, btn, out);
}

// round 16
// speedup vs baseline: 2.1796x; 1.0180x over previous
#include <cuda_runtime.h>
#include <math.h>
#include <stdint.h>

#define NN 50000
#define NE 800000
#define H 128
#define NRAD 16
#define TE 64              // edges per tile
#define TN 32
#define NTILES (NE / TE)   // 12500
#define GRID_EDGE 148
#define THREADS 512        // 16 warps: 4 m-tiles x 4 n-blocks
#define HS  132            // P/Q/h/eh row stride (floats)
#define SK2 132            // W2T row stride  [n=128][k=128]
#define SK3 132            // Wc1T row stride [n=64][k=128]
#define SK1 28             // W1cT row stride [n=128][k=28 pad]
#define EFS 28             // small-feature row stride (19 used; 112B -> LDSM conflict-free)
#define PI_F 3.14159265358979f

// ---- persistent edge kernel dynamic smem layout (bytes) ----
#define SZ_T    (TE * HS * 4)               // 33792
#define OFF_P   0
#define OFF_Q   (OFF_P + SZ_T)              // 33792
#define OFF_H2  (OFF_Q + SZ_T)              // 67584 (h; eh overlays)
#define OFF_W1C (OFF_H2 + SZ_T)             // 101376
#define SZ_W1C  (128 * SK1 * 4)             // 14336
#define OFF_W2  (OFF_W1C + SZ_W1C)          // 115712
#define SZ_W2   (128 * SK2 * 4)             // 67584
#define OFF_WC1 (OFF_W2 + SZ_W2)            // 183296
#define SZ_WC1  (64 * SK3 * 4)              // 33792
#define OFF_EFS (OFF_WC1 + SZ_WC1)          // 217088
#define SZ_EFS  (TE * EFS * 4)              // 7168
#define SMEM_EDGE (OFF_EFS + SZ_EFS)        // 224256

// ---- pre kernel smem ----
#define XS 132
#define SBNP 264
#define OFF_X   0
#define SZ_X    (64 * XS * 4)
#define OFF_PB0 (OFF_X + SZ_X)
#define SZ_PB   (32 * SBNP * 4)
#define OFF_PB1 (OFF_PB0 + SZ_PB)
#define SMEM_PRE (OFF_PB1 + SZ_PB)

typedef unsigned long long u64t;

__device__ float g_pq[NN * 256];
__device__ float g_agg[NN * H];
__device__ float g_cnt[NN];
__device__ float g_delta[NN * 3];

__device__ __forceinline__ float silu_f(float v) { return v / (1.f + __expf(-v)); }

__device__ __forceinline__ float tf32r(float f) {
    uint32_t u; asm("cvt.rna.tf32.f32 %0, %1;" : "=r"(u) : "f"(f));
    return __uint_as_float(u);
}
__device__ __forceinline__ float4 tf32r4(float4 v) {
    v.x = tf32r(v.x); v.y = tf32r(v.y); v.z = tf32r(v.z); v.w = tf32r(v.w);
    return v;
}
__device__ __forceinline__ void mma_tf32(float* d, uint32_t a0, uint32_t a1, uint32_t a2,
                                         uint32_t a3, uint32_t b0, uint32_t b1) {
    asm("mma.sync.aligned.m16n8k8.row.col.f32.tf32.tf32.f32 "
        "{%0,%1,%2,%3},{%4,%5,%6,%7},{%8,%9},{%0,%1,%2,%3};"
        : "+f"(d[0]), "+f"(d[1]), "+f"(d[2]), "+f"(d[3])
        : "r"(a0), "r"(a1), "r"(a2), "r"(a3), "r"(b0), "r"(b1));
}
__device__ __forceinline__ void ldsm4(uint32_t& r0, uint32_t& r1, uint32_t& r2, uint32_t& r3,
                                      uint32_t addr) {
    asm volatile("ldmatrix.sync.aligned.m8n8.x4.shared.b16 {%0,%1,%2,%3}, [%4];"
                 : "=r"(r0), "=r"(r1), "=r"(r2), "=r"(r3) : "r"(addr));
}

__device__ __forceinline__ void fma2(u64t& d, u64t a, u64t b) {
    asm("fma.rn.f32x2 %0, %1, %2, %0;" : "+l"(d) : "l"(a), "l"(b));
}
__device__ __forceinline__ u64t pack2(float lo, float hi) {
    u64t d; asm("mov.b64 %0, {%1, %2};" : "=l"(d) : "f"(lo), "f"(hi)); return d;
}
__device__ __forceinline__ float hadd2(u64t d) {
    float lo, hi; asm("mov.b64 {%0, %1}, %2;" : "=f"(lo), "=f"(hi) : "l"(d));
    return lo + hi;
}

__device__ __forceinline__ void cpasync16(uint32_t smem_dst, const void* gsrc) {
    asm volatile("cp.async.cg.shared.global [%0], [%1], 16;" :: "r"(smem_dst), "l"(gsrc));
}
#define CPASYNC_COMMIT() asm volatile("cp.async.commit_group;" ::: "memory")
#define CPASYNC_WAIT0()  asm volatile("cp.async.wait_group 0;" ::: "memory")

__device__ __forceinline__ void red_add_v4(float* gptr, float4 v) {
    asm volatile("red.global.add.v4.f32 [%0], {%1, %2, %3, %4};"
                 :: "l"(gptr), "f"(v.x), "f"(v.y), "f"(v.z), "f"(v.w) : "memory");
}

__device__ __forceinline__ void edge_scalar_body(
    float rx, float ry, float rz, float qs, float qd, float4 ea,
    float* efs_row, float* gate_out, float* unit_out)
{
    const float dist = sqrtf(rx * rx + ry * ry + rz * rz + 1e-8f);
    const float inv = 1.f / dist;
    unit_out[0] = rx * inv; unit_out[1] = ry * inv; unit_out[2] = rz * inv;

    float ca = cosf(ea.x);
    float p2 = 0.5f * (3.f * ca * ca - 1.f);
    float p3 = (5.f * ca * p2 - 2.f * ca) * (1.f / 3.f);
    float a_score = 0.25f * (1.f + fabsf(ca) + fabsf(p2) + fabsf(p3)) * ea.z;
    float cd = cosf(ea.y);
    float q2 = 0.5f * (3.f * cd * cd - 1.f);
    float q3 = (5.f * cd * q2 - 2.f * cd) * (1.f / 3.f);
    float d_score = 0.25f * (1.f + fabsf(cd) + fabsf(q2) + fabsf(q3)) * ea.w;
    float gate = fminf(fmaxf(1.f + 0.6f * (a_score + d_score), 0.35f), 2.5f);
    *gate_out = gate;

    const float gi = gate * inv;
    #pragma unroll
    for (int i = 0; i < NRAD; i++) {
        float f = (float)(i + 1) * (PI_F / 5.0f);
        efs_row[i] = tf32r(sinf(f * dist) * gi);
    }
    efs_row[16] = tf32r(dist * 0.2f * gate);
    efs_row[17] = tf32r(qs * qd * gate);
    efs_row[18] = tf32r(fabsf(qs - qd) * gate);
    #pragma unroll
    for (int i = 19; i < EFS; i++) efs_row[i] = 0.f;
}

// ================== PQ = x @ [We1a | We1b] ==================
__global__ __launch_bounds__(256) void pre_kernel(
    const float* __restrict__ x, const float* __restrict__ We1)
{
    extern __shared__ __align__(16) char dsm[];
    float* const s_x  = (float*)(dsm + OFF_X);
    float* const s_P0 = (float*)(dsm + OFF_PB0);
    float* const s_P1 = (float*)(dsm + OFF_PB1);

    const int tid = threadIdx.x;
    const int n0 = blockIdx.x * 64;
    const float4 z4 = make_float4(0.f, 0.f, 0.f, 0.f);

    for (int idx = tid; idx < 64 * 32; idx += 256) {
        const int e = idx >> 5, j4 = idx & 31;
        const int n = n0 + e;
        float4 v = (n < NN) ? tf32r4(*(const float4*)&x[n * H + j4 * 4]) : z4;
        *(float4*)&s_x[e * XS + j4 * 4] = v;
    }

    const int lane = tid & 31, w = tid >> 5;
    const int g = lane >> 2, tg = lane & 3;
    const int m0 = (w & 1) * 32;
    const int nb = (w >> 1) * 64;
    const int kk = tid >> 3, q = tid & 7;

    float d[2][8][4];
    #pragma unroll
    for (int mi = 0; mi < 2; mi++)
        #pragma unroll
        for (int t = 0; t < 8; t++)
            #pragma unroll
            for (int i = 0; i < 4; i++) d[mi][t][i] = 0.f;

    float4 ra0, ra1, ra2, ra3, rb0, rb1, rb2, rb3;
    {
        const float* sa = &We1[kk * H + q * 16];
        const float* sb = &We1[(128 + kk) * H + q * 16];
        ra0 = tf32r4(*(const float4*)(sa + 0));  ra1 = tf32r4(*(const float4*)(sa + 4));
        ra2 = tf32r4(*(const float4*)(sa + 8));  ra3 = tf32r4(*(const float4*)(sa + 12));
        rb0 = tf32r4(*(const float4*)(sb + 0));  rb1 = tf32r4(*(const float4*)(sb + 4));
        rb2 = tf32r4(*(const float4*)(sb + 8));  rb3 = tf32r4(*(const float4*)(sb + 12));
        float* dw = &s_P0[kk * SBNP];
        *(float4*)(dw + q * 16 + 0) = ra0; *(float4*)(dw + q * 16 + 4) = ra1;
        *(float4*)(dw + q * 16 + 8) = ra2; *(float4*)(dw + q * 16 + 12) = ra3;
        *(float4*)(dw + 128 + q * 16 + 0) = rb0; *(float4*)(dw + 128 + q * 16 + 4) = rb1;
        *(float4*)(dw + 128 + q * 16 + 8) = rb2; *(float4*)(dw + 128 + q * 16 + 12) = rb3;
    }
    for (int c = 0; c < 4; c++) {
        if (c < 3) {
            const int k = (c + 1) * 32 + kk;
            const float* sa = &We1[k * H + q * 16];
            const float* sb = &We1[(128 + k) * H + q * 16];
            ra0 = tf32r4(*(const float4*)(sa + 0));  ra1 = tf32r4(*(const float4*)(sa + 4));
            ra2 = tf32r4(*(const float4*)(sa + 8));  ra3 = tf32r4(*(const float4*)(sa + 12));
            rb0 = tf32r4(*(const float4*)(sb + 0));  rb1 = tf32r4(*(const float4*)(sb + 4));
            rb2 = tf32r4(*(const float4*)(sb + 8));  rb3 = tf32r4(*(const float4*)(sb + 12));
        }
        __syncthreads();
        const float* bp = (c & 1) ? s_P1 : s_P0;
        #pragma unroll
        for (int ks = 0; ks < 4; ks++) {
            const int kg = c * 32 + ks * 8, kl = ks * 8;
            uint32_t a[2][4];
            #pragma unroll
            for (int mi = 0; mi < 2; mi++) {
                const int rA = m0 + mi * 16 + g;
                a[mi][0] = __float_as_uint(s_x[rA * XS + kg + tg]);
                a[mi][1] = __float_as_uint(s_x[(rA + 8) * XS + kg + tg]);
                a[mi][2] = __float_as_uint(s_x[rA * XS + kg + 4 + tg]);
                a[mi][3] = __float_as_uint(s_x[(rA + 8) * XS + kg + 4 + tg]);
            }
            #pragma unroll
            for (int t = 0; t < 8; t++) {
                const uint32_t b0 = __float_as_uint(bp[(kl + tg) * SBNP + nb + t * 8 + g]);
                const uint32_t b1 = __float_as_uint(bp[(kl + 4 + tg) * SBNP + nb + t * 8 + g]);
                mma_tf32(d[0][t], a[0][0], a[0][1], a[0][2], a[0][3], b0, b1);
                mma_tf32(d[1][t], a[1][0], a[1][1], a[1][2], a[1][3], b0, b1);
            }
        }
        if (c < 3) {
            float* np = (c & 1) ? s_P0 : s_P1;
            float* dw = &np[kk * SBNP];
            *(float4*)(dw + q * 16 + 0) = ra0; *(float4*)(dw + q * 16 + 4) = ra1;
            *(float4*)(dw + q * 16 + 8) = ra2; *(float4*)(dw + q * 16 + 12) = ra3;
            *(float4*)(dw + 128 + q * 16 + 0) = rb0; *(float4*)(dw + 128 + q * 16 + 4) = rb1;
            *(float4*)(dw + 128 + q * 16 + 8) = rb2; *(float4*)(dw + 128 + q * 16 + 12) = rb3;
        }
    }

    #pragma unroll
    for (int mi = 0; mi < 2; mi++) {
        const int r0w = n0 + m0 + mi * 16 + g;
        #pragma unroll
        for (int t = 0; t < 8; t++) {
            const int col = nb + t * 8 + tg * 2;
            if (r0w < NN)
                *(float2*)&g_pq[r0w * 256 + col] = make_float2(d[mi][t][0], d[mi][t][1]);
            if (r0w + 8 < NN)
                *(float2*)&g_pq[(r0w + 8) * 256 + col] = make_float2(d[mi][t][2], d[mi][t][3]);
        }
    }
}

// ================== persistent edge kernel, 512 threads, LDSM fragments ==================
__global__ __launch_bounds__(THREADS) void edge_kernel(
    const float* __restrict__ pos,
    const float* __restrict__ charge, const float* __restrict__ edge_attr,
    const int* __restrict__ edge_index,
    const float* __restrict__ We1, const float* __restrict__ be1,
    const float* __restrict__ g1, const float* __restrict__ bt1,
    const float* __restrict__ We2, const float* __restrict__ be2,
    const float* __restrict__ Wc1, const float* __restrict__ bc1,
    const float* __restrict__ Wc2, const float* __restrict__ bc2)
{
    extern __shared__ __align__(16) char dsm[];
    float* const s_P    = (float*)(dsm + OFF_P);
    float* const s_Q    = (float*)(dsm + OFF_Q);
    float* const s_h    = (float*)(dsm + OFF_H2);
    float* const s_eh   = (float*)(dsm + OFF_H2);
    float* const s_W1cT = (float*)(dsm + OFF_W1C);   // [128][28] n-major
    float* const s_W2T  = (float*)(dsm + OFF_W2);    // [128][132] n-major
    float* const s_Wc1T = (float*)(dsm + OFF_WC1);   // [64][132] n-major
    float* const efs    = (float*)(dsm + OFF_EFS);   // [64][28]

    __shared__ float s_gateb[2][TE];
    __shared__ float s_unitb[2][TE][3];
    __shared__ int   s_srcb[2][TE];
    __shared__ float s_coordb[2][TE];
    __shared__ int   s_idx2[128];

    const int tid = threadIdx.x;
    const float4 z4 = make_float4(0.f, 0.f, 0.f, 0.f);
    const uint32_t sPb   = (uint32_t)__cvta_generic_to_shared(s_P);
    const uint32_t sQb   = (uint32_t)__cvta_generic_to_shared(s_Q);
    const uint32_t sHb   = (uint32_t)__cvta_generic_to_shared(s_h);
    const uint32_t sW1b  = (uint32_t)__cvta_generic_to_shared(s_W1cT);
    const uint32_t sW2b  = (uint32_t)__cvta_generic_to_shared(s_W2T);
    const uint32_t sWc1b = (uint32_t)__cvta_generic_to_shared(s_Wc1T);
    const uint32_t sEfsb = (uint32_t)__cvta_generic_to_shared(efs);

    // ---- stage weights once, TRANSPOSED to n-major (tf32) ----
    for (int idx = tid; idx < 128 * SK1; idx += THREADS)   // zero W1cT incl. pad rows
        s_W1cT[idx] = 0.f;
    __syncthreads();
    for (int idx = tid; idx < 19 * 32; idx += THREADS) {   // We1 rows 256..274 -> [n][k]
        const int k = idx >> 5, n4 = (idx & 31) * 4;
        const float4 v = tf32r4(*(const float4*)&We1[(256 + k) * H + n4]);
        s_W1cT[(n4 + 0) * SK1 + k] = v.x;
        s_W1cT[(n4 + 1) * SK1 + k] = v.y;
        s_W1cT[(n4 + 2) * SK1 + k] = v.z;
        s_W1cT[(n4 + 3) * SK1 + k] = v.w;
    }
    for (int idx = tid; idx < 128 * 32; idx += THREADS) {  // We2 -> [n][k]
        const int k = idx >> 5, n4 = (idx & 31) * 4;
        const float4 v = tf32r4(*(const float4*)&We2[k * H + n4]);
        s_W2T[(n4 + 0) * SK2 + k] = v.x;
        s_W2T[(n4 + 1) * SK2 + k] = v.y;
        s_W2T[(n4 + 2) * SK2 + k] = v.z;
        s_W2T[(n4 + 3) * SK2 + k] = v.w;
    }
    for (int idx = tid; idx < 128 * 16; idx += THREADS) {  // Wc1 -> [n][k]
        const int k = idx >> 4, n4 = (idx & 15) * 4;
        const float4 v = tf32r4(*(const float4*)&Wc1[k * 64 + n4]);
        s_Wc1T[(n4 + 0) * SK3 + k] = v.x;
        s_Wc1T[(n4 + 1) * SK3 + k] = v.y;
        s_Wc1T[(n4 + 2) * SK3 + k] = v.z;
        s_Wc1T[(n4 + 3) * SK3 + k] = v.w;
    }

    const int lane = tid & 31, w = tid >> 5;       // 16 warps
    const int g = lane >> 2, tg = lane & 3;
    const int m0 = (w & 3) * 16;                   // 4 m-tiles
    const int ng = w >> 2;                         // 4 n-groups
    const int nb = ng * 32;
    const int nb3 = ng * 16;

    // LDSM per-thread row/col patterns
    const int aRow = m0 + (lane & 15);             // A rows (m)
    const int aCol = (lane >> 4) << 2;             // A col offset (k)
    const int bRow = (lane & 7) + ((lane >> 4) << 3);   // B row-in-16 (n)
    const int bCol = ((lane >> 3) & 1) << 2;       // B col offset (k)

    float ln_g[4], ln_b[4];
    ln_g[0] = g1[lane]; ln_g[1] = g1[lane + 32]; ln_g[2] = g1[lane + 64]; ln_g[3] = g1[lane + 96];
    ln_b[0] = bt1[lane]; ln_b[1] = bt1[lane + 32]; ln_b[2] = bt1[lane + 64]; ln_b[3] = bt1[lane + 96];
    float be1v[4][2], be2v[4][2];
    #pragma unroll
    for (int t = 0; t < 4; t++) {
        const int col = nb + t * 8 + tg * 2;
        be1v[t][0] = be1[col]; be1v[t][1] = be1[col + 1];
        be2v[t][0] = be2[col]; be2v[t][1] = be2[col + 1];
    }
    float wc2v[2][2], bc1v[2][2];
    #pragma unroll
    for (int t = 0; t < 2; t++) {
        const int col = nb3 + t * 8 + tg * 2;
        wc2v[t][0] = Wc2[col]; wc2v[t][1] = Wc2[col + 1];
        bc1v[t][0] = bc1[col]; bc1v[t][1] = bc1[col + 1];
    }
    const float bc2v = bc2[0];

    // ---- prologue: tile 0 scalars + gather ----
    {
        const int e0p = blockIdx.x * TE;
        if (tid < TE) {
            const int e = e0p + tid;
            const int src = edge_index[e];
            const int dst = edge_index[NE + e];
            s_srcb[0][tid] = src;
            const float rx = pos[dst * 3 + 0] - pos[src * 3 + 0];
            const float ry = pos[dst * 3 + 1] - pos[src * 3 + 1];
            const float rz = pos[dst * 3 + 2] - pos[src * 3 + 2];
            edge_scalar_body(rx, ry, rz, charge[src], charge[dst],
                             *(const float4*)&edge_attr[e * 4],
                             &efs[tid * EFS], &s_gateb[0][tid], &s_unitb[0][tid][0]);
            s_coordb[0][tid] = bc2v;
        }
        for (int idx = tid; idx < TE * 32; idx += THREADS) {
            const int e = idx >> 5, j4 = idx & 31;
            const int src = edge_index[e0p + e];
            const int dst = edge_index[NE + e0p + e];
            *(float4*)&s_P[e * HS + j4 * 4] = *(const float4*)&g_pq[src * 256 + j4 * 4];
            *(float4*)&s_Q[e * HS + j4 * 4] = *(const float4*)&g_pq[dst * 256 + 128 + j4 * 4];
        }
    }

    int p = 0;
    for (int tile = blockIdx.x; tile < NTILES; tile += GRID_EDGE, p ^= 1) {
        const int np = p ^ 1;
        const int nt = tile + GRID_EDGE;
        const bool has_next = (nt < NTILES);

        int ni = 0, ndsti = 0;
        if (has_next) {
            if (tid < 128) {
                const int off = (tid < 64) ? (nt * TE + tid) : (NE + nt * TE + (tid - 64));
                ni = edge_index[off];
            }
            if (tid < 64) ndsti = edge_index[NE + nt * TE + tid];
        }

        CPASYNC_WAIT0();
        __syncthreads();     // A

        // ---- GEMM1-small + epilogue1 -> s_h ----
        float d[4][4];
        #pragma unroll
        for (int t = 0; t < 4; t++)
            #pragma unroll
            for (int i = 0; i < 4; i++) d[t][i] = 0.f;
        #pragma unroll
        for (int ks = 0; ks < 3; ks++) {
            const int kg = ks * 8;
            uint32_t a0, a1, a2, a3, b00, b01, b10, b11, b20, b21, b30, b31;
            ldsm4(a0, a1, a2, a3, sEfsb + (aRow * EFS + kg + aCol) * 4);
            ldsm4(b00, b01, b10, b11, sW1b + ((nb + bRow) * SK1 + kg + bCol) * 4);
            ldsm4(b20, b21, b30, b31, sW1b + ((nb + 16 + bRow) * SK1 + kg + bCol) * 4);
            mma_tf32(d[0], a0, a1, a2, a3, b00, b01);
            mma_tf32(d[1], a0, a1, a2, a3, b10, b11);
            mma_tf32(d[2], a0, a1, a2, a3, b20, b21);
            mma_tf32(d[3], a0, a1, a2, a3, b30, b31);
        }
        #pragma unroll
        for (int t = 0; t < 4; t++) {
            const int col = nb + t * 8 + tg * 2;
            const int rA = m0 + g;
            s_h[rA * HS + col] =
                silu_f(d[t][0] + s_P[rA * HS + col] + s_Q[rA * HS + col] + be1v[t][0]);
            s_h[rA * HS + col + 1] =
                silu_f(d[t][1] + s_P[rA * HS + col + 1] + s_Q[rA * HS + col + 1] + be1v[t][1]);
            s_h[(rA + 8) * HS + col] =
                silu_f(d[t][2] + s_P[(rA + 8) * HS + col] + s_Q[(rA + 8) * HS + col] + be1v[t][0]);
            s_h[(rA + 8) * HS + col + 1] =
                silu_f(d[t][3] + s_P[(rA + 8) * HS + col + 1] + s_Q[(rA + 8) * HS + col + 1] + be1v[t][1]);
        }
        __syncthreads();     // B

        float psx = 0.f, psy = 0.f, psz = 0.f, pdx = 0.f, pdy = 0.f, pdz = 0.f;
        float qsv = 0.f, qdv = 0.f;
        float4 nea = z4;
        if (has_next && tid < 64) {
            psx = pos[ni * 3 + 0]; psy = pos[ni * 3 + 1]; psz = pos[ni * 3 + 2];
            pdx = pos[ndsti * 3 + 0]; pdy = pos[ndsti * 3 + 1]; pdz = pos[ndsti * 3 + 2];
            qsv = charge[ni]; qdv = charge[ndsti];
            nea = *(const float4*)&edge_attr[(nt * TE + tid) * 4];
        }

        // ---- LayerNorm(h): warp per 4 edges ----
        #pragma unroll
        for (int qq = 0; qq < 4; qq++) {
            const int e = w * 4 + qq;
            float v0 = s_h[e * HS + lane], v1 = s_h[e * HS + lane + 32];
            float v2 = s_h[e * HS + lane + 64], v3 = s_h[e * HS + lane + 96];
            float s1 = v0 + v1 + v2 + v3;
            float s2 = v0 * v0 + v1 * v1 + v2 * v2 + v3 * v3;
            #pragma unroll
            for (int o = 16; o; o >>= 1) {
                s1 += __shfl_xor_sync(0xffffffffu, s1, o);
                s2 += __shfl_xor_sync(0xffffffffu, s2, o);
            }
            const float m = s1 * (1.f / 128.f);
            const float var = s2 * (1.f / 128.f) - m * m;
            const float rstd = rsqrtf(var + 1e-5f);
            s_h[e * HS + lane]      = tf32r((v0 - m) * rstd * ln_g[0] + ln_b[0]);
            s_h[e * HS + lane + 32] = tf32r((v1 - m) * rstd * ln_g[1] + ln_b[1]);
            s_h[e * HS + lane + 64] = tf32r((v2 - m) * rstd * ln_g[2] + ln_b[2]);
            s_h[e * HS + lane + 96] = tf32r((v3 - m) * rstd * ln_g[3] + ln_b[3]);
        }
        __syncthreads();     // C

        if (has_next && tid < 128) s_idx2[tid] = ni;

        // ---- GEMM2: h @ We2 (LDSM fragments) ----
        #pragma unroll
        for (int t = 0; t < 4; t++)
            #pragma unroll
            for (int i = 0; i < 4; i++) d[t][i] = 0.f;
        {
            const uint32_t aBase = sHb + (aRow * HS + aCol) * 4;
            const uint32_t bBase0 = sW2b + ((nb + bRow) * SK2 + bCol) * 4;
            const uint32_t bBase1 = sW2b + ((nb + 16 + bRow) * SK2 + bCol) * 4;
            #pragma unroll 4
            for (int ks = 0; ks < 16; ks++) {
                const uint32_t ko = ks * 32;   // 8 floats = 32B
                uint32_t a0, a1, a2, a3, b00, b01, b10, b11, b20, b21, b30, b31;
                ldsm4(a0, a1, a2, a3, aBase + ko);
                ldsm4(b00, b01, b10, b11, bBase0 + ko);
                ldsm4(b20, b21, b30, b31, bBase1 + ko);
                mma_tf32(d[0], a0, a1, a2, a3, b00, b01);
                mma_tf32(d[1], a0, a1, a2, a3, b10, b11);
                mma_tf32(d[2], a0, a1, a2, a3, b20, b21);
                mma_tf32(d[3], a0, a1, a2, a3, b30, b31);
            }
        }
        __syncthreads();     // D

        // ---- epilogue2: eh = silu(+be2) -> s_eh ----
        #pragma unroll
        for (int t = 0; t < 4; t++) {
            const int col = nb + t * 8 + tg * 2;
            const int rA = m0 + g;
            s_eh[rA * HS + col]           = tf32r(silu_f(d[t][0] + be2v[t][0]));
            s_eh[rA * HS + col + 1]       = tf32r(silu_f(d[t][1] + be2v[t][1]));
            s_eh[(rA + 8) * HS + col]     = tf32r(silu_f(d[t][2] + be2v[t][0]));
            s_eh[(rA + 8) * HS + col + 1] = tf32r(silu_f(d[t][3] + be2v[t][1]));
        }

        // ---- pipelined prefetch for next tile ----
        if (has_next) {
            #pragma unroll
            for (int k = 0; k < 4; k++) {
                const int idx = tid + k * THREADS;
                const int e = idx >> 5, j4 = idx & 31;
                const int se = s_idx2[e];
                const int de = s_idx2[64 + e];
                cpasync16(sPb + e * (HS * 4) + j4 * 16,
                          (const char*)g_pq + (size_t)se * 1024 + (size_t)j4 * 16);
                cpasync16(sQb + e * (HS * 4) + j4 * 16,
                          (const char*)g_pq + (size_t)de * 1024 + 512 + (size_t)j4 * 16);
            }
            CPASYNC_COMMIT();
            if (tid < 64) {
                edge_scalar_body(pdx - psx, pdy - psy, pdz - psz, qsv, qdv, nea,
                                 &efs[tid * EFS], &s_gateb[np][tid], &s_unitb[np][tid][0]);
                s_srcb[np][tid] = ni;
                s_coordb[np][tid] = bc2v;
            }
        }
        __syncthreads();     // E

        // ---- agg scatter (fire-and-forget v4 REDs overlap GEMM3) ----
        #pragma unroll
        for (int k = 0; k < 4; k++) {
            const int idx = tid + k * THREADS;
            const int e = idx >> 5, j4 = idx & 31;
            const float4 v = *(const float4*)&s_eh[e * HS + j4 * 4];
            red_add_v4(&g_agg[s_srcb[p][e] * H + j4 * 4], v);
        }

        // ---- GEMM3: eh @ Wc1 (LDSM) + coord epilogue ----
        float d3[2][4];
        #pragma unroll
        for (int t = 0; t < 2; t++)
            #pragma unroll
            for (int i = 0; i < 4; i++) d3[t][i] = 0.f;
        {
            const uint32_t aBase = sHb + (aRow * HS + aCol) * 4;   // s_eh == s_h region
            const uint32_t bBase = sWc1b + ((nb3 + bRow) * SK3 + bCol) * 4;
            #pragma unroll 4
            for (int ks = 0; ks < 16; ks++) {
                const uint32_t ko = ks * 32;
                uint32_t a0, a1, a2, a3, b00, b01, b10, b11;
                ldsm4(a0, a1, a2, a3, aBase + ko);
                ldsm4(b00, b01, b10, b11, bBase + ko);
                mma_tf32(d3[0], a0, a1, a2, a3, b00, b01);
                mma_tf32(d3[1], a0, a1, a2, a3, b10, b11);
            }
        }
        {
            float sA = 0.f, sB2 = 0.f;
            #pragma unroll
            for (int t = 0; t < 2; t++) {
                sA  += silu_f(d3[t][0] + bc1v[t][0]) * wc2v[t][0]
                     + silu_f(d3[t][1] + bc1v[t][1]) * wc2v[t][1];
                sB2 += silu_f(d3[t][2] + bc1v[t][0]) * wc2v[t][0]
                     + silu_f(d3[t][3] + bc1v[t][1]) * wc2v[t][1];
            }
            const int rA = m0 + g;
            atomicAdd(&s_coordb[p][rA], sA);
            atomicAdd(&s_coordb[p][rA + 8], sB2);
        }
        __syncthreads();     // F

        // ---- cnt/delta scatter ----
        if (tid < TE) {
            const int src = s_srcb[p][tid];
            const float f = s_coordb[p][tid] * s_gateb[p][tid];
            atomicAdd(&g_cnt[src], 1.0f);
            atomicAdd(&g_delta[src * 3 + 0], s_unitb[p][tid][0] * f);
            atomicAdd(&g_delta[src * 3 + 1], s_unitb[p][tid][1] * f);
            atomicAdd(&g_delta[src * 3 + 2], s_unitb[p][tid][2] * f);
        }
        // next-iter barrier A separates smem reuse
    }
}

__global__ __launch_bounds__(256) void node_kernel(
    const float* __restrict__ x, const float* __restrict__ pos,
    const float* __restrict__ Wn, const float* __restrict__ bn,
    const float* __restrict__ gn, const float* __restrict__ btn,
    float* __restrict__ out)
{
    __shared__ __align__(16) float s_cat[TN * 260];
    const int tid = threadIdx.x;
    const int n0 = blockIdx.x * TN;

    for (int idx = tid; idx < TN * 64; idx += 256) {
        const int nl = idx >> 6, j4 = idx & 63;
        const int n = n0 + nl;
        float4 v = make_float4(0.f, 0.f, 0.f, 0.f);
        if (n < NN) {
            if (j4 < 32) {
                v = *(const float4*)&x[n * H + j4 * 4];
            } else {
                const float c = fmaxf(g_cnt[n], 1.f);
                const float iv = 1.f / c;
                v = *(const float4*)&g_agg[n * H + (j4 - 32) * 4];
                v.x *= iv; v.y *= iv; v.z *= iv; v.w *= iv;
            }
        }
        *(float4*)&s_cat[nl * 260 + j4 * 4] = v;
    }
    __syncthreads();

    const int jj = tid & 63, g = tid >> 6;
    const int nbv = g * 8;
    u64t accA[8], accB[8];
    #pragma unroll
    for (int e = 0; e < 8; e++) { accA[e] = 0ull; accB[e] = 0ull; }
    for (int k = 0; k < 256; k += 4) {
        const float wA0 = Wn[(k + 0) * H + jj],      wA1 = Wn[(k + 1) * H + jj];
        const float wA2 = Wn[(k + 2) * H + jj],      wA3 = Wn[(k + 3) * H + jj];
        const float wB0 = Wn[(k + 0) * H + jj + 64], wB1 = Wn[(k + 1) * H + jj + 64];
        const float wB2 = Wn[(k + 2) * H + jj + 64], wB3 = Wn[(k + 3) * H + jj + 64];
        const u64t pA0 = pack2(wA0, wA1), pA1 = pack2(wA2, wA3);
        const u64t pB0 = pack2(wB0, wB1), pB1 = pack2(wB2, wB3);
        #pragma unroll
        for (int e = 0; e < 8; e++) {
            const ulonglong2 v = *(const ulonglong2*)&s_cat[(nbv + e) * 260 + k];
            fma2(accA[e], v.x, pA0); fma2(accA[e], v.y, pA1);
            fma2(accB[e], v.x, pB0); fma2(accB[e], v.y, pB1);
        }
    }
    const float bA = bn[jj], bB = bn[jj + 64];
    __syncthreads();
    float* const s_y = s_cat;
    #pragma unroll
    for (int e = 0; e < 8; e++) {
        s_y[(nbv + e) * H + jj]      = silu_f(hadd2(accA[e]) + bA);
        s_y[(nbv + e) * H + jj + 64] = silu_f(hadd2(accB[e]) + bB);
    }
    __syncthreads();

    const int lane = tid & 31, wrp = tid >> 5;
    const float ga = gn[lane], gb = gn[lane + 32], gc = gn[lane + 64], gd = gn[lane + 96];
    const float ba = btn[lane], bb = btn[lane + 32], bcv = btn[lane + 64], bd = btn[lane + 96];
    #pragma unroll
    for (int qq = 0; qq < 4; qq++) {
        const int nl = wrp * 4 + qq;
        const int n = n0 + nl;
        float v0 = s_y[nl * H + lane], v1 = s_y[nl * H + lane + 32];
        float v2 = s_y[nl * H + lane + 64], v3 = s_y[nl * H + lane + 96];
        float s1 = v0 + v1 + v2 + v3;
        float s2 = v0 * v0 + v1 * v1 + v2 * v2 + v3 * v3;
        #pragma unroll
        for (int o = 16; o; o >>= 1) {
            s1 += __shfl_xor_sync(0xffffffffu, s1, o);
            s2 += __shfl_xor_sync(0xffffffffu, s2, o);
        }
        const float m = s1 * (1.f / 128.f);
        const float var = s2 * (1.f / 128.f) - m * m;
        const float rstd = rsqrtf(var + 1e-5f);
        if (n < NN) {
            out[n * H + lane]      = x[n * H + lane]      + (v0 - m) * rstd * ga + ba;
            out[n * H + lane + 32] = x[n * H + lane + 32] + (v1 - m) * rstd * gb + bb;
            out[n * H + lane + 64] = x[n * H + lane + 64] + (v2 - m) * rstd * gc + bcv;
            out[n * H + lane + 96] = x[n * H + lane + 96] + (v3 - m) * rstd * gd + bd;
        }
    }
    if (tid < TN) {
        const int n = n0 + tid;
        if (n < NN) {
            const float c = fmaxf(g_cnt[n], 1.f);
            const float s = 0.1f / c;
            out[NN * H + n * 3 + 0] = pos[n * 3 + 0] + s * g_delta[n * 3 + 0];
            out[NN * H + n * 3 + 1] = pos[n * 3 + 1] + s * g_delta[n * 3 + 1];
            out[NN * H + n * 3 + 2] = pos[n * 3 + 2] + s * g_delta[n * 3 + 2];
        }
    }

    // ---- re-zero scratch for next launch ----
    __syncthreads();
    const float4 z4 = make_float4(0.f, 0.f, 0.f, 0.f);
    for (int idx = tid; idx < TN * 32; idx += 256) {
        const int nl = idx >> 5, j4 = idx & 31;
        const int n = n0 + nl;
        if (n < NN) *(float4*)&g_agg[n * H + j4 * 4] = z4;
    }
    if (tid < TN) {
        const int n = n0 + tid;
        if (n < NN) {
            g_cnt[n] = 0.f;
            g_delta[n * 3 + 0] = 0.f;
            g_delta[n * 3 + 1] = 0.f;
            g_delta[n * 3 + 2] = 0.f;
        }
    }
}

extern "C" void kernel_launch(void* const* d_in, const int* in_sizes, int n_in,
                              void* d_out, int out_size) {
    const float* x         = (const float*)d_in[0];
    const float* pos       = (const float*)d_in[1];
    const float* charge    = (const float*)d_in[2];
    const float* edge_attr = (const float*)d_in[3];
    const int*   edge_index= (const int*)d_in[4];
    const float* We1 = (const float*)d_in[5];
    const float* be1 = (const float*)d_in[6];
    const float* g1  = (const float*)d_in[7];
    const float* bt1 = (const float*)d_in[8];
    const float* We2 = (const float*)d_in[9];
    const float* be2 = (const float*)d_in[10];
    const float* Wn  = (const float*)d_in[11];
    const float* bn  = (const float*)d_in[12];
    const float* gn  = (const float*)d_in[13];
    const float* btn = (const float*)d_in[14];
    const float* Wc1 = (const float*)d_in[15];
    const float* bc1 = (const float*)d_in[16];
    const float* Wc2 = (const float*)d_in[17];
    const float* bc2 = (const float*)d_in[18];
    float* out = (float*)d_out;

    cudaFuncSetAttribute(pre_kernel, cudaFuncAttributeMaxDynamicSharedMemorySize, SMEM_PRE);
    cudaFuncSetAttribute(edge_kernel, cudaFuncAttributeMaxDynamicSharedMemorySize, SMEM_EDGE);

    pre_kernel<<<(NN + 63) / 64, 256, SMEM_PRE>>>(x, We1);
    edge_kernel<<<GRID_EDGE, THREADS, SMEM_EDGE>>>(pos, charge, edge_attr, edge_index,
                                                   We1, be1, g1, bt1, We2, be2, Wc1, bc1, Wc2, bc2);
    node_kernel<<<(NN + TN - 1) / TN, 256>>>(x, pos, Wn, bn, gn, btn, out);
}

// round 17
// speedup vs baseline: 2.5078x; 1.1506x over previous
#include <cuda_runtime.h>
#include <cuda_fp16.h>
#include <math.h>
#include <stdint.h>

#define NN 50000
#define NE 800000
#define H 128
#define NRAD 16
#define TE 64              // edges per tile
#define TN 32
#define NTILES (NE / TE)   // 12500
#define GRID_EDGE 148
#define THREADS 512        // 16 warps: 4 m-tiles x 4 n-blocks
#define HS  132            // P/Q row stride (floats)
#define HSH 136            // h/eh row stride (halves): 272B, mod128=16 -> LDSM conflict-free
#define SKH 136            // fp16 weight row stride (halves)
#define SK1 28             // W1cT row stride [n=128][k=28 pad] (floats, tf32)
#define EFS 28             // small-feature row stride (floats)
#define PI_F 3.14159265358979f

// ---- persistent edge kernel dynamic smem layout (bytes) ----
#define SZ_T    (TE * HS * 4)               // 33792
#define OFF_P   0
#define OFF_Q   (OFF_P + SZ_T)              // 33792
#define OFF_H2  (OFF_Q + SZ_T)              // 67584 : h/eh fp16 [64][136]
#define SZ_H2   (TE * HSH * 2)              // 17408
#define OFF_W1C (OFF_H2 + SZ_H2)            // 84992 : W1cT tf32 [128][28]
#define SZ_W1C  (128 * SK1 * 4)             // 14336
#define OFF_W2  (OFF_W1C + SZ_W1C)          // 99328 : W2T fp16 [128][136]
#define SZ_W2   (128 * SKH * 2)             // 34816
#define OFF_WC1 (OFF_W2 + SZ_W2)            // 134144 : Wc1T fp16 [64][136]
#define SZ_WC1  (64 * SKH * 2)              // 17408
#define OFF_EFS (OFF_WC1 + SZ_WC1)          // 151552 : efs fp32 [64][28]
#define SZ_EFS  (TE * EFS * 4)              // 7168
#define SMEM_EDGE (OFF_EFS + SZ_EFS)        // 158720

// ---- pre kernel smem ----
#define XS 132
#define SBNP 264
#define OFF_X   0
#define SZ_X    (64 * XS * 4)
#define OFF_PB0 (OFF_X + SZ_X)
#define SZ_PB   (32 * SBNP * 4)
#define OFF_PB1 (OFF_PB0 + SZ_PB)
#define SMEM_PRE (OFF_PB1 + SZ_PB)

typedef unsigned long long u64t;

__device__ float g_pq[NN * 256];
__device__ float g_agg[NN * H];
__device__ float g_cnt[NN];
__device__ float g_delta[NN * 3];

__device__ __forceinline__ float silu_f(float v) { return v / (1.f + __expf(-v)); }

__device__ __forceinline__ float tf32r(float f) {
    uint32_t u; asm("cvt.rna.tf32.f32 %0, %1;" : "=r"(u) : "f"(f));
    return __uint_as_float(u);
}
__device__ __forceinline__ float4 tf32r4(float4 v) {
    v.x = tf32r(v.x); v.y = tf32r(v.y); v.z = tf32r(v.z); v.w = tf32r(v.w);
    return v;
}
__device__ __forceinline__ void mma_tf32(float* d, uint32_t a0, uint32_t a1, uint32_t a2,
                                         uint32_t a3, uint32_t b0, uint32_t b1) {
    asm("mma.sync.aligned.m16n8k8.row.col.f32.tf32.tf32.f32 "
        "{%0,%1,%2,%3},{%4,%5,%6,%7},{%8,%9},{%0,%1,%2,%3};"
        : "+f"(d[0]), "+f"(d[1]), "+f"(d[2]), "+f"(d[3])
        : "r"(a0), "r"(a1), "r"(a2), "r"(a3), "r"(b0), "r"(b1));
}
__device__ __forceinline__ void mma_f16(float* d, uint32_t a0, uint32_t a1, uint32_t a2,
                                        uint32_t a3, uint32_t b0, uint32_t b1) {
    asm("mma.sync.aligned.m16n8k16.row.col.f32.f16.f16.f32 "
        "{%0,%1,%2,%3},{%4,%5,%6,%7},{%8,%9},{%0,%1,%2,%3};"
        : "+f"(d[0]), "+f"(d[1]), "+f"(d[2]), "+f"(d[3])
        : "r"(a0), "r"(a1), "r"(a2), "r"(a3), "r"(b0), "r"(b1));
}
__device__ __forceinline__ void ldsm4(uint32_t& r0, uint32_t& r1, uint32_t& r2, uint32_t& r3,
                                      uint32_t addr) {
    asm volatile("ldmatrix.sync.aligned.m8n8.x4.shared.b16 {%0,%1,%2,%3}, [%4];"
                 : "=r"(r0), "=r"(r1), "=r"(r2), "=r"(r3) : "r"(addr));
}

__device__ __forceinline__ void fma2(u64t& d, u64t a, u64t b) {
    asm("fma.rn.f32x2 %0, %1, %2, %0;" : "+l"(d) : "l"(a), "l"(b));
}
__device__ __forceinline__ u64t pack2(float lo, float hi) {
    u64t d; asm("mov.b64 %0, {%1, %2};" : "=l"(d) : "f"(lo), "f"(hi)); return d;
}
__device__ __forceinline__ float hadd2(u64t d) {
    float lo, hi; asm("mov.b64 {%0, %1}, %2;" : "=f"(lo), "=f"(hi) : "l"(d));
    return lo + hi;
}

__device__ __forceinline__ void cpasync16(uint32_t smem_dst, const void* gsrc) {
    asm volatile("cp.async.cg.shared.global [%0], [%1], 16;" :: "r"(smem_dst), "l"(gsrc));
}
#define CPASYNC_COMMIT() asm volatile("cp.async.commit_group;" ::: "memory")
#define CPASYNC_WAIT0()  asm volatile("cp.async.wait_group 0;" ::: "memory")

__device__ __forceinline__ void red_add_v4(float* gptr, float4 v) {
    asm volatile("red.global.add.v4.f32 [%0], {%1, %2, %3, %4};"
                 :: "l"(gptr), "f"(v.x), "f"(v.y), "f"(v.z), "f"(v.w) : "memory");
}

__device__ __forceinline__ void edge_scalar_body(
    float rx, float ry, float rz, float qs, float qd, float4 ea,
    float* efs_row, float* gate_out, float* unit_out)
{
    const float dist = sqrtf(rx * rx + ry * ry + rz * rz + 1e-8f);
    const float inv = 1.f / dist;
    unit_out[0] = rx * inv; unit_out[1] = ry * inv; unit_out[2] = rz * inv;

    float ca = cosf(ea.x);
    float p2 = 0.5f * (3.f * ca * ca - 1.f);
    float p3 = (5.f * ca * p2 - 2.f * ca) * (1.f / 3.f);
    float a_score = 0.25f * (1.f + fabsf(ca) + fabsf(p2) + fabsf(p3)) * ea.z;
    float cd = cosf(ea.y);
    float q2 = 0.5f * (3.f * cd * cd - 1.f);
    float q3 = (5.f * cd * q2 - 2.f * cd) * (1.f / 3.f);
    float d_score = 0.25f * (1.f + fabsf(cd) + fabsf(q2) + fabsf(q3)) * ea.w;
    float gate = fminf(fmaxf(1.f + 0.6f * (a_score + d_score), 0.35f), 2.5f);
    *gate_out = gate;

    const float gi = gate * inv;
    #pragma unroll
    for (int i = 0; i < NRAD; i++) {
        float f = (float)(i + 1) * (PI_F / 5.0f);
        efs_row[i] = tf32r(sinf(f * dist) * gi);
    }
    efs_row[16] = tf32r(dist * 0.2f * gate);
    efs_row[17] = tf32r(qs * qd * gate);
    efs_row[18] = tf32r(fabsf(qs - qd) * gate);
    #pragma unroll
    for (int i = 19; i < EFS; i++) efs_row[i] = 0.f;
}

// ================== PQ = x @ [We1a | We1b] ==================
__global__ __launch_bounds__(256) void pre_kernel(
    const float* __restrict__ x, const float* __restrict__ We1)
{
    extern __shared__ __align__(16) char dsm[];
    float* const s_x  = (float*)(dsm + OFF_X);
    float* const s_P0 = (float*)(dsm + OFF_PB0);
    float* const s_P1 = (float*)(dsm + OFF_PB1);

    const int tid = threadIdx.x;
    const int n0 = blockIdx.x * 64;
    const float4 z4 = make_float4(0.f, 0.f, 0.f, 0.f);

    for (int idx = tid; idx < 64 * 32; idx += 256) {
        const int e = idx >> 5, j4 = idx & 31;
        const int n = n0 + e;
        float4 v = (n < NN) ? tf32r4(*(const float4*)&x[n * H + j4 * 4]) : z4;
        *(float4*)&s_x[e * XS + j4 * 4] = v;
    }

    const int lane = tid & 31, w = tid >> 5;
    const int g = lane >> 2, tg = lane & 3;
    const int m0 = (w & 1) * 32;
    const int nb = (w >> 1) * 64;
    const int kk = tid >> 3, q = tid & 7;

    float d[2][8][4];
    #pragma unroll
    for (int mi = 0; mi < 2; mi++)
        #pragma unroll
        for (int t = 0; t < 8; t++)
            #pragma unroll
            for (int i = 0; i < 4; i++) d[mi][t][i] = 0.f;

    float4 ra0, ra1, ra2, ra3, rb0, rb1, rb2, rb3;
    {
        const float* sa = &We1[kk * H + q * 16];
        const float* sb = &We1[(128 + kk) * H + q * 16];
        ra0 = tf32r4(*(const float4*)(sa + 0));  ra1 = tf32r4(*(const float4*)(sa + 4));
        ra2 = tf32r4(*(const float4*)(sa + 8));  ra3 = tf32r4(*(const float4*)(sa + 12));
        rb0 = tf32r4(*(const float4*)(sb + 0));  rb1 = tf32r4(*(const float4*)(sb + 4));
        rb2 = tf32r4(*(const float4*)(sb + 8));  rb3 = tf32r4(*(const float4*)(sb + 12));
        float* dw = &s_P0[kk * SBNP];
        *(float4*)(dw + q * 16 + 0) = ra0; *(float4*)(dw + q * 16 + 4) = ra1;
        *(float4*)(dw + q * 16 + 8) = ra2; *(float4*)(dw + q * 16 + 12) = ra3;
        *(float4*)(dw + 128 + q * 16 + 0) = rb0; *(float4*)(dw + 128 + q * 16 + 4) = rb1;
        *(float4*)(dw + 128 + q * 16 + 8) = rb2; *(float4*)(dw + 128 + q * 16 + 12) = rb3;
    }
    for (int c = 0; c < 4; c++) {
        if (c < 3) {
            const int k = (c + 1) * 32 + kk;
            const float* sa = &We1[k * H + q * 16];
            const float* sb = &We1[(128 + k) * H + q * 16];
            ra0 = tf32r4(*(const float4*)(sa + 0));  ra1 = tf32r4(*(const float4*)(sa + 4));
            ra2 = tf32r4(*(const float4*)(sa + 8));  ra3 = tf32r4(*(const float4*)(sa + 12));
            rb0 = tf32r4(*(const float4*)(sb + 0));  rb1 = tf32r4(*(const float4*)(sb + 4));
            rb2 = tf32r4(*(const float4*)(sb + 8));  rb3 = tf32r4(*(const float4*)(sb + 12));
        }
        __syncthreads();
        const float* bp = (c & 1) ? s_P1 : s_P0;
        #pragma unroll
        for (int ks = 0; ks < 4; ks++) {
            const int kg = c * 32 + ks * 8, kl = ks * 8;
            uint32_t a[2][4];
            #pragma unroll
            for (int mi = 0; mi < 2; mi++) {
                const int rA = m0 + mi * 16 + g;
                a[mi][0] = __float_as_uint(s_x[rA * XS + kg + tg]);
                a[mi][1] = __float_as_uint(s_x[(rA + 8) * XS + kg + tg]);
                a[mi][2] = __float_as_uint(s_x[rA * XS + kg + 4 + tg]);
                a[mi][3] = __float_as_uint(s_x[(rA + 8) * XS + kg + 4 + tg]);
            }
            #pragma unroll
            for (int t = 0; t < 8; t++) {
                const uint32_t b0 = __float_as_uint(bp[(kl + tg) * SBNP + nb + t * 8 + g]);
                const uint32_t b1 = __float_as_uint(bp[(kl + 4 + tg) * SBNP + nb + t * 8 + g]);
                mma_tf32(d[0][t], a[0][0], a[0][1], a[0][2], a[0][3], b0, b1);
                mma_tf32(d[1][t], a[1][0], a[1][1], a[1][2], a[1][3], b0, b1);
            }
        }
        if (c < 3) {
            float* np = (c & 1) ? s_P0 : s_P1;
            float* dw = &np[kk * SBNP];
            *(float4*)(dw + q * 16 + 0) = ra0; *(float4*)(dw + q * 16 + 4) = ra1;
            *(float4*)(dw + q * 16 + 8) = ra2; *(float4*)(dw + q * 16 + 12) = ra3;
            *(float4*)(dw + 128 + q * 16 + 0) = rb0; *(float4*)(dw + 128 + q * 16 + 4) = rb1;
            *(float4*)(dw + 128 + q * 16 + 8) = rb2; *(float4*)(dw + 128 + q * 16 + 12) = rb3;
        }
    }

    #pragma unroll
    for (int mi = 0; mi < 2; mi++) {
        const int r0w = n0 + m0 + mi * 16 + g;
        #pragma unroll
        for (int t = 0; t < 8; t++) {
            const int col = nb + t * 8 + tg * 2;
            if (r0w < NN)
                *(float2*)&g_pq[r0w * 256 + col] = make_float2(d[mi][t][0], d[mi][t][1]);
            if (r0w + 8 < NN)
                *(float2*)&g_pq[(r0w + 8) * 256 + col] = make_float2(d[mi][t][2], d[mi][t][3]);
        }
    }
}

// ================== persistent edge kernel: fp16 GEMM2/3 ==================
__global__ __launch_bounds__(THREADS) void edge_kernel(
    const float* __restrict__ pos,
    const float* __restrict__ charge, const float* __restrict__ edge_attr,
    const int* __restrict__ edge_index,
    const float* __restrict__ We1, const float* __restrict__ be1,
    const float* __restrict__ g1, const float* __restrict__ bt1,
    const float* __restrict__ We2, const float* __restrict__ be2,
    const float* __restrict__ Wc1, const float* __restrict__ bc1,
    const float* __restrict__ Wc2, const float* __restrict__ bc2)
{
    extern __shared__ __align__(16) char dsm[];
    float* const s_P    = (float*)(dsm + OFF_P);
    float* const s_Q    = (float*)(dsm + OFF_Q);
    __half* const s_h16 = (__half*)(dsm + OFF_H2);   // [64][136] h; eh overlays
    float* const s_W1cT = (float*)(dsm + OFF_W1C);   // [128][28] tf32 n-major
    __half* const s_W2T = (__half*)(dsm + OFF_W2);   // [128][136] fp16 n-major
    __half* const s_Wc1T= (__half*)(dsm + OFF_WC1);  // [64][136] fp16 n-major
    float* const efs    = (float*)(dsm + OFF_EFS);   // [64][28]

    __shared__ float s_gateb[2][TE];
    __shared__ float s_unitb[2][TE][3];
    __shared__ int   s_srcb[2][TE];
    __shared__ float s_coordb[2][TE];
    __shared__ int   s_idx2[128];

    const int tid = threadIdx.x;
    const float4 z4 = make_float4(0.f, 0.f, 0.f, 0.f);
    const uint32_t sPb   = (uint32_t)__cvta_generic_to_shared(s_P);
    const uint32_t sQb   = (uint32_t)__cvta_generic_to_shared(s_Q);
    const uint32_t sHb   = (uint32_t)__cvta_generic_to_shared(s_h16);
    const uint32_t sW1b  = (uint32_t)__cvta_generic_to_shared(s_W1cT);
    const uint32_t sW2b  = (uint32_t)__cvta_generic_to_shared(s_W2T);
    const uint32_t sWc1b = (uint32_t)__cvta_generic_to_shared(s_Wc1T);
    const uint32_t sEfsb = (uint32_t)__cvta_generic_to_shared(efs);

    // ---- stage weights once ----
    for (int idx = tid; idx < 128 * SK1; idx += THREADS)   // zero W1cT incl. pad
        s_W1cT[idx] = 0.f;
    for (int idx = tid; idx < 128 * SKH; idx += THREADS) { // zero fp16 pads
        s_W2T[idx] = __float2half(0.f);
        if (idx < 64 * SKH) s_Wc1T[idx] = __float2half(0.f);
    }
    __syncthreads();
    for (int idx = tid; idx < 19 * 32; idx += THREADS) {   // We1 rows 256..274 -> tf32 [n][k]
        const int k = idx >> 5, n4 = (idx & 31) * 4;
        const float4 v = tf32r4(*(const float4*)&We1[(256 + k) * H + n4]);
        s_W1cT[(n4 + 0) * SK1 + k] = v.x;
        s_W1cT[(n4 + 1) * SK1 + k] = v.y;
        s_W1cT[(n4 + 2) * SK1 + k] = v.z;
        s_W1cT[(n4 + 3) * SK1 + k] = v.w;
    }
    for (int idx = tid; idx < 128 * 32; idx += THREADS) {  // We2 -> fp16 [n][k]
        const int k = idx >> 5, n4 = (idx & 31) * 4;
        const float4 v = *(const float4*)&We2[k * H + n4];
        s_W2T[(n4 + 0) * SKH + k] = __float2half_rn(v.x);
        s_W2T[(n4 + 1) * SKH + k] = __float2half_rn(v.y);
        s_W2T[(n4 + 2) * SKH + k] = __float2half_rn(v.z);
        s_W2T[(n4 + 3) * SKH + k] = __float2half_rn(v.w);
    }
    for (int idx = tid; idx < 128 * 16; idx += THREADS) {  // Wc1 -> fp16 [n][k]
        const int k = idx >> 4, n4 = (idx & 15) * 4;
        const float4 v = *(const float4*)&Wc1[k * 64 + n4];
        s_Wc1T[(n4 + 0) * SKH + k] = __float2half_rn(v.x);
        s_Wc1T[(n4 + 1) * SKH + k] = __float2half_rn(v.y);
        s_Wc1T[(n4 + 2) * SKH + k] = __float2half_rn(v.z);
        s_Wc1T[(n4 + 3) * SKH + k] = __float2half_rn(v.w);
    }

    const int lane = tid & 31, w = tid >> 5;       // 16 warps
    const int g = lane >> 2, tg = lane & 3;
    const int m0 = (w & 3) * 16;                   // 4 m-tiles
    const int ng = w >> 2;                         // 4 n-groups
    const int nb = ng * 32;
    const int nb3 = ng * 16;

    // tf32 LDSM patterns (GEMM1-small)
    const int aRowF = m0 + (lane & 15);
    const int aColF = (lane >> 4) << 2;
    const int bRowF = (lane & 7) + ((lane >> 4) << 3);
    const int bColF = ((lane >> 3) & 1) << 2;
    // fp16 LDSM patterns (GEMM2/3): halves
    const int aRowH = m0 + (lane & 7) + ((lane >> 3) & 1) * 8;
    const int aColH = ((lane >> 4) & 1) * 8;
    const int bNoff = ((lane >> 4) & 1) * 8 + (lane & 7);
    const int bKoff = ((lane >> 3) & 1) * 8;

    float ln_g[4], ln_b[4];
    ln_g[0] = g1[lane]; ln_g[1] = g1[lane + 32]; ln_g[2] = g1[lane + 64]; ln_g[3] = g1[lane + 96];
    ln_b[0] = bt1[lane]; ln_b[1] = bt1[lane + 32]; ln_b[2] = bt1[lane + 64]; ln_b[3] = bt1[lane + 96];
    float be1v[4][2], be2v[4][2];
    #pragma unroll
    for (int t = 0; t < 4; t++) {
        const int col = nb + t * 8 + tg * 2;
        be1v[t][0] = be1[col]; be1v[t][1] = be1[col + 1];
        be2v[t][0] = be2[col]; be2v[t][1] = be2[col + 1];
    }
    float wc2v[2][2], bc1v[2][2];
    #pragma unroll
    for (int t = 0; t < 2; t++) {
        const int col = nb3 + t * 8 + tg * 2;
        wc2v[t][0] = Wc2[col]; wc2v[t][1] = Wc2[col + 1];
        bc1v[t][0] = bc1[col]; bc1v[t][1] = bc1[col + 1];
    }
    const float bc2v = bc2[0];

    // ---- prologue: tile 0 scalars + gather ----
    {
        const int e0p = blockIdx.x * TE;
        if (tid < TE) {
            const int e = e0p + tid;
            const int src = edge_index[e];
            const int dst = edge_index[NE + e];
            s_srcb[0][tid] = src;
            const float rx = pos[dst * 3 + 0] - pos[src * 3 + 0];
            const float ry = pos[dst * 3 + 1] - pos[src * 3 + 1];
            const float rz = pos[dst * 3 + 2] - pos[src * 3 + 2];
            edge_scalar_body(rx, ry, rz, charge[src], charge[dst],
                             *(const float4*)&edge_attr[e * 4],
                             &efs[tid * EFS], &s_gateb[0][tid], &s_unitb[0][tid][0]);
            s_coordb[0][tid] = bc2v;
        }
        for (int idx = tid; idx < TE * 32; idx += THREADS) {
            const int e = idx >> 5, j4 = idx & 31;
            const int src = edge_index[e0p + e];
            const int dst = edge_index[NE + e0p + e];
            *(float4*)&s_P[e * HS + j4 * 4] = *(const float4*)&g_pq[src * 256 + j4 * 4];
            *(float4*)&s_Q[e * HS + j4 * 4] = *(const float4*)&g_pq[dst * 256 + 128 + j4 * 4];
        }
    }

    int p = 0;
    for (int tile = blockIdx.x; tile < NTILES; tile += GRID_EDGE, p ^= 1) {
        const int np = p ^ 1;
        const int nt = tile + GRID_EDGE;
        const bool has_next = (nt < NTILES);

        int ni = 0, ndsti = 0;
        if (has_next) {
            if (tid < 128) {
                const int off = (tid < 64) ? (nt * TE + tid) : (NE + nt * TE + (tid - 64));
                ni = edge_index[off];
            }
            if (tid < 64) ndsti = edge_index[NE + nt * TE + tid];
        }

        CPASYNC_WAIT0();
        __syncthreads();     // A

        // ---- GEMM1-small (tf32) + epilogue1 -> s_h16 ----
        float d[4][4];
        #pragma unroll
        for (int t = 0; t < 4; t++)
            #pragma unroll
            for (int i = 0; i < 4; i++) d[t][i] = 0.f;
        #pragma unroll
        for (int ks = 0; ks < 3; ks++) {
            const int kg = ks * 8;
            uint32_t a0, a1, a2, a3, b00, b01, b10, b11, b20, b21, b30, b31;
            ldsm4(a0, a1, a2, a3, sEfsb + (aRowF * EFS + kg + aColF) * 4);
            ldsm4(b00, b01, b10, b11, sW1b + ((nb + bRowF) * SK1 + kg + bColF) * 4);
            ldsm4(b20, b21, b30, b31, sW1b + ((nb + 16 + bRowF) * SK1 + kg + bColF) * 4);
            mma_tf32(d[0], a0, a1, a2, a3, b00, b01);
            mma_tf32(d[1], a0, a1, a2, a3, b10, b11);
            mma_tf32(d[2], a0, a1, a2, a3, b20, b21);
            mma_tf32(d[3], a0, a1, a2, a3, b30, b31);
        }
        #pragma unroll
        for (int t = 0; t < 4; t++) {
            const int col = nb + t * 8 + tg * 2;
            const int rA = m0 + g;
            const float v00 = silu_f(d[t][0] + s_P[rA * HS + col] + s_Q[rA * HS + col] + be1v[t][0]);
            const float v01 = silu_f(d[t][1] + s_P[rA * HS + col + 1] + s_Q[rA * HS + col + 1] + be1v[t][1]);
            const float v10 = silu_f(d[t][2] + s_P[(rA + 8) * HS + col] + s_Q[(rA + 8) * HS + col] + be1v[t][0]);
            const float v11 = silu_f(d[t][3] + s_P[(rA + 8) * HS + col + 1] + s_Q[(rA + 8) * HS + col + 1] + be1v[t][1]);
            *(__half2*)&s_h16[rA * HSH + col]       = __floats2half2_rn(v00, v01);
            *(__half2*)&s_h16[(rA + 8) * HSH + col] = __floats2half2_rn(v10, v11);
        }
        __syncthreads();     // B

        float psx = 0.f, psy = 0.f, psz = 0.f, pdx = 0.f, pdy = 0.f, pdz = 0.f;
        float qsv = 0.f, qdv = 0.f;
        float4 nea = z4;
        if (has_next && tid < 64) {
            psx = pos[ni * 3 + 0]; psy = pos[ni * 3 + 1]; psz = pos[ni * 3 + 2];
            pdx = pos[ndsti * 3 + 0]; pdy = pos[ndsti * 3 + 1]; pdz = pos[ndsti * 3 + 2];
            qsv = charge[ni]; qdv = charge[ndsti];
            nea = *(const float4*)&edge_attr[(nt * TE + tid) * 4];
        }

        // ---- LayerNorm(h fp16): warp per 4 edges ----
        #pragma unroll
        for (int qq = 0; qq < 4; qq++) {
            const int e = w * 4 + qq;
            float v0 = __half2float(s_h16[e * HSH + lane]);
            float v1 = __half2float(s_h16[e * HSH + lane + 32]);
            float v2 = __half2float(s_h16[e * HSH + lane + 64]);
            float v3 = __half2float(s_h16[e * HSH + lane + 96]);
            float s1 = v0 + v1 + v2 + v3;
            float s2 = v0 * v0 + v1 * v1 + v2 * v2 + v3 * v3;
            #pragma unroll
            for (int o = 16; o; o >>= 1) {
                s1 += __shfl_xor_sync(0xffffffffu, s1, o);
                s2 += __shfl_xor_sync(0xffffffffu, s2, o);
            }
            const float m = s1 * (1.f / 128.f);
            const float var = s2 * (1.f / 128.f) - m * m;
            const float rstd = rsqrtf(var + 1e-5f);
            s_h16[e * HSH + lane]      = __float2half_rn((v0 - m) * rstd * ln_g[0] + ln_b[0]);
            s_h16[e * HSH + lane + 32] = __float2half_rn((v1 - m) * rstd * ln_g[1] + ln_b[1]);
            s_h16[e * HSH + lane + 64] = __float2half_rn((v2 - m) * rstd * ln_g[2] + ln_b[2]);
            s_h16[e * HSH + lane + 96] = __float2half_rn((v3 - m) * rstd * ln_g[3] + ln_b[3]);
        }
        __syncthreads();     // C

        if (has_next && tid < 128) s_idx2[tid] = ni;

        // ---- GEMM2: h @ We2 (fp16 m16n8k16) ----
        #pragma unroll
        for (int t = 0; t < 4; t++)
            #pragma unroll
            for (int i = 0; i < 4; i++) d[t][i] = 0.f;
        {
            const uint32_t aBase = sHb + (aRowH * HSH + aColH) * 2;
            const uint32_t bBase0 = sW2b + ((nb + bNoff) * SKH + bKoff) * 2;
            const uint32_t bBase1 = sW2b + ((nb + 16 + bNoff) * SKH + bKoff) * 2;
            #pragma unroll
            for (int ks = 0; ks < 8; ks++) {
                const uint32_t ko = ks * 32;   // 16 halves
                uint32_t a0, a1, a2, a3, b00, b01, b10, b11, b20, b21, b30, b31;
                ldsm4(a0, a1, a2, a3, aBase + ko);
                ldsm4(b00, b01, b10, b11, bBase0 + ko);
                ldsm4(b20, b21, b30, b31, bBase1 + ko);
                mma_f16(d[0], a0, a1, a2, a3, b00, b01);
                mma_f16(d[1], a0, a1, a2, a3, b10, b11);
                mma_f16(d[2], a0, a1, a2, a3, b20, b21);
                mma_f16(d[3], a0, a1, a2, a3, b30, b31);
            }
        }
        __syncthreads();     // D

        // ---- epilogue2: eh = silu(+be2) -> s_h16 (overlay) ----
        #pragma unroll
        for (int t = 0; t < 4; t++) {
            const int col = nb + t * 8 + tg * 2;
            const int rA = m0 + g;
            *(__half2*)&s_h16[rA * HSH + col] =
                __floats2half2_rn(silu_f(d[t][0] + be2v[t][0]), silu_f(d[t][1] + be2v[t][1]));
            *(__half2*)&s_h16[(rA + 8) * HSH + col] =
                __floats2half2_rn(silu_f(d[t][2] + be2v[t][0]), silu_f(d[t][3] + be2v[t][1]));
        }

        // ---- pipelined prefetch for next tile ----
        if (has_next) {
            #pragma unroll
            for (int k = 0; k < 4; k++) {
                const int idx = tid + k * THREADS;
                const int e = idx >> 5, j4 = idx & 31;
                const int se = s_idx2[e];
                const int de = s_idx2[64 + e];
                cpasync16(sPb + e * (HS * 4) + j4 * 16,
                          (const char*)g_pq + (size_t)se * 1024 + (size_t)j4 * 16);
                cpasync16(sQb + e * (HS * 4) + j4 * 16,
                          (const char*)g_pq + (size_t)de * 1024 + 512 + (size_t)j4 * 16);
            }
            CPASYNC_COMMIT();
            if (tid < 64) {
                edge_scalar_body(pdx - psx, pdy - psy, pdz - psz, qsv, qdv, nea,
                                 &efs[tid * EFS], &s_gateb[np][tid], &s_unitb[np][tid][0]);
                s_srcb[np][tid] = ni;
                s_coordb[np][tid] = bc2v;
            }
        }
        __syncthreads();     // E

        // ---- agg scatter (v4 REDs, overlap GEMM3) ----
        #pragma unroll
        for (int k = 0; k < 4; k++) {
            const int idx = tid + k * THREADS;
            const int e = idx >> 5, j4 = idx & 31;
            const __half2 p0 = *(const __half2*)&s_h16[e * HSH + j4 * 4];
            const __half2 p1 = *(const __half2*)&s_h16[e * HSH + j4 * 4 + 2];
            const float2 f0 = __half22float2(p0), f1 = __half22float2(p1);
            red_add_v4(&g_agg[s_srcb[p][e] * H + j4 * 4],
                       make_float4(f0.x, f0.y, f1.x, f1.y));
        }

        // ---- GEMM3: eh @ Wc1 (fp16) + coord epilogue ----
        float d3[2][4];
        #pragma unroll
        for (int t = 0; t < 2; t++)
            #pragma unroll
            for (int i = 0; i < 4; i++) d3[t][i] = 0.f;
        {
            const uint32_t aBase = sHb + (aRowH * HSH + aColH) * 2;
            const uint32_t bBase = sWc1b + ((nb3 + bNoff) * SKH + bKoff) * 2;
            #pragma unroll
            for (int ks = 0; ks < 8; ks++) {
                const uint32_t ko = ks * 32;
                uint32_t a0, a1, a2, a3, b00, b01, b10, b11;
                ldsm4(a0, a1, a2, a3, aBase + ko);
                ldsm4(b00, b01, b10, b11, bBase + ko);
                mma_f16(d3[0], a0, a1, a2, a3, b00, b01);
                mma_f16(d3[1], a0, a1, a2, a3, b10, b11);
            }
        }
        {
            float sA = 0.f, sB2 = 0.f;
            #pragma unroll
            for (int t = 0; t < 2; t++) {
                sA  += silu_f(d3[t][0] + bc1v[t][0]) * wc2v[t][0]
                     + silu_f(d3[t][1] + bc1v[t][1]) * wc2v[t][1];
                sB2 += silu_f(d3[t][2] + bc1v[t][0]) * wc2v[t][0]
                     + silu_f(d3[t][3] + bc1v[t][1]) * wc2v[t][1];
            }
            const int rA = m0 + g;
            atomicAdd(&s_coordb[p][rA], sA);
            atomicAdd(&s_coordb[p][rA + 8], sB2);
        }
        __syncthreads();     // F

        // ---- cnt/delta scatter ----
        if (tid < TE) {
            const int src = s_srcb[p][tid];
            const float f = s_coordb[p][tid] * s_gateb[p][tid];
            atomicAdd(&g_cnt[src], 1.0f);
            atomicAdd(&g_delta[src * 3 + 0], s_unitb[p][tid][0] * f);
            atomicAdd(&g_delta[src * 3 + 1], s_unitb[p][tid][1] * f);
            atomicAdd(&g_delta[src * 3 + 2], s_unitb[p][tid][2] * f);
        }
        // next-iter barrier A separates smem reuse
    }
}

__global__ __launch_bounds__(256) void node_kernel(
    const float* __restrict__ x, const float* __restrict__ pos,
    const float* __restrict__ Wn, const float* __restrict__ bn,
    const float* __restrict__ gn, const float* __restrict__ btn,
    float* __restrict__ out)
{
    __shared__ __align__(16) float s_cat[TN * 260];
    const int tid = threadIdx.x;
    const int n0 = blockIdx.x * TN;

    for (int idx = tid; idx < TN * 64; idx += 256) {
        const int nl = idx >> 6, j4 = idx & 63;
        const int n = n0 + nl;
        float4 v = make_float4(0.f, 0.f, 0.f, 0.f);
        if (n < NN) {
            if (j4 < 32) {
                v = *(const float4*)&x[n * H + j4 * 4];
            } else {
                const float c = fmaxf(g_cnt[n], 1.f);
                const float iv = 1.f / c;
                v = *(const float4*)&g_agg[n * H + (j4 - 32) * 4];
                v.x *= iv; v.y *= iv; v.z *= iv; v.w *= iv;
            }
        }
        *(float4*)&s_cat[nl * 260 + j4 * 4] = v;
    }
    __syncthreads();

    const int jj = tid & 63, g = tid >> 6;
    const int nbv = g * 8;
    u64t accA[8], accB[8];
    #pragma unroll
    for (int e = 0; e < 8; e++) { accA[e] = 0ull; accB[e] = 0ull; }
    for (int k = 0; k < 256; k += 4) {
        const float wA0 = Wn[(k + 0) * H + jj],      wA1 = Wn[(k + 1) * H + jj];
        const float wA2 = Wn[(k + 2) * H + jj],      wA3 = Wn[(k + 3) * H + jj];
        const float wB0 = Wn[(k + 0) * H + jj + 64], wB1 = Wn[(k + 1) * H + jj + 64];
        const float wB2 = Wn[(k + 2) * H + jj + 64], wB3 = Wn[(k + 3) * H + jj + 64];
        const u64t pA0 = pack2(wA0, wA1), pA1 = pack2(wA2, wA3);
        const u64t pB0 = pack2(wB0, wB1), pB1 = pack2(wB2, wB3);
        #pragma unroll
        for (int e = 0; e < 8; e++) {
            const ulonglong2 v = *(const ulonglong2*)&s_cat[(nbv + e) * 260 + k];
            fma2(accA[e], v.x, pA0); fma2(accA[e], v.y, pA1);
            fma2(accB[e], v.x, pB0); fma2(accB[e], v.y, pB1);
        }
    }
    const float bA = bn[jj], bB = bn[jj + 64];
    __syncthreads();
    float* const s_y = s_cat;
    #pragma unroll
    for (int e = 0; e < 8; e++) {
        s_y[(nbv + e) * H + jj]      = silu_f(hadd2(accA[e]) + bA);
        s_y[(nbv + e) * H + jj + 64] = silu_f(hadd2(accB[e]) + bB);
    }
    __syncthreads();

    const int lane = tid & 31, wrp = tid >> 5;
    const float ga = gn[lane], gb = gn[lane + 32], gc = gn[lane + 64], gd = gn[lane + 96];
    const float ba = btn[lane], bb = btn[lane + 32], bcv = btn[lane + 64], bd = btn[lane + 96];
    #pragma unroll
    for (int qq = 0; qq < 4; qq++) {
        const int nl = wrp * 4 + qq;
        const int n = n0 + nl;
        float v0 = s_y[nl * H + lane], v1 = s_y[nl * H + lane + 32];
        float v2 = s_y[nl * H + lane + 64], v3 = s_y[nl * H + lane + 96];
        float s1 = v0 + v1 + v2 + v3;
        float s2 = v0 * v0 + v1 * v1 + v2 * v2 + v3 * v3;
        #pragma unroll
        for (int o = 16; o; o >>= 1) {
            s1 += __shfl_xor_sync(0xffffffffu, s1, o);
            s2 += __shfl_xor_sync(0xffffffffu, s2, o);
        }
        const float m = s1 * (1.f / 128.f);
        const float var = s2 * (1.f / 128.f) - m * m;
        const float rstd = rsqrtf(var + 1e-5f);
        if (n < NN) {
            out[n * H + lane]      = x[n * H + lane]      + (v0 - m) * rstd * ga + ba;
            out[n * H + lane + 32] = x[n * H + lane + 32] + (v1 - m) * rstd * gb + bb;
            out[n * H + lane + 64] = x[n * H + lane + 64] + (v2 - m) * rstd * gc + bcv;
            out[n * H + lane + 96] = x[n * H + lane + 96] + (v3 - m) * rstd * gd + bd;
        }
    }
    if (tid < TN) {
        const int n = n0 + tid;
        if (n < NN) {
            const float c = fmaxf(g_cnt[n], 1.f);
            const float s = 0.1f / c;
            out[NN * H + n * 3 + 0] = pos[n * 3 + 0] + s * g_delta[n * 3 + 0];
            out[NN * H + n * 3 + 1] = pos[n * 3 + 1] + s * g_delta[n * 3 + 1];
            out[NN * H + n * 3 + 2] = pos[n * 3 + 2] + s * g_delta[n * 3 + 2];
        }
    }

    // ---- re-zero scratch for next launch ----
    __syncthreads();
    const float4 z4 = make_float4(0.f, 0.f, 0.f, 0.f);
    for (int idx = tid; idx < TN * 32; idx += 256) {
        const int nl = idx >> 5, j4 = idx & 31;
        const int n = n0 + nl;
        if (n < NN) *(float4*)&g_agg[n * H + j4 * 4] = z4;
    }
    if (tid < TN) {
        const int n = n0 + tid;
        if (n < NN) {
            g_cnt[n] = 0.f;
            g_delta[n * 3 + 0] = 0.f;
            g_delta[n * 3 + 1] = 0.f;
            g_delta[n * 3 + 2] = 0.f;
        }
    }
}

extern "C" void kernel_launch(void* const* d_in, const int* in_sizes, int n_in,
                              void* d_out, int out_size) {
    const float* x         = (const float*)d_in[0];
    const float* pos       = (const float*)d_in[1];
    const float* charge    = (const float*)d_in[2];
    const float* edge_attr = (const float*)d_in[3];
    const int*   edge_index= (const int*)d_in[4];
    const float* We1 = (const float*)d_in[5];
    const float* be1 = (const float*)d_in[6];
    const float* g1  = (const float*)d_in[7];
    const float* bt1 = (const float*)d_in[8];
    const float* We2 = (const float*)d_in[9];
    const float* be2 = (const float*)d_in[10];
    const float* Wn  = (const float*)d_in[11];
    const float* bn  = (const float*)d_in[12];
    const float* gn  = (const float*)d_in[13];
    const float* btn = (const float*)d_in[14];
    const float* Wc1 = (const float*)d_in[15];
    const float* bc1 = (const float*)d_in[16];
    const float* Wc2 = (const float*)d_in[17];
    const float* bc2 = (const float*)d_in[18];
    float* out = (float*)d_out;

    cudaFuncSetAttribute(pre_kernel, cudaFuncAttributeMaxDynamicSharedMemorySize, SMEM_PRE);
    cudaFuncSetAttribute(edge_kernel, cudaFuncAttributeMaxDynamicSharedMemorySize, SMEM_EDGE);

    pre_kernel<<<(NN + 63) / 64, 256, SMEM_PRE>>>(x, We1);
    edge_kernel<<<GRID_EDGE, THREADS, SMEM_EDGE>>>(pos, charge, edge_attr, edge_index,
                                                   We1, be1, g1, bt1, We2, be2, Wc1, bc1, Wc2, bc2);
    node_kernel<<<(NN + TN - 1) / TN, 256>>>(x, pos, Wn, bn, gn, btn, out);
}